// round 1
// baseline (speedup 1.0000x reference)
#include <cuda_runtime.h>
#include <math.h>

#define Bsz 128
#define Pd  196
#define Ed  512
#define Hd  512
#define Ad  256
#define Vd  30000
#define Td  21
#define NSTEPS 20
#define KCAT 1536   // 2E + H
#define G4   2048   // 4H

// ---------------- device scratch (static allocations are allowed) ----------
__device__ float g_enc_proj[Bsz * Pd * Ad];      // 25.7 MB
__device__ float g_WencT[Ad * Ed];               // W_enc transposed to (A, E)
__device__ float g_Wcat[G4 * KCAT];              // [W_ih | W_hh] packed, 12.6 MB
__device__ float g_bcat[G4];
__device__ float g_h[Bsz * Hd];
__device__ float g_c[Bsz * Hd];
__device__ float g_x[Bsz * KCAT];                // [xt | context | h]
__device__ float g_gates[Bsz * G4];
__device__ float g_Hall[Bsz * NSTEPS * Hd];      // h_t history, row = b*20+t

// ---------------- prep: pack weights, transpose W_enc, zero state ----------
__global__ void k_prep(const float* __restrict__ W_enc,
                       const float* __restrict__ W_ih, const float* __restrict__ b_ih,
                       const float* __restrict__ W_hh, const float* __restrict__ b_hh) {
    int idx = blockIdx.x * blockDim.x + threadIdx.x;
    int nthr = gridDim.x * blockDim.x;
    if (idx < Ad * Ed) {
        int a = idx / Ed, e = idx % Ed;
        g_WencT[idx] = W_enc[e * Ad + a];
    }
    for (int i = idx; i < G4 * KCAT; i += nthr) {
        int n = i / KCAT, k = i % KCAT;
        g_Wcat[i] = (k < 2 * Ed) ? W_ih[n * (2 * Ed) + k] : W_hh[n * Hd + (k - 2 * Ed)];
    }
    if (idx < G4) g_bcat[idx] = b_ih[idx] + b_hh[idx];
    if (idx < Bsz * Hd) { g_h[idx] = 0.f; g_c[idx] = 0.f; }
}

// ---------------- generic C = A(MxK) * B(NxK)^T + bias, 64x64 tile --------
__global__ __launch_bounds__(256)
void gemm_nt64(const float* __restrict__ A, const float* __restrict__ B,
               const float* __restrict__ bias, float* __restrict__ C,
               int M, int N, int K) {
    __shared__ float As[16][64];
    __shared__ float Bs[16][64];
    const int tid = threadIdx.x;
    const int m0 = blockIdx.y * 64;
    const int n0 = blockIdx.x * 64;
    const int tx = tid & 15;          // 0..15 -> N micro
    const int ty = tid >> 4;          // 0..15 -> M micro
    const int lr = tid >> 2;          // 0..63 tile row for loads
    const int lk = (tid & 3) << 2;    // 0,4,8,12 k offset

    const bool bok = (n0 + lr) < N;   // M is always a multiple of 64 here
    const float* Ap = A + (size_t)(m0 + lr) * K + lk;
    const float* Bp = B + (bok ? (size_t)(n0 + lr) * K + lk : 0);

    float acc[4][4] = {};

    for (int k0 = 0; k0 < K; k0 += 16) {
        float4 av = *(const float4*)(Ap + k0);
        float4 bv = make_float4(0.f, 0.f, 0.f, 0.f);
        if (bok) bv = *(const float4*)(Bp + k0);
        As[lk + 0][lr] = av.x; As[lk + 1][lr] = av.y;
        As[lk + 2][lr] = av.z; As[lk + 3][lr] = av.w;
        Bs[lk + 0][lr] = bv.x; Bs[lk + 1][lr] = bv.y;
        Bs[lk + 2][lr] = bv.z; Bs[lk + 3][lr] = bv.w;
        __syncthreads();
        #pragma unroll
        for (int k = 0; k < 16; k++) {
            float a0 = As[k][ty * 4 + 0], a1 = As[k][ty * 4 + 1];
            float a2 = As[k][ty * 4 + 2], a3 = As[k][ty * 4 + 3];
            float b0 = Bs[k][tx * 4 + 0], b1 = Bs[k][tx * 4 + 1];
            float b2 = Bs[k][tx * 4 + 2], b3 = Bs[k][tx * 4 + 3];
            acc[0][0] = fmaf(a0, b0, acc[0][0]); acc[0][1] = fmaf(a0, b1, acc[0][1]);
            acc[0][2] = fmaf(a0, b2, acc[0][2]); acc[0][3] = fmaf(a0, b3, acc[0][3]);
            acc[1][0] = fmaf(a1, b0, acc[1][0]); acc[1][1] = fmaf(a1, b1, acc[1][1]);
            acc[1][2] = fmaf(a1, b2, acc[1][2]); acc[1][3] = fmaf(a1, b3, acc[1][3]);
            acc[2][0] = fmaf(a2, b0, acc[2][0]); acc[2][1] = fmaf(a2, b1, acc[2][1]);
            acc[2][2] = fmaf(a2, b2, acc[2][2]); acc[2][3] = fmaf(a2, b3, acc[2][3]);
            acc[3][0] = fmaf(a3, b0, acc[3][0]); acc[3][1] = fmaf(a3, b1, acc[3][1]);
            acc[3][2] = fmaf(a3, b2, acc[3][2]); acc[3][3] = fmaf(a3, b3, acc[3][3]);
        }
        __syncthreads();
    }

    int col = n0 + tx * 4;
    if (col < N) {   // N % 4 == 0 in all uses, so the whole float4 is in/out together
        float bx = bias[col + 0], by = bias[col + 1], bz = bias[col + 2], bw = bias[col + 3];
        #pragma unroll
        for (int i = 0; i < 4; i++) {
            int row = m0 + ty * 4 + i;
            float4 v = make_float4(acc[i][0] + bx, acc[i][1] + by,
                                   acc[i][2] + bz, acc[i][3] + bw);
            *(float4*)&C[(size_t)row * N + col] = v;
        }
    }
}

// ---------------- fused attention: dec-proj + e + softmax + context -------
__global__ __launch_bounds__(256)
void k_attention(const float* __restrict__ enc_out,
                 const float* __restrict__ W_dec, const float* __restrict__ b_dec,
                 const float* __restrict__ w_full, const float* __restrict__ b_full) {
    const int b = blockIdx.x;
    const int tid = threadIdx.x, lane = tid & 31, wid = tid >> 5;
    __shared__ float s_h[Hd];
    __shared__ float s_dec[Ad];
    __shared__ float s_e[Pd];
    __shared__ float s_red[16];

    for (int i = tid; i < Hd; i += 256) s_h[i] = g_h[b * Hd + i];
    __syncthreads();

    // dec[a] = b_dec[a] + h . W_dec[:,a]   (thread a = tid)
    {
        float a0 = 0.f, a1 = 0.f, a2 = 0.f, a3 = 0.f;
        #pragma unroll 4
        for (int k = 0; k < Hd; k += 4) {
            a0 = fmaf(s_h[k + 0], W_dec[(k + 0) * Ad + tid], a0);
            a1 = fmaf(s_h[k + 1], W_dec[(k + 1) * Ad + tid], a1);
            a2 = fmaf(s_h[k + 2], W_dec[(k + 2) * Ad + tid], a2);
            a3 = fmaf(s_h[k + 3], W_dec[(k + 3) * Ad + tid], a3);
        }
        s_dec[tid] = b_dec[tid] + ((a0 + a1) + (a2 + a3));
    }
    __syncthreads();

    // e[p] = sum_a relu(enc_proj[b,p,a] + dec[a]) * w_full[a] + b_full
    const float* ep_b = g_enc_proj + (size_t)b * Pd * Ad;
    const float bf = b_full[0];
    for (int p = wid; p < Pd; p += 8) {
        const float* ep = ep_b + p * Ad;
        float s = 0.f;
        #pragma unroll
        for (int a = lane; a < Ad; a += 32) {
            float v = ep[a] + s_dec[a];
            v = fmaxf(v, 0.f);
            s = fmaf(v, w_full[a], s);
        }
        #pragma unroll
        for (int o = 16; o > 0; o >>= 1) s += __shfl_xor_sync(0xffffffffu, s, o);
        if (lane == 0) s_e[p] = s + bf;
    }
    __syncthreads();

    // softmax over P (block reduce)
    float m = -1e30f;
    for (int p = tid; p < Pd; p += 256) m = fmaxf(m, s_e[p]);
    #pragma unroll
    for (int o = 16; o > 0; o >>= 1) m = fmaxf(m, __shfl_xor_sync(0xffffffffu, m, o));
    if (lane == 0) s_red[wid] = m;
    __syncthreads();
    float mm = s_red[0];
    #pragma unroll
    for (int i = 1; i < 8; i++) mm = fmaxf(mm, s_red[i]);

    float ss = 0.f;
    for (int p = tid; p < Pd; p += 256) {
        float v = __expf(s_e[p] - mm);
        s_e[p] = v;
        ss += v;
    }
    #pragma unroll
    for (int o = 16; o > 0; o >>= 1) ss += __shfl_xor_sync(0xffffffffu, ss, o);
    if (lane == 0) s_red[8 + wid] = ss;
    __syncthreads();
    float tot = 0.f;
    #pragma unroll
    for (int i = 0; i < 8; i++) tot += s_red[8 + i];
    const float inv = 1.f / tot;

    // context[e'] = (1/tot) * sum_p s_e[p] * enc_out[b,p,e'] -> x[512:1024)
    const float* eo = enc_out + (size_t)b * Pd * Ed;
    float c0 = 0.f, c1 = 0.f;
    for (int p = 0; p < Pd; p++) {
        float al = s_e[p];
        c0 = fmaf(al, eo[p * Ed + tid], c0);
        c1 = fmaf(al, eo[p * Ed + tid + 256], c1);
    }
    g_x[b * KCAT + 2 * Ed/2 + tid]       = c0 * inv;   // 512 + tid
    g_x[b * KCAT + 2 * Ed/2 + tid + 256] = c1 * inv;   // 768 + tid
}

// ---------------- pack x = [emb(tok), (context already written), h] -------
__global__ __launch_bounds__(256)
void k_pack(const int* __restrict__ captions, const float* __restrict__ emb, int t) {
    const int b = blockIdx.x, tid = threadIdx.x;
    const int tok = captions[b * Td + t];
    const float* er = emb + (size_t)tok * Ed;
    float* xr = g_x + b * KCAT;
    xr[tid]        = er[tid];
    xr[tid + 256]  = er[tid + 256];
    xr[1024 + tid]       = g_h[b * Hd + tid];
    xr[1024 + tid + 256] = g_h[b * Hd + tid + 256];
}

// ---------------- LSTM pointwise, write h/c and Hall[t] -------------------
__device__ __forceinline__ float sigf(float x) { return 1.f / (1.f + expf(-x)); }

__global__ __launch_bounds__(256)
void k_lstm(int t) {
    int idx = blockIdx.x * blockDim.x + threadIdx.x;   // Bsz*Hd = 65536
    int b = idx >> 9, j = idx & (Hd - 1);
    const float* g = g_gates + b * G4;
    float i_ = sigf(g[j]);
    float f_ = sigf(g[Hd + j]);
    float gg = tanhf(g[2 * Hd + j]);
    float o_ = sigf(g[3 * Hd + j]);
    float c  = f_ * g_c[idx] + i_ * gg;
    float h  = o_ * tanhf(c);
    g_c[idx] = c;
    g_h[idx] = h;
    g_Hall[((size_t)b * NSTEPS + t) * Hd + j] = h;
}

// ---------------- launcher -------------------------------------------------
extern "C" void kernel_launch(void* const* d_in, const int* in_sizes, int n_in,
                              void* d_out, int out_size) {
    const float* enc     = (const float*)d_in[0];
    const int*   caps    = (const int*)  d_in[1];
    const float* emb     = (const float*)d_in[2];
    const float* W_enc   = (const float*)d_in[3];
    const float* b_enc   = (const float*)d_in[4];
    const float* W_dec   = (const float*)d_in[5];
    const float* b_dec   = (const float*)d_in[6];
    const float* w_full  = (const float*)d_in[7];
    const float* b_full  = (const float*)d_in[8];
    const float* W_ih    = (const float*)d_in[9];
    const float* b_ih    = (const float*)d_in[10];
    const float* W_hh    = (const float*)d_in[11];
    const float* b_hh    = (const float*)d_in[12];
    const float* W_fc    = (const float*)d_in[13];
    const float* b_fc    = (const float*)d_in[14];
    float* out = (float*)d_out;

    float *p_encproj, *p_WencT, *p_Wcat, *p_bcat, *p_x, *p_gates, *p_Hall;
    cudaGetSymbolAddress((void**)&p_encproj, g_enc_proj);
    cudaGetSymbolAddress((void**)&p_WencT,   g_WencT);
    cudaGetSymbolAddress((void**)&p_Wcat,    g_Wcat);
    cudaGetSymbolAddress((void**)&p_bcat,    g_bcat);
    cudaGetSymbolAddress((void**)&p_x,       g_x);
    cudaGetSymbolAddress((void**)&p_gates,   g_gates);
    cudaGetSymbolAddress((void**)&p_Hall,    g_Hall);

    k_prep<<<4096, 256>>>(W_enc, W_ih, b_ih, W_hh, b_hh);

    // enc_proj = encoder_out @ W_enc + b_enc : (25088 x 256), K = 512
    gemm_nt64<<<dim3(Ad / 64, (Bsz * Pd) / 64), 256>>>(
        enc, p_WencT, b_enc, p_encproj, Bsz * Pd, Ad, Ed);

    for (int t = 0; t < NSTEPS; t++) {
        k_attention<<<Bsz, 256>>>(enc, W_dec, b_dec, w_full, b_full);
        k_pack<<<Bsz, 256>>>(caps, emb, t);
        // gates = x @ Wcat^T + bcat : (128 x 2048), K = 1536
        gemm_nt64<<<dim3(G4 / 64, Bsz / 64), 256>>>(
            p_x, p_Wcat, p_bcat, p_gates, Bsz, G4, KCAT);
        k_lstm<<<(Bsz * Hd) / 256, 256>>>(t);
    }

    // out = Hall @ W_fc^T + b_fc : (2560 x 30000), K = 512
    gemm_nt64<<<dim3((Vd + 63) / 64, (Bsz * NSTEPS) / 64), 256>>>(
        p_Hall, W_fc, b_fc, out, Bsz * NSTEPS, Vd, Hd);
}

// round 3
// speedup vs baseline: 1.3382x; 1.3382x over previous
#include <cuda_runtime.h>
#include <cuda_fp16.h>
#include <math.h>
#include <stdint.h>

#define Bsz 128
#define Pd  196
#define Ed  512
#define Hd  512
#define Ad  256
#define Vd  30000
#define Td  21
#define NSTEPS 20
#define KCAT 1536
#define G4   2048

// FC mma.sync GEMM config (fp16 2-term split precision)
#define MROWS  (Bsz * NSTEPS)   // 2560
#define KE2    1024             // [Ahi | Alo] x [Bhi | Bhi]
#define NPAD   30208            // 236 * 128
#define NSLAB  16               // KE2 / 64

// ---------------- device scratch ------------------------------------------
__device__ float g_enc_proj[Bsz * Pd * Ad];
__device__ float g_WencT[Ad * Ed];
__device__ float g_Wcat[G4 * KCAT];
__device__ float g_bcat[G4];
__device__ float g_h[Bsz * Hd];
__device__ float g_c[Bsz * Hd];
__device__ float g_x[Bsz * KCAT];
__device__ float g_gates[Bsz * G4];
__device__ __align__(256) __half g_A2[(size_t)MROWS * KE2];   // 5.2 MB
__device__ __align__(256) __half g_B2[(size_t)NPAD * KE2];    // 62 MB

// ---------------- asm helpers ----------------------------------------------
__device__ __forceinline__ uint32_t smem_u32(const void* p) {
    uint32_t a;
    asm("{ .reg .u64 t; cvta.to.shared.u64 t, %1; cvt.u32.u64 %0, t; }" : "=r"(a) : "l"(p));
    return a;
}
#define LDSM_X4(r0, r1, r2, r3, addr) \
    asm volatile("ldmatrix.sync.aligned.m8n8.x4.shared.b16 {%0,%1,%2,%3}, [%4];" \
                 : "=r"(r0), "=r"(r1), "=r"(r2), "=r"(r3) : "r"(addr))
#define MMA16816(d, a, b0v, b1v) \
    asm volatile("mma.sync.aligned.m16n8k16.row.col.f32.f16.f16.f32 " \
                 "{%0,%1,%2,%3}, {%4,%5,%6,%7}, {%8,%9}, {%0,%1,%2,%3};" \
                 : "+f"((d)[0]), "+f"((d)[1]), "+f"((d)[2]), "+f"((d)[3]) \
                 : "r"((a)[0]), "r"((a)[1]), "r"((a)[2]), "r"((a)[3]), \
                   "r"(b0v), "r"(b1v))

// ---------------- prep ------------------------------------------------------
__global__ void k_prep(const float* __restrict__ W_enc,
                       const float* __restrict__ W_ih, const float* __restrict__ b_ih,
                       const float* __restrict__ W_hh, const float* __restrict__ b_hh) {
    int idx = blockIdx.x * blockDim.x + threadIdx.x;
    int nthr = gridDim.x * blockDim.x;
    if (idx < Ad * Ed) {
        int a = idx / Ed, e = idx % Ed;
        g_WencT[idx] = W_enc[e * Ad + a];
    }
    for (int i = idx; i < G4 * KCAT; i += nthr) {
        int n = i / KCAT, k = i % KCAT;
        g_Wcat[i] = (k < 2 * Ed) ? W_ih[n * (2 * Ed) + k] : W_hh[n * Hd + (k - 2 * Ed)];
    }
    if (idx < G4) g_bcat[idx] = b_ih[idx] + b_hh[idx];
    if (idx < Bsz * Hd) { g_h[idx] = 0.f; g_c[idx] = 0.f; }
}

// ---------------- W_fc -> B2 = [Bhi | Bhi] fp16 ----------------------------
__global__ __launch_bounds__(256)
void k_convert_wfc(const float* __restrict__ W_fc) {
    int idx = blockIdx.x * blockDim.x + threadIdx.x;
    int nthr = gridDim.x * blockDim.x;
    for (int i = idx; i < NPAD * Ed; i += nthr) {
        int n = i >> 9, k = i & 511;
        float v = (n < Vd) ? W_fc[(size_t)n * Ed + k] : 0.f;
        __half hi = __float2half(v);
        size_t base = (size_t)n * KE2;
        g_B2[base + k]       = hi;
        g_B2[base + 512 + k] = hi;
    }
}

// ---------------- SIMT GEMM (enc_proj, gates) ------------------------------
__global__ __launch_bounds__(256)
void gemm_nt64(const float* __restrict__ A, const float* __restrict__ B,
               const float* __restrict__ bias, float* __restrict__ C,
               int M, int N, int K) {
    __shared__ float As[16][64];
    __shared__ float Bs[16][64];
    const int tid = threadIdx.x;
    const int m0 = blockIdx.y * 64;
    const int n0 = blockIdx.x * 64;
    const int tx = tid & 15;
    const int ty = tid >> 4;
    const int lr = tid >> 2;
    const int lk = (tid & 3) << 2;

    const bool bok = (n0 + lr) < N;
    const float* Ap = A + (size_t)(m0 + lr) * K + lk;
    const float* Bp = B + (bok ? (size_t)(n0 + lr) * K + lk : 0);

    float acc[4][4] = {};
    for (int k0 = 0; k0 < K; k0 += 16) {
        float4 av = *(const float4*)(Ap + k0);
        float4 bv = make_float4(0.f, 0.f, 0.f, 0.f);
        if (bok) bv = *(const float4*)(Bp + k0);
        As[lk + 0][lr] = av.x; As[lk + 1][lr] = av.y;
        As[lk + 2][lr] = av.z; As[lk + 3][lr] = av.w;
        Bs[lk + 0][lr] = bv.x; Bs[lk + 1][lr] = bv.y;
        Bs[lk + 2][lr] = bv.z; Bs[lk + 3][lr] = bv.w;
        __syncthreads();
        #pragma unroll
        for (int k = 0; k < 16; k++) {
            float a0 = As[k][ty * 4 + 0], a1 = As[k][ty * 4 + 1];
            float a2 = As[k][ty * 4 + 2], a3 = As[k][ty * 4 + 3];
            float b0 = Bs[k][tx * 4 + 0], b1 = Bs[k][tx * 4 + 1];
            float b2 = Bs[k][tx * 4 + 2], b3 = Bs[k][tx * 4 + 3];
            acc[0][0] = fmaf(a0, b0, acc[0][0]); acc[0][1] = fmaf(a0, b1, acc[0][1]);
            acc[0][2] = fmaf(a0, b2, acc[0][2]); acc[0][3] = fmaf(a0, b3, acc[0][3]);
            acc[1][0] = fmaf(a1, b0, acc[1][0]); acc[1][1] = fmaf(a1, b1, acc[1][1]);
            acc[1][2] = fmaf(a1, b2, acc[1][2]); acc[1][3] = fmaf(a1, b3, acc[1][3]);
            acc[2][0] = fmaf(a2, b0, acc[2][0]); acc[2][1] = fmaf(a2, b1, acc[2][1]);
            acc[2][2] = fmaf(a2, b2, acc[2][2]); acc[2][3] = fmaf(a2, b3, acc[2][3]);
            acc[3][0] = fmaf(a3, b0, acc[3][0]); acc[3][1] = fmaf(a3, b1, acc[3][1]);
            acc[3][2] = fmaf(a3, b2, acc[3][2]); acc[3][3] = fmaf(a3, b3, acc[3][3]);
        }
        __syncthreads();
    }
    int col = n0 + tx * 4;
    if (col < N) {
        float bx = bias[col + 0], by = bias[col + 1], bz = bias[col + 2], bw = bias[col + 3];
        #pragma unroll
        for (int i = 0; i < 4; i++) {
            int row = m0 + ty * 4 + i;
            float4 v = make_float4(acc[i][0] + bx, acc[i][1] + by,
                                   acc[i][2] + bz, acc[i][3] + bw);
            *(float4*)&C[(size_t)row * N + col] = v;
        }
    }
}

// ---------------- fused attention ------------------------------------------
__global__ __launch_bounds__(256)
void k_attention(const float* __restrict__ enc_out,
                 const float* __restrict__ W_dec, const float* __restrict__ b_dec,
                 const float* __restrict__ w_full, const float* __restrict__ b_full) {
    const int b = blockIdx.x;
    const int tid = threadIdx.x, lane = tid & 31, wid = tid >> 5;
    __shared__ float s_h[Hd];
    __shared__ float s_dec[Ad];
    __shared__ float s_e[Pd];
    __shared__ float s_red[16];

    for (int i = tid; i < Hd; i += 256) s_h[i] = g_h[b * Hd + i];
    __syncthreads();
    {
        float a0 = 0.f, a1 = 0.f, a2 = 0.f, a3 = 0.f;
        #pragma unroll 4
        for (int k = 0; k < Hd; k += 4) {
            a0 = fmaf(s_h[k + 0], W_dec[(k + 0) * Ad + tid], a0);
            a1 = fmaf(s_h[k + 1], W_dec[(k + 1) * Ad + tid], a1);
            a2 = fmaf(s_h[k + 2], W_dec[(k + 2) * Ad + tid], a2);
            a3 = fmaf(s_h[k + 3], W_dec[(k + 3) * Ad + tid], a3);
        }
        s_dec[tid] = b_dec[tid] + ((a0 + a1) + (a2 + a3));
    }
    __syncthreads();

    const float* ep_b = g_enc_proj + (size_t)b * Pd * Ad;
    const float bf = b_full[0];
    for (int p = wid; p < Pd; p += 8) {
        const float* ep = ep_b + p * Ad;
        float s = 0.f;
        #pragma unroll
        for (int a = lane; a < Ad; a += 32) {
            float v = ep[a] + s_dec[a];
            v = fmaxf(v, 0.f);
            s = fmaf(v, w_full[a], s);
        }
        #pragma unroll
        for (int o = 16; o > 0; o >>= 1) s += __shfl_xor_sync(0xffffffffu, s, o);
        if (lane == 0) s_e[p] = s + bf;
    }
    __syncthreads();

    float m = -1e30f;
    for (int p = tid; p < Pd; p += 256) m = fmaxf(m, s_e[p]);
    #pragma unroll
    for (int o = 16; o > 0; o >>= 1) m = fmaxf(m, __shfl_xor_sync(0xffffffffu, m, o));
    if (lane == 0) s_red[wid] = m;
    __syncthreads();
    float mm = s_red[0];
    #pragma unroll
    for (int i = 1; i < 8; i++) mm = fmaxf(mm, s_red[i]);

    float ss = 0.f;
    for (int p = tid; p < Pd; p += 256) {
        float v = __expf(s_e[p] - mm);
        s_e[p] = v;
        ss += v;
    }
    #pragma unroll
    for (int o = 16; o > 0; o >>= 1) ss += __shfl_xor_sync(0xffffffffu, ss, o);
    if (lane == 0) s_red[8 + wid] = ss;
    __syncthreads();
    float tot = 0.f;
    #pragma unroll
    for (int i = 0; i < 8; i++) tot += s_red[8 + i];
    const float inv = 1.f / tot;

    const float* eo = enc_out + (size_t)b * Pd * Ed;
    float c0 = 0.f, c1 = 0.f;
    for (int p = 0; p < Pd; p++) {
        float al = s_e[p];
        c0 = fmaf(al, eo[p * Ed + tid], c0);
        c1 = fmaf(al, eo[p * Ed + tid + 256], c1);
    }
    g_x[b * KCAT + 512 + tid]       = c0 * inv;
    g_x[b * KCAT + 512 + tid + 256] = c1 * inv;
}

// ---------------- pack x = [emb, ctx, h] -----------------------------------
__global__ __launch_bounds__(256)
void k_pack(const int* __restrict__ captions, const float* __restrict__ emb, int t) {
    const int b = blockIdx.x, tid = threadIdx.x;
    const int tok = captions[b * Td + t];
    const float* er = emb + (size_t)tok * Ed;
    float* xr = g_x + b * KCAT;
    xr[tid]        = er[tid];
    xr[tid + 256]  = er[tid + 256];
    xr[1024 + tid]       = g_h[b * Hd + tid];
    xr[1024 + tid + 256] = g_h[b * Hd + tid + 256];
}

// ---------------- LSTM pointwise: writes split-fp16 h into A2 --------------
__device__ __forceinline__ float sigf(float x) { return 1.f / (1.f + expf(-x)); }

__global__ __launch_bounds__(256)
void k_lstm(int t) {
    int idx = blockIdx.x * blockDim.x + threadIdx.x;
    int b = idx >> 9, j = idx & (Hd - 1);
    const float* g = g_gates + b * G4;
    float i_ = sigf(g[j]);
    float f_ = sigf(g[Hd + j]);
    float gg = tanhf(g[2 * Hd + j]);
    float o_ = sigf(g[3 * Hd + j]);
    float c  = f_ * g_c[idx] + i_ * gg;
    float h  = o_ * tanhf(c);
    g_c[idx] = c;
    g_h[idx] = h;
    __half hi = __float2half(h);
    float  lo = h - __half2float(hi);
    size_t base = ((size_t)b * NSTEPS + t) * KE2;
    g_A2[base + j]       = hi;
    g_A2[base + 512 + j] = __float2half(lo);
}

// ---------------- FC GEMM via mma.sync fp16 --------------------------------
// CTA tile 128x128, 8 warps (4 M x 2 N), warp tile 32x64. K slab = 64 fp16.
// dyn smem: A buf0 @0, A buf1 @16384, B buf0 @32768, B buf1 @49152. 64 KB.
__global__ __launch_bounds__(256, 2)
void k_fc(const float* __restrict__ b_fc, float* __restrict__ C) {
    extern __shared__ char smem[];
    const int tid = threadIdx.x, lane = tid & 31, wid = tid >> 5;
    const int m0 = blockIdx.x * 128;
    const int n0 = blockIdx.y * 128;
    const int wm = wid >> 1;          // 0..3
    const int wn = wid & 1;           // 0..1
    const uint32_t sb = smem_u32(smem);

    const __half* Ab = g_A2 + (size_t)m0 * KE2;
    const __half* Bb = g_B2 + (size_t)n0 * KE2;

    // ldmatrix per-lane addressing (pre-swizzled row components)
    const int a_r  = lane & 15;
    const int a_cb = (lane >> 4) * 16;
    const uint32_t a_row = (uint32_t)(wm * 32 + a_r) * 128;
    const uint32_t a_msk = (uint32_t)(a_r & 7) << 4;
    const int b_r  = (lane & 7) + ((lane >> 4) << 3);
    const int b_cb = ((lane >> 3) & 1) * 16;
    const uint32_t b_row = (uint32_t)(wn * 64 + b_r) * 128;
    const uint32_t b_msk = (uint32_t)(b_r & 7) << 4;

    // gmem/smem slab copy addressing: 4x 16B per thread per matrix
    int c_row[4], c_off[4];
    #pragma unroll
    for (int u = 0; u < 4; u++) {
        int e = tid + 256 * u;
        c_row[u] = e >> 3;
        int ch   = e & 7;
        c_off[u] = c_row[u] * 128 + ((ch * 16) ^ ((c_row[u] & 7) << 4));
    }

    float d[2][8][4] = {};

    uint4 ra[4], rb[4];
    #pragma unroll
    for (int u = 0; u < 4; u++) {
        ra[u] = *(const uint4*)(Ab + (size_t)c_row[u] * KE2 + (tid & 7) * 8 + (u ? 0 : 0) + ( (tid + 256*u) & 7) * 0 );
    }
    // (proper prologue below; the loop body re-issues loads uniformly)
    #pragma unroll
    for (int u = 0; u < 4; u++) {
        int e = tid + 256 * u;
        int row = e >> 3, ch = e & 7;
        ra[u] = *(const uint4*)(Ab + (size_t)row * KE2 + ch * 8);
        rb[u] = *(const uint4*)(Bb + (size_t)row * KE2 + ch * 8);
    }

    for (int s = 0; s < NSLAB; s++) {
        const int p = s & 1;
        // store current slab regs to smem buffer p
        #pragma unroll
        for (int u = 0; u < 4; u++) {
            *(uint4*)(smem + p * 16384 + c_off[u])         = ra[u];
            *(uint4*)(smem + 32768 + p * 16384 + c_off[u]) = rb[u];
        }
        // prefetch next slab
        if (s + 1 < NSLAB) {
            #pragma unroll
            for (int u = 0; u < 4; u++) {
                int e = tid + 256 * u;
                int row = e >> 3, ch = e & 7;
                ra[u] = *(const uint4*)(Ab + (size_t)row * KE2 + (s + 1) * 64 + ch * 8);
                rb[u] = *(const uint4*)(Bb + (size_t)row * KE2 + (s + 1) * 64 + ch * 8);
            }
        }
        __syncthreads();

        const uint32_t abase = sb + p * 16384;
        const uint32_t bbase = sb + 32768 + p * 16384;
        #pragma unroll
        for (int ks = 0; ks < 4; ks++) {
            uint32_t afr[2][4];
            {
                uint32_t byte = (uint32_t)((ks * 32 + a_cb)) ^ a_msk;
                uint32_t ad0 = abase + a_row + byte;
                LDSM_X4(afr[0][0], afr[0][1], afr[0][2], afr[0][3], ad0);
                LDSM_X4(afr[1][0], afr[1][1], afr[1][2], afr[1][3], ad0 + 2048);
            }
            #pragma unroll
            for (int g = 0; g < 3 + 1; g++) {
                uint32_t bfr[4];
                uint32_t byte = (uint32_t)((ks * 32 + b_cb)) ^ b_msk;
                uint32_t bd = bbase + b_row + g * 2048 + byte;
                LDSM_X4(bfr[0], bfr[1], bfr[2], bfr[3], bd);
                MMA16816(d[0][2 * g],     afr[0], bfr[0], bfr[1]);
                MMA16816(d[0][2 * g + 1], afr[0], bfr[2], bfr[3]);
                MMA16816(d[1][2 * g],     afr[1], bfr[0], bfr[1]);
                MMA16816(d[1][2 * g + 1], afr[1], bfr[2], bfr[3]);
            }
        }
    }

    // epilogue: direct global write with bias
    #pragma unroll
    for (int j = 0; j < 8; j++) {
        int col = n0 + wn * 64 + j * 8 + (lane & 3) * 2;
        if (col < Vd) {
            float bb0 = b_fc[col], bb1 = b_fc[col + 1];
            #pragma unroll
            for (int i = 0; i < 2; i++) {
                size_t r0 = (size_t)(m0 + wm * 32 + i * 16 + (lane >> 2));
                float2 v0 = make_float2(d[i][j][0] + bb0, d[i][j][1] + bb1);
                *(float2*)&C[r0 * Vd + col] = v0;
                float2 v1 = make_float2(d[i][j][2] + bb0, d[i][j][3] + bb1);
                *(float2*)&C[(r0 + 8) * Vd + col] = v1;
            }
        }
    }
}

// ---------------- launcher -------------------------------------------------
extern "C" void kernel_launch(void* const* d_in, const int* in_sizes, int n_in,
                              void* d_out, int out_size) {
    const float* enc     = (const float*)d_in[0];
    const int*   caps    = (const int*)  d_in[1];
    const float* emb     = (const float*)d_in[2];
    const float* W_enc   = (const float*)d_in[3];
    const float* b_enc   = (const float*)d_in[4];
    const float* W_dec   = (const float*)d_in[5];
    const float* b_dec   = (const float*)d_in[6];
    const float* w_full  = (const float*)d_in[7];
    const float* b_full  = (const float*)d_in[8];
    const float* W_ih    = (const float*)d_in[9];
    const float* b_ih    = (const float*)d_in[10];
    const float* W_hh    = (const float*)d_in[11];
    const float* b_hh    = (const float*)d_in[12];
    const float* W_fc    = (const float*)d_in[13];
    const float* b_fc    = (const float*)d_in[14];
    float* out = (float*)d_out;

    cudaFuncSetAttribute(k_fc, cudaFuncAttributeMaxDynamicSharedMemorySize, 65536);

    float *p_encproj, *p_WencT, *p_Wcat, *p_bcat, *p_x, *p_gates;
    cudaGetSymbolAddress((void**)&p_encproj, g_enc_proj);
    cudaGetSymbolAddress((void**)&p_WencT,   g_WencT);
    cudaGetSymbolAddress((void**)&p_Wcat,    g_Wcat);
    cudaGetSymbolAddress((void**)&p_bcat,    g_bcat);
    cudaGetSymbolAddress((void**)&p_x,       g_x);
    cudaGetSymbolAddress((void**)&p_gates,   g_gates);

    k_prep<<<4096, 256>>>(W_enc, W_ih, b_ih, W_hh, b_hh);
    k_convert_wfc<<<4096, 256>>>(W_fc);

    gemm_nt64<<<dim3(Ad / 64, (Bsz * Pd) / 64), 256>>>(
        enc, p_WencT, b_enc, p_encproj, Bsz * Pd, Ad, Ed);

    for (int t = 0; t < NSTEPS; t++) {
        k_attention<<<Bsz, 256>>>(enc, W_dec, b_dec, w_full, b_full);
        k_pack<<<Bsz, 256>>>(caps, emb, t);
        gemm_nt64<<<dim3(G4 / 64, Bsz / 64), 256>>>(
            p_x, p_Wcat, p_bcat, p_gates, Bsz, G4, KCAT);
        k_lstm<<<(Bsz * Hd) / 256, 256>>>(t);
    }

    // out = Hall @ W_fc^T + b_fc via mma.sync fp16 2-term split
    k_fc<<<dim3(MROWS / 128, NPAD / 128), 256, 65536>>>(b_fc, out);
}

// round 5
// speedup vs baseline: 1.9109x; 1.4280x over previous
#include <cuda_runtime.h>
#include <cuda_fp16.h>
#include <math.h>
#include <stdint.h>

#define Bsz 128
#define Pd  196
#define Ed  512
#define Hd  512
#define Ad  256
#define Vd  30000
#define Td  21
#define NSTEPS 20
#define KCAT 1536
#define G4   2048
#define KSPLIT 8
#define KSK   (KCAT / KSPLIT)    // 192

// FC mma.sync GEMM config (fp16 2-term split precision)
#define MROWS  (Bsz * NSTEPS)   // 2560
#define KE2    1024             // [Ahi | Alo] x [Bhi | Bhi]
#define NPAD   30208            // 236 * 128
#define NSLAB  16               // KE2 / 64

// ---------------- device scratch ------------------------------------------
__device__ float g_enc_proj[Bsz * Pd * Ad];
__device__ float g_WencT[Ad * Ed];
__device__ float g_Wcat[G4 * KCAT];
__device__ float g_bcat[G4];
__device__ float g_h[Bsz * Hd];
__device__ float g_c[Bsz * Hd];
__device__ float g_dec[Bsz * Ad];
__device__ float g_e[Bsz * Pd];
__device__ float g_xall[NSTEPS * Bsz * KCAT];          // 15.7 MB
__device__ float g_gpart[KSPLIT][Bsz * G4];            // 8 MB
__device__ __align__(256) __half g_A2[(size_t)MROWS * KE2];
__device__ __align__(256) __half g_B2[(size_t)NPAD * KE2];

// ---------------- asm helpers ----------------------------------------------
__device__ __forceinline__ uint32_t smem_u32(const void* p) {
    uint32_t a;
    asm("{ .reg .u64 t; cvta.to.shared.u64 t, %1; cvt.u32.u64 %0, t; }" : "=r"(a) : "l"(p));
    return a;
}
#define LDSM_X4(r0, r1, r2, r3, addr) \
    asm volatile("ldmatrix.sync.aligned.m8n8.x4.shared.b16 {%0,%1,%2,%3}, [%4];" \
                 : "=r"(r0), "=r"(r1), "=r"(r2), "=r"(r3) : "r"(addr))
#define MMA16816(d, a, b0v, b1v) \
    asm volatile("mma.sync.aligned.m16n8k16.row.col.f32.f16.f16.f32 " \
                 "{%0,%1,%2,%3}, {%4,%5,%6,%7}, {%8,%9}, {%0,%1,%2,%3};" \
                 : "+f"((d)[0]), "+f"((d)[1]), "+f"((d)[2]), "+f"((d)[3]) \
                 : "r"((a)[0]), "r"((a)[1]), "r"((a)[2]), "r"((a)[3]), \
                   "r"(b0v), "r"(b1v))

// ---------------- prep ------------------------------------------------------
__global__ void k_prep(const float* __restrict__ W_enc,
                       const float* __restrict__ W_ih, const float* __restrict__ b_ih,
                       const float* __restrict__ W_hh, const float* __restrict__ b_hh) {
    int idx = blockIdx.x * blockDim.x + threadIdx.x;
    int nthr = gridDim.x * blockDim.x;
    if (idx < Ad * Ed) {
        int a = idx / Ed, e = idx % Ed;
        g_WencT[idx] = W_enc[e * Ad + a];
    }
    for (int i = idx; i < G4 * KCAT; i += nthr) {
        int n = i / KCAT, k = i % KCAT;
        g_Wcat[i] = (k < 2 * Ed) ? W_ih[n * (2 * Ed) + k] : W_hh[n * Hd + (k - 2 * Ed)];
    }
    if (idx < G4) g_bcat[idx] = b_ih[idx] + b_hh[idx];
    if (idx < Bsz * Hd) { g_h[idx] = 0.f; g_c[idx] = 0.f; }
}

// ---------------- prefill x buffers: emb slots for all t, h-slot of t=0 ----
__global__ __launch_bounds__(256)
void k_prefill(const int* __restrict__ captions, const float* __restrict__ emb) {
    int idx = blockIdx.x * blockDim.x + threadIdx.x;
    // emb sections: NSTEPS * Bsz * Ed elements
    if (idx < NSTEPS * Bsz * Ed) {
        int j = idx & (Ed - 1);
        int bt = idx >> 9;
        int b = bt & (Bsz - 1);
        int t = bt >> 7;
        int tok = captions[b * Td + t];
        g_xall[((size_t)t * Bsz + b) * KCAT + j] = emb[(size_t)tok * Ed + j];
    }
    // zero h-slot of t = 0
    if (idx < Bsz * Hd) {
        int b = idx >> 9, j = idx & (Hd - 1);
        g_xall[(size_t)b * KCAT + 1024 + j] = 0.f;
    }
}

// ---------------- W_fc -> B2 = [Bhi | Bhi] fp16 ----------------------------
__global__ __launch_bounds__(256)
void k_convert_wfc(const float* __restrict__ W_fc) {
    int idx = blockIdx.x * blockDim.x + threadIdx.x;
    int nthr = gridDim.x * blockDim.x;
    for (int i = idx; i < NPAD * Ed; i += nthr) {
        int n = i >> 9, k = i & 511;
        float v = (n < Vd) ? W_fc[(size_t)n * Ed + k] : 0.f;
        __half hi = __float2half(v);
        size_t base = (size_t)n * KE2;
        g_B2[base + k]       = hi;
        g_B2[base + 512 + k] = hi;
    }
}

// ---------------- SIMT GEMM (enc_proj) -------------------------------------
__global__ __launch_bounds__(256)
void gemm_nt64(const float* __restrict__ A, const float* __restrict__ B,
               const float* __restrict__ bias, float* __restrict__ C,
               int M, int N, int K) {
    __shared__ float As[16][64];
    __shared__ float Bs[16][64];
    const int tid = threadIdx.x;
    const int m0 = blockIdx.y * 64;
    const int n0 = blockIdx.x * 64;
    const int tx = tid & 15;
    const int ty = tid >> 4;
    const int lr = tid >> 2;
    const int lk = (tid & 3) << 2;

    const float* Ap = A + (size_t)(m0 + lr) * K + lk;
    const float* Bp = B + (size_t)(n0 + lr) * K + lk;

    float acc[4][4] = {};
    for (int k0 = 0; k0 < K; k0 += 16) {
        float4 av = *(const float4*)(Ap + k0);
        float4 bv = *(const float4*)(Bp + k0);
        As[lk + 0][lr] = av.x; As[lk + 1][lr] = av.y;
        As[lk + 2][lr] = av.z; As[lk + 3][lr] = av.w;
        Bs[lk + 0][lr] = bv.x; Bs[lk + 1][lr] = bv.y;
        Bs[lk + 2][lr] = bv.z; Bs[lk + 3][lr] = bv.w;
        __syncthreads();
        #pragma unroll
        for (int k = 0; k < 16; k++) {
            float a0 = As[k][ty * 4 + 0], a1 = As[k][ty * 4 + 1];
            float a2 = As[k][ty * 4 + 2], a3 = As[k][ty * 4 + 3];
            float b0 = Bs[k][tx * 4 + 0], b1 = Bs[k][tx * 4 + 1];
            float b2 = Bs[k][tx * 4 + 2], b3 = Bs[k][tx * 4 + 3];
            acc[0][0] = fmaf(a0, b0, acc[0][0]); acc[0][1] = fmaf(a0, b1, acc[0][1]);
            acc[0][2] = fmaf(a0, b2, acc[0][2]); acc[0][3] = fmaf(a0, b3, acc[0][3]);
            acc[1][0] = fmaf(a1, b0, acc[1][0]); acc[1][1] = fmaf(a1, b1, acc[1][1]);
            acc[1][2] = fmaf(a1, b2, acc[1][2]); acc[1][3] = fmaf(a1, b3, acc[1][3]);
            acc[2][0] = fmaf(a2, b0, acc[2][0]); acc[2][1] = fmaf(a2, b1, acc[2][1]);
            acc[2][2] = fmaf(a2, b2, acc[2][2]); acc[2][3] = fmaf(a2, b3, acc[2][3]);
            acc[3][0] = fmaf(a3, b0, acc[3][0]); acc[3][1] = fmaf(a3, b1, acc[3][1]);
            acc[3][2] = fmaf(a3, b2, acc[3][2]); acc[3][3] = fmaf(a3, b3, acc[3][3]);
        }
        __syncthreads();
    }
    int col = n0 + tx * 4;
    float bx = bias[col + 0], by = bias[col + 1], bz = bias[col + 2], bw = bias[col + 3];
    #pragma unroll
    for (int i = 0; i < 4; i++) {
        int row = m0 + ty * 4 + i;
        float4 v = make_float4(acc[i][0] + bx, acc[i][1] + by,
                               acc[i][2] + bz, acc[i][3] + bw);
        *(float4*)&C[(size_t)row * N + col] = v;
    }
}

// ---------------- gates GEMM, split-K partials -----------------------------
// A = g_xall[t] (128 x 1536), B = g_Wcat (2048 x 1536)
// grid (G4/64=32, Bsz/64=2, KSPLIT)
__global__ __launch_bounds__(256)
void gemm_gates_sk(const float* __restrict__ A) {
    __shared__ float As[16][64];
    __shared__ float Bs[16][64];
    const int tid = threadIdx.x;
    const int m0 = blockIdx.y * 64;
    const int n0 = blockIdx.x * 64;
    const int ks = blockIdx.z;
    const int tx = tid & 15;
    const int ty = tid >> 4;
    const int lr = tid >> 2;
    const int lk = (tid & 3) << 2;

    const float* Ap = A + (size_t)(m0 + lr) * KCAT + ks * KSK + lk;
    const float* Bp = g_Wcat + (size_t)(n0 + lr) * KCAT + ks * KSK + lk;

    float acc[4][4] = {};
    for (int k0 = 0; k0 < KSK; k0 += 16) {
        float4 av = *(const float4*)(Ap + k0);
        float4 bv = *(const float4*)(Bp + k0);
        As[lk + 0][lr] = av.x; As[lk + 1][lr] = av.y;
        As[lk + 2][lr] = av.z; As[lk + 3][lr] = av.w;
        Bs[lk + 0][lr] = bv.x; Bs[lk + 1][lr] = bv.y;
        Bs[lk + 2][lr] = bv.z; Bs[lk + 3][lr] = bv.w;
        __syncthreads();
        #pragma unroll
        for (int k = 0; k < 16; k++) {
            float a0 = As[k][ty * 4 + 0], a1 = As[k][ty * 4 + 1];
            float a2 = As[k][ty * 4 + 2], a3 = As[k][ty * 4 + 3];
            float b0 = Bs[k][tx * 4 + 0], b1 = Bs[k][tx * 4 + 1];
            float b2 = Bs[k][tx * 4 + 2], b3 = Bs[k][tx * 4 + 3];
            acc[0][0] = fmaf(a0, b0, acc[0][0]); acc[0][1] = fmaf(a0, b1, acc[0][1]);
            acc[0][2] = fmaf(a0, b2, acc[0][2]); acc[0][3] = fmaf(a0, b3, acc[0][3]);
            acc[1][0] = fmaf(a1, b0, acc[1][0]); acc[1][1] = fmaf(a1, b1, acc[1][1]);
            acc[1][2] = fmaf(a1, b2, acc[1][2]); acc[1][3] = fmaf(a1, b3, acc[1][3]);
            acc[2][0] = fmaf(a2, b0, acc[2][0]); acc[2][1] = fmaf(a2, b1, acc[2][1]);
            acc[2][2] = fmaf(a2, b2, acc[2][2]); acc[2][3] = fmaf(a2, b3, acc[2][3]);
            acc[3][0] = fmaf(a3, b0, acc[3][0]); acc[3][1] = fmaf(a3, b1, acc[3][1]);
            acc[3][2] = fmaf(a3, b2, acc[3][2]); acc[3][3] = fmaf(a3, b3, acc[3][3]);
        }
        __syncthreads();
    }
    float* Cp = g_gpart[ks];
    int col = n0 + tx * 4;
    #pragma unroll
    for (int i = 0; i < 4; i++) {
        int row = m0 + ty * 4 + i;
        *(float4*)&Cp[(size_t)row * G4 + col] =
            make_float4(acc[i][0], acc[i][1], acc[i][2], acc[i][3]);
    }
}

// ---------------- k_dec: dec = h @ W_dec + b_dec, 4 batches per block ------
__global__ __launch_bounds__(256)
void k_dec(const float* __restrict__ W_dec, const float* __restrict__ b_dec) {
    __shared__ float sh[4][Hd];
    const int tid = threadIdx.x;
    const int b0 = blockIdx.x * 4;
    for (int i = tid; i < 4 * Hd; i += 256)
        sh[i >> 9][i & (Hd - 1)] = g_h[(b0 + (i >> 9)) * Hd + (i & (Hd - 1))];
    __syncthreads();
    float a0 = 0.f, a1 = 0.f, a2 = 0.f, a3 = 0.f;
    #pragma unroll 4
    for (int k = 0; k < Hd; k++) {
        float w = W_dec[k * Ad + tid];
        a0 = fmaf(sh[0][k], w, a0);
        a1 = fmaf(sh[1][k], w, a1);
        a2 = fmaf(sh[2][k], w, a2);
        a3 = fmaf(sh[3][k], w, a3);
    }
    float bd = b_dec[tid];
    g_dec[(b0 + 0) * Ad + tid] = a0 + bd;
    g_dec[(b0 + 1) * Ad + tid] = a1 + bd;
    g_dec[(b0 + 2) * Ad + tid] = a2 + bd;
    g_dec[(b0 + 3) * Ad + tid] = a3 + bd;
}

// ---------------- k_att_e: e[b,p] = relu(enc_proj + dec).w_full + b --------
// grid (7, 128), block 256; block handles 28 p's for one b
__global__ __launch_bounds__(256)
void k_att_e(const float* __restrict__ w_full, const float* __restrict__ b_full) {
    const int b = blockIdx.y;
    const int p0 = blockIdx.x * 28;
    const int tid = threadIdx.x, lane = tid & 31, wid = tid >> 5;
    __shared__ float s_dec[Ad];
    __shared__ float s_wf[Ad];
    if (tid < Ad) {
        s_dec[tid] = g_dec[b * Ad + tid];
        s_wf[tid]  = w_full[tid];
    }
    __syncthreads();
    const float bf = b_full[0];
    const float* ep_b = g_enc_proj + (size_t)b * Pd * Ad;
    for (int p = p0 + wid; p < p0 + 28; p += 8) {
        const float* ep = ep_b + p * Ad;
        float s = 0.f;
        #pragma unroll
        for (int i = 0; i < 8; i++) {
            int a = lane + 32 * i;
            float v = ep[a] + s_dec[a];
            s = fmaf(fmaxf(v, 0.f), s_wf[a], s);
        }
        #pragma unroll
        for (int o = 16; o > 0; o >>= 1) s += __shfl_xor_sync(0xffffffffu, s, o);
        if (lane == 0) g_e[b * Pd + p] = s + bf;
    }
}

// ---------------- k_ctx: softmax(e) then context -> x[t] ctx slot ----------
// grid (4, 128), block 128; chunk of 128 e-dims per block
__global__ __launch_bounds__(128)
void k_ctx(const float* __restrict__ enc_out, int t) {
    const int b = blockIdx.y;
    const int ec = blockIdx.x;
    const int tid = threadIdx.x, lane = tid & 31, wid = tid >> 5;
    __shared__ float s_a[Pd];
    __shared__ float s_red[8];

    float v0 = (tid < Pd) ? g_e[b * Pd + tid] : -1e30f;
    float v1 = (tid + 128 < Pd) ? g_e[b * Pd + tid + 128] : -1e30f;
    float m = fmaxf(v0, v1);
    #pragma unroll
    for (int o = 16; o > 0; o >>= 1) m = fmaxf(m, __shfl_xor_sync(0xffffffffu, m, o));
    if (lane == 0) s_red[wid] = m;
    __syncthreads();
    float mm = fmaxf(fmaxf(s_red[0], s_red[1]), fmaxf(s_red[2], s_red[3]));

    float e0 = (tid < Pd) ? __expf(v0 - mm) : 0.f;
    float e1 = (tid + 128 < Pd) ? __expf(v1 - mm) : 0.f;
    if (tid < Pd) s_a[tid] = e0;
    if (tid + 128 < Pd) s_a[tid + 128] = e1;
    float ss = e0 + e1;
    #pragma unroll
    for (int o = 16; o > 0; o >>= 1) ss += __shfl_xor_sync(0xffffffffu, ss, o);
    if (lane == 0) s_red[4 + wid] = ss;
    __syncthreads();
    const float inv = 1.f / (s_red[4] + s_red[5] + s_red[6] + s_red[7]);

    const int e = ec * 128 + tid;
    const float* eo = enc_out + (size_t)b * Pd * Ed + e;
    float acc = 0.f;
    #pragma unroll 4
    for (int p = 0; p < Pd; p++)
        acc = fmaf(s_a[p], eo[(size_t)p * Ed], acc);
    g_xall[((size_t)t * Bsz + b) * KCAT + 512 + e] = acc * inv;
}

// ---------------- LSTM pointwise + partial reduction -----------------------
__device__ __forceinline__ float sigf(float x) { return 1.f / (1.f + expf(-x)); }

__global__ __launch_bounds__(256)
void k_lstm(int t) {
    int idx = blockIdx.x * blockDim.x + threadIdx.x;   // 65536
    int b = idx >> 9, j = idx & (Hd - 1);
    int base = b * G4 + j;
    float gi = g_bcat[j], gf = g_bcat[Hd + j], gg = g_bcat[2 * Hd + j], go = g_bcat[3 * Hd + j];
    #pragma unroll
    for (int s = 0; s < KSPLIT; s++) {
        gi += g_gpart[s][base];
        gf += g_gpart[s][base + Hd];
        gg += g_gpart[s][base + 2 * Hd];
        go += g_gpart[s][base + 3 * Hd];
    }
    float i_ = sigf(gi);
    float f_ = sigf(gf);
    float g_ = tanhf(gg);
    float o_ = sigf(go);
    float c  = f_ * g_c[idx] + i_ * g_;
    float h  = o_ * tanhf(c);
    g_c[idx] = c;
    g_h[idx] = h;
    if (t + 1 < NSTEPS)
        g_xall[((size_t)(t + 1) * Bsz + b) * KCAT + 1024 + j] = h;
    __half hi = __float2half(h);
    float  lo = h - __half2float(hi);
    size_t ab = ((size_t)b * NSTEPS + t) * KE2;
    g_A2[ab + j]       = hi;
    g_A2[ab + 512 + j] = __float2half(lo);
}

// ---------------- FC GEMM via mma.sync fp16 --------------------------------
__global__ __launch_bounds__(256, 2)
void k_fc(const float* __restrict__ b_fc, float* __restrict__ C) {
    extern __shared__ char smem[];
    const int tid = threadIdx.x, lane = tid & 31, wid = tid >> 5;
    const int m0 = blockIdx.x * 128;
    const int n0 = blockIdx.y * 128;
    const int wm = wid >> 1;
    const int wn = wid & 1;
    const uint32_t sb = smem_u32(smem);

    const __half* Ab = g_A2 + (size_t)m0 * KE2;
    const __half* Bb = g_B2 + (size_t)n0 * KE2;

    const int a_r  = lane & 15;
    const int a_cb = (lane >> 4) * 16;
    const uint32_t a_row = (uint32_t)(wm * 32 + a_r) * 128;
    const uint32_t a_msk = (uint32_t)(a_r & 7) << 4;
    const int b_r  = (lane & 7) + ((lane >> 4) << 3);
    const int b_cb = ((lane >> 3) & 1) * 16;
    const uint32_t b_row = (uint32_t)(wn * 64 + b_r) * 128;
    const uint32_t b_msk = (uint32_t)(b_r & 7) << 4;

    int c_row[4], c_off[4];
    #pragma unroll
    for (int u = 0; u < 4; u++) {
        int e = tid + 256 * u;
        c_row[u] = e >> 3;
        int ch   = e & 7;
        c_off[u] = c_row[u] * 128 + ((ch * 16) ^ ((c_row[u] & 7) << 4));
    }

    float d[2][8][4] = {};
    uint4 ra[4], rb[4];
    #pragma unroll
    for (int u = 0; u < 4; u++) {
        int e = tid + 256 * u;
        int row = e >> 3, ch = e & 7;
        ra[u] = *(const uint4*)(Ab + (size_t)row * KE2 + ch * 8);
        rb[u] = *(const uint4*)(Bb + (size_t)row * KE2 + ch * 8);
    }

    for (int s = 0; s < NSLAB; s++) {
        const int p = s & 1;
        #pragma unroll
        for (int u = 0; u < 4; u++) {
            *(uint4*)(smem + p * 16384 + c_off[u])         = ra[u];
            *(uint4*)(smem + 32768 + p * 16384 + c_off[u]) = rb[u];
        }
        if (s + 1 < NSLAB) {
            #pragma unroll
            for (int u = 0; u < 4; u++) {
                int e = tid + 256 * u;
                int row = e >> 3, ch = e & 7;
                ra[u] = *(const uint4*)(Ab + (size_t)row * KE2 + (s + 1) * 64 + ch * 8);
                rb[u] = *(const uint4*)(Bb + (size_t)row * KE2 + (s + 1) * 64 + ch * 8);
            }
        }
        __syncthreads();

        const uint32_t abase = sb + p * 16384;
        const uint32_t bbase = sb + 32768 + p * 16384;
        #pragma unroll
        for (int ks = 0; ks < 4; ks++) {
            uint32_t afr[2][4];
            {
                uint32_t byte = (uint32_t)((ks * 32 + a_cb)) ^ a_msk;
                uint32_t ad0 = abase + a_row + byte;
                LDSM_X4(afr[0][0], afr[0][1], afr[0][2], afr[0][3], ad0);
                LDSM_X4(afr[1][0], afr[1][1], afr[1][2], afr[1][3], ad0 + 2048);
            }
            #pragma unroll
            for (int g = 0; g < 4; g++) {
                uint32_t bfr[4];
                uint32_t byte = (uint32_t)((ks * 32 + b_cb)) ^ b_msk;
                uint32_t bd = bbase + b_row + g * 2048 + byte;
                LDSM_X4(bfr[0], bfr[1], bfr[2], bfr[3], bd);
                MMA16816(d[0][2 * g],     afr[0], bfr[0], bfr[1]);
                MMA16816(d[0][2 * g + 1], afr[0], bfr[2], bfr[3]);
                MMA16816(d[1][2 * g],     afr[1], bfr[0], bfr[1]);
                MMA16816(d[1][2 * g + 1], afr[1], bfr[2], bfr[3]);
            }
        }
        __syncthreads();
    }

    #pragma unroll
    for (int j = 0; j < 8; j++) {
        int col = n0 + wn * 64 + j * 8 + (lane & 3) * 2;
        if (col < Vd) {
            float bb0 = b_fc[col], bb1 = b_fc[col + 1];
            #pragma unroll
            for (int i = 0; i < 2; i++) {
                size_t r0 = (size_t)(m0 + wm * 32 + i * 16 + (lane >> 2));
                float2 v0 = make_float2(d[i][j][0] + bb0, d[i][j][1] + bb1);
                *(float2*)&C[r0 * Vd + col] = v0;
                float2 v1 = make_float2(d[i][j][2] + bb0, d[i][j][3] + bb1);
                *(float2*)&C[(r0 + 8) * Vd + col] = v1;
            }
        }
    }
}

// ---------------- launcher -------------------------------------------------
extern "C" void kernel_launch(void* const* d_in, const int* in_sizes, int n_in,
                              void* d_out, int out_size) {
    const float* enc     = (const float*)d_in[0];
    const int*   caps    = (const int*)  d_in[1];
    const float* emb     = (const float*)d_in[2];
    const float* W_enc   = (const float*)d_in[3];
    const float* b_enc   = (const float*)d_in[4];
    const float* W_dec   = (const float*)d_in[5];
    const float* b_dec   = (const float*)d_in[6];
    const float* w_full  = (const float*)d_in[7];
    const float* b_full  = (const float*)d_in[8];
    const float* W_ih    = (const float*)d_in[9];
    const float* b_ih    = (const float*)d_in[10];
    const float* W_hh    = (const float*)d_in[11];
    const float* b_hh    = (const float*)d_in[12];
    const float* W_fc    = (const float*)d_in[13];
    const float* b_fc    = (const float*)d_in[14];
    float* out = (float*)d_out;

    cudaFuncSetAttribute(k_fc, cudaFuncAttributeMaxDynamicSharedMemorySize, 65536);

    float *p_encproj, *p_WencT, *p_xall;
    cudaGetSymbolAddress((void**)&p_encproj, g_enc_proj);
    cudaGetSymbolAddress((void**)&p_WencT,   g_WencT);
    cudaGetSymbolAddress((void**)&p_xall,    g_xall);

    k_prep<<<4096, 256>>>(W_enc, W_ih, b_ih, W_hh, b_hh);
    k_prefill<<<(NSTEPS * Bsz * Ed + 255) / 256, 256>>>(caps, emb);
    k_convert_wfc<<<4096, 256>>>(W_fc);

    gemm_nt64<<<dim3(Ad / 64, (Bsz * Pd) / 64), 256>>>(
        enc, p_WencT, b_enc, p_encproj, Bsz * Pd, Ad, Ed);

    for (int t = 0; t < NSTEPS; t++) {
        k_dec<<<Bsz / 4, 256>>>(W_dec, b_dec);
        k_att_e<<<dim3(7, Bsz), 256>>>(w_full, b_full);
        k_ctx<<<dim3(4, Bsz), 128>>>(enc, t);
        gemm_gates_sk<<<dim3(G4 / 64, Bsz / 64, KSPLIT), 256>>>(
            p_xall + (size_t)t * Bsz * KCAT);
        k_lstm<<<(Bsz * Hd) / 256, 256>>>(t);
    }

    k_fc<<<dim3(MROWS / 128, NPAD / 128), 256, 65536>>>(b_fc, out);
}

// round 6
// speedup vs baseline: 3.1051x; 1.6249x over previous
#include <cuda_runtime.h>
#include <cuda_fp16.h>
#include <math.h>
#include <stdint.h>

#define Bsz 128
#define Pd  196
#define Ed  512
#define Hd  512
#define Ad  256
#define Vd  30000
#define Td  21
#define NSTEPS 20
#define G4   2048

// 3-term split-precision ext-K for all recurrence/enc GEMMs
#define KX3  1536
// FC (2-term)
#define MROWS  (Bsz * NSTEPS)   // 2560
#define KE2    1024
#define NPAD   30208            // 236 * 128
#define NSLAB  16

#define NH    2304              // 2048 gates + 256 dec
#define PSH   (Bsz * NH)
#define PSC   (Bsz * G4)

// ---------------- device scratch ------------------------------------------
__device__ float g_enc_proj[Bsz * Pd * Ad];                 // 25.7 MB
__device__ float g_bcat[G4];
__device__ float g_c[Bsz * Hd];
__device__ float g_e[Bsz * Pd];
__device__ float g_embgates[(size_t)MROWS * G4];            // 21 MB
__device__ float g_hgp[4 * PSH];                            // 4.7 MB
__device__ float g_cgp[4 * PSC];                            // 4.2 MB
__device__ __align__(256) __half g_encext[(size_t)Bsz * Pd * KX3];  // 77 MB
__device__ __align__(256) __half g_Wencext[Ad * KX3];
__device__ __align__(256) __half g_Whext[NH * KX3];         // 7.1 MB
__device__ __align__(256) __half g_Wcext[G4 * KX3];         // 6.3 MB
__device__ __align__(256) __half g_Wembext[G4 * KX3];       // 6.3 MB
__device__ __align__(256) __half g_xembext[(size_t)MROWS * KX3];  // 7.9 MB
__device__ __align__(256) __half g_hext[Bsz * KX3];
__device__ __align__(256) __half g_cext[Bsz * KX3];
__device__ __align__(256) __half g_A2[(size_t)MROWS * KE2]; // 5.2 MB
__device__ __align__(256) __half g_B2[(size_t)NPAD * KE2];  // 62 MB

// ---------------- asm helpers ----------------------------------------------
__device__ __forceinline__ uint32_t smem_u32(const void* p) {
    uint32_t a;
    asm("{ .reg .u64 t; cvta.to.shared.u64 t, %1; cvt.u32.u64 %0, t; }" : "=r"(a) : "l"(p));
    return a;
}
#define LDSM_X4(r0, r1, r2, r3, addr) \
    asm volatile("ldmatrix.sync.aligned.m8n8.x4.shared.b16 {%0,%1,%2,%3}, [%4];" \
                 : "=r"(r0), "=r"(r1), "=r"(r2), "=r"(r3) : "r"(addr))
#define MMA16816(d, a, b0v, b1v) \
    asm volatile("mma.sync.aligned.m16n8k16.row.col.f32.f16.f16.f32 " \
                 "{%0,%1,%2,%3}, {%4,%5,%6,%7}, {%8,%9}, {%0,%1,%2,%3};" \
                 : "+f"((d)[0]), "+f"((d)[1]), "+f"((d)[2]), "+f"((d)[3]) \
                 : "r"((a)[0]), "r"((a)[1]), "r"((a)[2]), "r"((a)[3]), \
                   "r"(b0v), "r"(b1v))

__device__ __forceinline__ void split3A(float v, __half* p, int j) {
    __half hi = __float2half(v);
    __half lo = __float2half(v - __half2float(hi));
    p[j] = hi; p[512 + j] = lo; p[1024 + j] = hi;   // [Ahi|Alo|Ahi]
}
__device__ __forceinline__ void split3B(float v, __half* p, int j) {
    __half hi = __float2half(v);
    __half lo = __float2half(v - __half2float(hi));
    p[j] = hi; p[512 + j] = hi; p[1024 + j] = lo;   // [Bhi|Bhi|Blo]
}

// ---------------- prep: weight ext-matrices, bias, state -------------------
__global__ void k_prep(const float* __restrict__ W_enc, const float* __restrict__ W_dec,
                       const float* __restrict__ W_ih, const float* __restrict__ W_hh,
                       const float* __restrict__ b_ih, const float* __restrict__ b_hh) {
    int idx = blockIdx.x * blockDim.x + threadIdx.x;
    int nthr = gridDim.x * blockDim.x;
    // W_enc^T ext: rows a<256, k<512 : w = W_enc[k*Ad + a]
    for (int i = idx; i < Ad * Ed; i += nthr) {
        int a = i >> 9, k = i & 511;
        split3B(W_enc[k * Ad + a], g_Wencext + (size_t)a * KX3, k);
    }
    // Whext: rows n<2048 from W_hh, rows 2048..2303 = W_dec^T
    for (int i = idx; i < NH * Ed; i += nthr) {
        int n = i >> 9, k = i & 511;
        float w = (n < G4) ? W_hh[(size_t)n * Hd + k] : W_dec[k * Ad + (n - G4)];
        split3B(w, g_Whext + (size_t)n * KX3, k);
    }
    // Wcext: ctx section of W_ih (cols 512..1023)
    for (int i = idx; i < G4 * Ed; i += nthr) {
        int n = i >> 9, k = i & 511;
        split3B(W_ih[(size_t)n * (2 * Ed) + Ed + k], g_Wcext + (size_t)n * KX3, k);
    }
    // Wembext: emb section of W_ih (cols 0..511)
    for (int i = idx; i < G4 * Ed; i += nthr) {
        int n = i >> 9, k = i & 511;
        split3B(W_ih[(size_t)n * (2 * Ed) + k], g_Wembext + (size_t)n * KX3, k);
    }
    if (idx < G4) g_bcat[idx] = b_ih[idx] + b_hh[idx];
    if (idx < Bsz * Hd) g_c[idx] = 0.f;
    for (int i = idx; i < Bsz * KX3; i += nthr) g_hext[i] = __float2half(0.f);
}

// ---------------- encoder_out -> 3-term ext fp16 ---------------------------
__global__ __launch_bounds__(256)
void k_convert_enc(const float* __restrict__ enc) {
    int idx = blockIdx.x * blockDim.x + threadIdx.x;
    int nthr = gridDim.x * blockDim.x;
    for (size_t i = idx; i < (size_t)Bsz * Pd * Ed; i += nthr) {
        size_t r = i >> 9; int k = (int)(i & 511);
        split3A(enc[i], g_encext + r * KX3, k);
    }
}

// ---------------- emb gather -> 3-term ext fp16 ----------------------------
__global__ __launch_bounds__(256)
void k_prefill(const int* __restrict__ captions, const float* __restrict__ emb) {
    int idx = blockIdx.x * blockDim.x + threadIdx.x;
    if (idx >= MROWS * Ed) return;
    int r = idx >> 9, j = idx & 511;
    int t = r >> 7, b = r & 127;
    int tok = captions[b * Td + t];
    split3A(emb[(size_t)tok * Ed + j], g_xembext + (size_t)r * KX3, j);
}

// ---------------- W_fc -> B2 = [Bhi | Bhi] fp16 (FC, 2-term) ---------------
__global__ __launch_bounds__(256)
void k_convert_wfc(const float* __restrict__ W_fc) {
    int idx = blockIdx.x * blockDim.x + threadIdx.x;
    int nthr = gridDim.x * blockDim.x;
    for (size_t i = idx; i < (size_t)NPAD * Ed; i += nthr) {
        int n = (int)(i >> 9), k = (int)(i & 511);
        float v = (n < Vd) ? W_fc[(size_t)n * Ed + k] : 0.f;
        __half hi = __float2half(v);
        size_t base = (size_t)n * KE2;
        g_B2[base + k] = hi;
        g_B2[base + 512 + k] = hi;
    }
}

// ---------------- generic HMMA GEMM: C = A(fp16ext) x B^T + bias -----------
// CTA tile 128x128, 8 warps (4M x 2N). grid = (M/128, N/128, splits).
// ksize per split, multiple of 64. Partials at C + z*partStride.
__global__ __launch_bounds__(256, 2)
void hgemm128(const __half* __restrict__ A, const __half* __restrict__ Bm,
              float* __restrict__ C, int N, int Kext, int ksize,
              const float* __restrict__ bias, size_t partStride) {
    extern __shared__ char smem[];
    const int tid = threadIdx.x, lane = tid & 31, wid = tid >> 5;
    const int m0 = blockIdx.x * 128;
    const int n0 = blockIdx.y * 128;
    const int nslab = ksize >> 6;
    const int wm = wid >> 1, wn = wid & 1;
    const uint32_t sb = smem_u32(smem);

    const __half* Ab = A + (size_t)m0 * Kext + (size_t)blockIdx.z * ksize;
    const __half* Bb = Bm + (size_t)n0 * Kext + (size_t)blockIdx.z * ksize;
    float* Cp = C + blockIdx.z * partStride;

    const int a_r  = lane & 15;
    const int a_cb = (lane >> 4) * 16;
    const uint32_t a_row = (uint32_t)(wm * 32 + a_r) * 128;
    const uint32_t a_msk = (uint32_t)(a_r & 7) << 4;
    const int b_r  = (lane & 7) + ((lane >> 4) << 3);
    const int b_cb = ((lane >> 3) & 1) * 16;
    const uint32_t b_row = (uint32_t)(wn * 64 + b_r) * 128;
    const uint32_t b_msk = (uint32_t)(b_r & 7) << 4;

    int c_row[4], c_off[4];
    #pragma unroll
    for (int u = 0; u < 4; u++) {
        int e = tid + 256 * u;
        c_row[u] = e >> 3;
        int ch   = e & 7;
        c_off[u] = c_row[u] * 128 + ((ch * 16) ^ ((c_row[u] & 7) << 4));
    }

    float d[2][8][4] = {};
    uint4 ra[4], rb[4];
    #pragma unroll
    for (int u = 0; u < 4; u++) {
        int e = tid + 256 * u;
        int row = e >> 3, ch = e & 7;
        ra[u] = *(const uint4*)(Ab + (size_t)row * Kext + ch * 8);
        rb[u] = *(const uint4*)(Bb + (size_t)row * Kext + ch * 8);
    }

    for (int s = 0; s < nslab; s++) {
        const int p = s & 1;
        #pragma unroll
        for (int u = 0; u < 4; u++) {
            *(uint4*)(smem + p * 16384 + c_off[u])         = ra[u];
            *(uint4*)(smem + 32768 + p * 16384 + c_off[u]) = rb[u];
        }
        if (s + 1 < nslab) {
            #pragma unroll
            for (int u = 0; u < 4; u++) {
                int e = tid + 256 * u;
                int row = e >> 3, ch = e & 7;
                ra[u] = *(const uint4*)(Ab + (size_t)row * Kext + (s + 1) * 64 + ch * 8);
                rb[u] = *(const uint4*)(Bb + (size_t)row * Kext + (s + 1) * 64 + ch * 8);
            }
        }
        __syncthreads();

        const uint32_t abase = sb + p * 16384;
        const uint32_t bbase = sb + 32768 + p * 16384;
        #pragma unroll
        for (int ks = 0; ks < 4; ks++) {
            uint32_t afr[2][4];
            {
                uint32_t byte = (uint32_t)((ks * 32 + a_cb)) ^ a_msk;
                uint32_t ad0 = abase + a_row + byte;
                LDSM_X4(afr[0][0], afr[0][1], afr[0][2], afr[0][3], ad0);
                LDSM_X4(afr[1][0], afr[1][1], afr[1][2], afr[1][3], ad0 + 2048);
            }
            #pragma unroll
            for (int g = 0; g < 4; g++) {
                uint32_t bfr[4];
                uint32_t byte = (uint32_t)((ks * 32 + b_cb)) ^ b_msk;
                uint32_t bd = bbase + b_row + g * 2048 + byte;
                LDSM_X4(bfr[0], bfr[1], bfr[2], bfr[3], bd);
                MMA16816(d[0][2 * g],     afr[0], bfr[0], bfr[1]);
                MMA16816(d[0][2 * g + 1], afr[0], bfr[2], bfr[3]);
                MMA16816(d[1][2 * g],     afr[1], bfr[0], bfr[1]);
                MMA16816(d[1][2 * g + 1], afr[1], bfr[2], bfr[3]);
            }
        }
        __syncthreads();
    }

    #pragma unroll
    for (int j = 0; j < 8; j++) {
        int col = n0 + wn * 64 + j * 8 + (lane & 3) * 2;
        float bb0 = bias ? bias[col] : 0.f;
        float bb1 = bias ? bias[col + 1] : 0.f;
        #pragma unroll
        for (int i = 0; i < 2; i++) {
            size_t r0 = (size_t)(m0 + wm * 32 + i * 16 + (lane >> 2));
            *(float2*)&Cp[r0 * N + col] =
                make_float2(d[i][j][0] + bb0, d[i][j][1] + bb1);
            *(float2*)&Cp[(r0 + 8) * N + col] =
                make_float2(d[i][j][2] + bb0, d[i][j][3] + bb1);
        }
    }
}

// ---------------- k_att_e: e[b,p] (reduces dec partials inline) ------------
__global__ __launch_bounds__(256)
void k_att_e(const float* __restrict__ b_dec,
             const float* __restrict__ w_full, const float* __restrict__ b_full) {
    const int b = blockIdx.y;
    const int p0 = blockIdx.x * 28;
    const int tid = threadIdx.x, lane = tid & 31, wid = tid >> 5;
    __shared__ float s_dec[Ad];
    __shared__ float s_wf[Ad];
    if (tid < Ad) {
        float dv = b_dec[tid];
        #pragma unroll
        for (int s = 0; s < 4; s++)
            dv += g_hgp[s * PSH + b * NH + G4 + tid];
        s_dec[tid] = dv;
        s_wf[tid]  = w_full[tid];
    }
    __syncthreads();
    const float bf = b_full[0];
    const float* ep_b = g_enc_proj + (size_t)b * Pd * Ad;
    for (int p = p0 + wid; p < p0 + 28; p += 8) {
        const float* ep = ep_b + p * Ad;
        float s = 0.f;
        #pragma unroll
        for (int i = 0; i < 8; i++) {
            int a = lane + 32 * i;
            float v = ep[a] + s_dec[a];
            s = fmaf(fmaxf(v, 0.f), s_wf[a], s);
        }
        #pragma unroll
        for (int o = 16; o > 0; o >>= 1) s += __shfl_xor_sync(0xffffffffu, s, o);
        if (lane == 0) g_e[b * Pd + p] = s + bf;
    }
}

// ---------------- k_ctx: softmax + context -> g_cext (3-term fp16) ---------
__global__ __launch_bounds__(128)
void k_ctx(const float* __restrict__ enc_out) {
    const int b = blockIdx.y;
    const int ec = blockIdx.x;
    const int tid = threadIdx.x, lane = tid & 31, wid = tid >> 5;
    __shared__ float s_a[Pd];
    __shared__ float s_red[8];

    float v0 = (tid < Pd) ? g_e[b * Pd + tid] : -1e30f;
    float v1 = (tid + 128 < Pd) ? g_e[b * Pd + tid + 128] : -1e30f;
    float m = fmaxf(v0, v1);
    #pragma unroll
    for (int o = 16; o > 0; o >>= 1) m = fmaxf(m, __shfl_xor_sync(0xffffffffu, m, o));
    if (lane == 0) s_red[wid] = m;
    __syncthreads();
    float mm = fmaxf(fmaxf(s_red[0], s_red[1]), fmaxf(s_red[2], s_red[3]));

    float e0 = (tid < Pd) ? __expf(v0 - mm) : 0.f;
    float e1 = (tid + 128 < Pd) ? __expf(v1 - mm) : 0.f;
    if (tid < Pd) s_a[tid] = e0;
    if (tid + 128 < Pd) s_a[tid + 128] = e1;
    float ss = e0 + e1;
    #pragma unroll
    for (int o = 16; o > 0; o >>= 1) ss += __shfl_xor_sync(0xffffffffu, ss, o);
    if (lane == 0) s_red[4 + wid] = ss;
    __syncthreads();
    const float inv = 1.f / (s_red[4] + s_red[5] + s_red[6] + s_red[7]);

    const int e = ec * 128 + tid;
    const float* eo = enc_out + (size_t)b * Pd * Ed + e;
    float acc = 0.f;
    #pragma unroll 4
    for (int p = 0; p < Pd; p++)
        acc = fmaf(s_a[p], eo[(size_t)p * Ed], acc);
    split3A(acc * inv, g_cext + (size_t)b * KX3, e);
}

// ---------------- LSTM: reduce partials + pointwise + emit split h ---------
__device__ __forceinline__ float sigf(float x) { return 1.f / (1.f + expf(-x)); }

__global__ __launch_bounds__(256)
void k_lstm(int t) {
    int idx = blockIdx.x * blockDim.x + threadIdx.x;   // 65536
    int b = idx >> 9, j = idx & (Hd - 1);
    const float* eg = g_embgates + ((size_t)t * Bsz + b) * G4;
    float gi = g_bcat[j]          + eg[j];
    float gf = g_bcat[Hd + j]     + eg[Hd + j];
    float gg = g_bcat[2 * Hd + j] + eg[2 * Hd + j];
    float go = g_bcat[3 * Hd + j] + eg[3 * Hd + j];
    #pragma unroll
    for (int s = 0; s < 4; s++) {
        const float* hg = g_hgp + s * PSH + b * NH;
        const float* cg = g_cgp + s * PSC + b * G4;
        gi += hg[j]          + cg[j];
        gf += hg[Hd + j]     + cg[Hd + j];
        gg += hg[2 * Hd + j] + cg[2 * Hd + j];
        go += hg[3 * Hd + j] + cg[3 * Hd + j];
    }
    float i_ = sigf(gi);
    float f_ = sigf(gf);
    float g_ = tanhf(gg);
    float o_ = sigf(go);
    float c  = f_ * g_c[idx] + i_ * g_;
    float h  = o_ * tanhf(c);
    g_c[idx] = c;
    // 3-term split for next-step recurrence GEMM
    split3A(h, g_hext + (size_t)b * KX3, j);
    // 2-term split for FC
    __half hi = __float2half(h);
    float  lo = h - __half2float(hi);
    size_t ab = ((size_t)b * NSTEPS + t) * KE2;
    g_A2[ab + j]       = hi;
    g_A2[ab + 512 + j] = __float2half(lo);
}

// ---------------- FC GEMM (2-term fp16, bounds-checked epilogue) -----------
__global__ __launch_bounds__(256, 2)
void k_fc(const float* __restrict__ b_fc, float* __restrict__ C) {
    extern __shared__ char smem[];
    const int tid = threadIdx.x, lane = tid & 31, wid = tid >> 5;
    const int m0 = blockIdx.x * 128;
    const int n0 = blockIdx.y * 128;
    const int wm = wid >> 1;
    const int wn = wid & 1;
    const uint32_t sb = smem_u32(smem);

    const __half* Ab = g_A2 + (size_t)m0 * KE2;
    const __half* Bb = g_B2 + (size_t)n0 * KE2;

    const int a_r  = lane & 15;
    const int a_cb = (lane >> 4) * 16;
    const uint32_t a_row = (uint32_t)(wm * 32 + a_r) * 128;
    const uint32_t a_msk = (uint32_t)(a_r & 7) << 4;
    const int b_r  = (lane & 7) + ((lane >> 4) << 3);
    const int b_cb = ((lane >> 3) & 1) * 16;
    const uint32_t b_row = (uint32_t)(wn * 64 + b_r) * 128;
    const uint32_t b_msk = (uint32_t)(b_r & 7) << 4;

    int c_row[4], c_off[4];
    #pragma unroll
    for (int u = 0; u < 4; u++) {
        int e = tid + 256 * u;
        c_row[u] = e >> 3;
        int ch   = e & 7;
        c_off[u] = c_row[u] * 128 + ((ch * 16) ^ ((c_row[u] & 7) << 4));
    }

    float d[2][8][4] = {};
    uint4 ra[4], rb[4];
    #pragma unroll
    for (int u = 0; u < 4; u++) {
        int e = tid + 256 * u;
        int row = e >> 3, ch = e & 7;
        ra[u] = *(const uint4*)(Ab + (size_t)row * KE2 + ch * 8);
        rb[u] = *(const uint4*)(Bb + (size_t)row * KE2 + ch * 8);
    }

    for (int s = 0; s < NSLAB; s++) {
        const int p = s & 1;
        #pragma unroll
        for (int u = 0; u < 4; u++) {
            *(uint4*)(smem + p * 16384 + c_off[u])         = ra[u];
            *(uint4*)(smem + 32768 + p * 16384 + c_off[u]) = rb[u];
        }
        if (s + 1 < NSLAB) {
            #pragma unroll
            for (int u = 0; u < 4; u++) {
                int e = tid + 256 * u;
                int row = e >> 3, ch = e & 7;
                ra[u] = *(const uint4*)(Ab + (size_t)row * KE2 + (s + 1) * 64 + ch * 8);
                rb[u] = *(const uint4*)(Bb + (size_t)row * KE2 + (s + 1) * 64 + ch * 8);
            }
        }
        __syncthreads();

        const uint32_t abase = sb + p * 16384;
        const uint32_t bbase = sb + 32768 + p * 16384;
        #pragma unroll
        for (int ks = 0; ks < 4; ks++) {
            uint32_t afr[2][4];
            {
                uint32_t byte = (uint32_t)((ks * 32 + a_cb)) ^ a_msk;
                uint32_t ad0 = abase + a_row + byte;
                LDSM_X4(afr[0][0], afr[0][1], afr[0][2], afr[0][3], ad0);
                LDSM_X4(afr[1][0], afr[1][1], afr[1][2], afr[1][3], ad0 + 2048);
            }
            #pragma unroll
            for (int g = 0; g < 4; g++) {
                uint32_t bfr[4];
                uint32_t byte = (uint32_t)((ks * 32 + b_cb)) ^ b_msk;
                uint32_t bd = bbase + b_row + g * 2048 + byte;
                LDSM_X4(bfr[0], bfr[1], bfr[2], bfr[3], bd);
                MMA16816(d[0][2 * g],     afr[0], bfr[0], bfr[1]);
                MMA16816(d[0][2 * g + 1], afr[0], bfr[2], bfr[3]);
                MMA16816(d[1][2 * g],     afr[1], bfr[0], bfr[1]);
                MMA16816(d[1][2 * g + 1], afr[1], bfr[2], bfr[3]);
            }
        }
        __syncthreads();
    }

    #pragma unroll
    for (int j = 0; j < 8; j++) {
        int col = n0 + wn * 64 + j * 8 + (lane & 3) * 2;
        if (col < Vd) {
            float bb0 = b_fc[col], bb1 = b_fc[col + 1];
            #pragma unroll
            for (int i = 0; i < 2; i++) {
                size_t r0 = (size_t)(m0 + wm * 32 + i * 16 + (lane >> 2));
                *(float2*)&C[r0 * Vd + col] =
                    make_float2(d[i][j][0] + bb0, d[i][j][1] + bb1);
                *(float2*)&C[(r0 + 8) * Vd + col] =
                    make_float2(d[i][j][2] + bb0, d[i][j][3] + bb1);
            }
        }
    }
}

// ---------------- launcher -------------------------------------------------
extern "C" void kernel_launch(void* const* d_in, const int* in_sizes, int n_in,
                              void* d_out, int out_size) {
    const float* enc     = (const float*)d_in[0];
    const int*   caps    = (const int*)  d_in[1];
    const float* emb     = (const float*)d_in[2];
    const float* W_enc   = (const float*)d_in[3];
    const float* b_enc   = (const float*)d_in[4];
    const float* W_dec   = (const float*)d_in[5];
    const float* b_dec   = (const float*)d_in[6];
    const float* w_full  = (const float*)d_in[7];
    const float* b_full  = (const float*)d_in[8];
    const float* W_ih    = (const float*)d_in[9];
    const float* b_ih    = (const float*)d_in[10];
    const float* W_hh    = (const float*)d_in[11];
    const float* b_hh    = (const float*)d_in[12];
    const float* W_fc    = (const float*)d_in[13];
    const float* b_fc    = (const float*)d_in[14];
    float* out = (float*)d_out;

    cudaFuncSetAttribute(k_fc, cudaFuncAttributeMaxDynamicSharedMemorySize, 65536);
    cudaFuncSetAttribute(hgemm128, cudaFuncAttributeMaxDynamicSharedMemorySize, 65536);

    __half *p_encext, *p_Wencext, *p_Whext, *p_Wcext, *p_Wembext, *p_xembext,
           *p_hext, *p_cext;
    float *p_encproj, *p_embgates, *p_hgp, *p_cgp;
    cudaGetSymbolAddress((void**)&p_encext,   g_encext);
    cudaGetSymbolAddress((void**)&p_Wencext,  g_Wencext);
    cudaGetSymbolAddress((void**)&p_Whext,    g_Whext);
    cudaGetSymbolAddress((void**)&p_Wcext,    g_Wcext);
    cudaGetSymbolAddress((void**)&p_Wembext,  g_Wembext);
    cudaGetSymbolAddress((void**)&p_xembext,  g_xembext);
    cudaGetSymbolAddress((void**)&p_hext,     g_hext);
    cudaGetSymbolAddress((void**)&p_cext,     g_cext);
    cudaGetSymbolAddress((void**)&p_encproj,  g_enc_proj);
    cudaGetSymbolAddress((void**)&p_embgates, g_embgates);
    cudaGetSymbolAddress((void**)&p_hgp,      g_hgp);
    cudaGetSymbolAddress((void**)&p_cgp,      g_cgp);

    k_prep<<<4096, 256>>>(W_enc, W_dec, W_ih, W_hh, b_ih, b_hh);
    k_convert_enc<<<4096, 256>>>(enc);
    k_convert_wfc<<<4096, 256>>>(W_fc);
    k_prefill<<<(MROWS * Ed + 255) / 256, 256>>>(caps, emb);

    // enc_proj = enc @ W_enc + b_enc  (25088 x 256, Kext 1536)
    hgemm128<<<dim3(196, 2, 1), 256, 65536>>>(
        p_encext, p_Wencext, p_encproj, Ad, KX3, KX3, b_enc, 0);

    // emb-part of gates for all steps (2560 x 2048, Kext 1536)
    hgemm128<<<dim3(MROWS / 128, G4 / 128, 1), 256, 65536>>>(
        p_xembext, p_Wembext, p_embgates, G4, KX3, KX3, nullptr, 0);

    for (int t = 0; t < NSTEPS; t++) {
        // h @ [W_hh | W_dec]: (128 x 2304), split-K 4
        hgemm128<<<dim3(1, NH / 128, 4), 256, 65536>>>(
            p_hext, p_Whext, p_hgp, NH, KX3, KX3 / 4, nullptr, PSH);
        k_att_e<<<dim3(7, Bsz), 256>>>(b_dec, w_full, b_full);
        k_ctx<<<dim3(4, Bsz), 128>>>(enc);
        // ctx @ W_ih_ctx: (128 x 2048), split-K 4
        hgemm128<<<dim3(1, G4 / 128, 4), 256, 65536>>>(
            p_cext, p_Wcext, p_cgp, G4, KX3, KX3 / 4, nullptr, PSC);
        k_lstm<<<(Bsz * Hd) / 256, 256>>>(t);
    }

    k_fc<<<dim3(MROWS / 128, NPAD / 128), 256, 65536>>>(b_fc, out);
}

// round 8
// speedup vs baseline: 3.1439x; 1.0125x over previous
#include <cuda_runtime.h>
#include <cuda_fp16.h>
#include <math.h>
#include <stdint.h>

#define Bsz 128
#define Pd  196
#define Ed  512
#define Hd  512
#define Ad  256
#define Vd  30000
#define Td  21
#define NSTEPS 20
#define G4   2048

#define KX3  1536               // 3-term ext K (recurrence / enc)
#define MROWS  (Bsz * NSTEPS)   // 2560
#define KE2    512              // FC: plain fp16, K = 512
#define NPAD   30208            // 236 * 128
#define NSLAB  (KE2 / 64)       // 8

#define NH    2304              // 2048 gates + 256 dec
#define PSH   (Bsz * NH)
#define PSC   (Bsz * G4)

// ---------------- device scratch ------------------------------------------
__device__ float g_enc_proj[Bsz * Pd * Ad];                 // 25.7 MB
__device__ float g_bcat[G4];
__device__ float g_c[Bsz * Hd];
__device__ float g_embgates[(size_t)MROWS * G4];            // 21 MB
__device__ float g_hgp[4 * PSH];                            // 4.7 MB
__device__ float g_cgp[4 * PSC];                            // 4.2 MB
__device__ __align__(256) __half g_encext[(size_t)Bsz * Pd * KX3];  // 77 MB
__device__ __align__(256) __half g_Wencext[Ad * KX3];
__device__ __align__(256) __half g_Whext[NH * KX3];         // 7.1 MB
__device__ __align__(256) __half g_Wcext[G4 * KX3];         // 6.3 MB
__device__ __align__(256) __half g_Wembext[G4 * KX3];       // 6.3 MB
__device__ __align__(256) __half g_xembext[(size_t)MROWS * KX3];  // 7.9 MB
__device__ __align__(256) __half g_hext[Bsz * KX3];
__device__ __align__(256) __half g_cext[Bsz * KX3];
__device__ __align__(256) __half g_A2[(size_t)MROWS * KE2]; // 2.6 MB
__device__ __align__(256) __half g_B2[(size_t)NPAD * KE2];  // 31 MB

// ---------------- asm helpers ----------------------------------------------
__device__ __forceinline__ uint32_t smem_u32(const void* p) {
    uint32_t a;
    asm("{ .reg .u64 t; cvta.to.shared.u64 t, %1; cvt.u32.u64 %0, t; }" : "=r"(a) : "l"(p));
    return a;
}
#define LDSM_X4(r0, r1, r2, r3, addr) \
    asm volatile("ldmatrix.sync.aligned.m8n8.x4.shared.b16 {%0,%1,%2,%3}, [%4];" \
                 : "=r"(r0), "=r"(r1), "=r"(r2), "=r"(r3) : "r"(addr))
#define MMA16816(d, a, b0v, b1v) \
    asm volatile("mma.sync.aligned.m16n8k16.row.col.f32.f16.f16.f32 " \
                 "{%0,%1,%2,%3}, {%4,%5,%6,%7}, {%8,%9}, {%0,%1,%2,%3};" \
                 : "+f"((d)[0]), "+f"((d)[1]), "+f"((d)[2]), "+f"((d)[3]) \
                 : "r"((a)[0]), "r"((a)[1]), "r"((a)[2]), "r"((a)[3]), \
                   "r"(b0v), "r"(b1v))

__device__ __forceinline__ void split3A(float v, __half* p, int j) {
    __half hi = __float2half(v);
    __half lo = __float2half(v - __half2float(hi));
    p[j] = hi; p[512 + j] = lo; p[1024 + j] = hi;   // [Ahi|Alo|Ahi]
}
__device__ __forceinline__ void split3B(float v, __half* p, int j) {
    __half hi = __float2half(v);
    __half lo = __float2half(v - __half2float(hi));
    p[j] = hi; p[512 + j] = hi; p[1024 + j] = lo;   // [Bhi|Bhi|Blo]
}

// ---------------- prep: weight ext-matrices, bias, state -------------------
__global__ void k_prep(const float* __restrict__ W_enc, const float* __restrict__ W_dec,
                       const float* __restrict__ W_ih, const float* __restrict__ W_hh,
                       const float* __restrict__ b_ih, const float* __restrict__ b_hh) {
    int idx = blockIdx.x * blockDim.x + threadIdx.x;
    int nthr = gridDim.x * blockDim.x;
    for (int i = idx; i < Ad * Ed; i += nthr) {
        int a = i >> 9, k = i & 511;
        split3B(W_enc[k * Ad + a], g_Wencext + (size_t)a * KX3, k);
    }
    for (int i = idx; i < NH * Ed; i += nthr) {
        int n = i >> 9, k = i & 511;
        float w = (n < G4) ? W_hh[(size_t)n * Hd + k] : W_dec[k * Ad + (n - G4)];
        split3B(w, g_Whext + (size_t)n * KX3, k);
    }
    for (int i = idx; i < G4 * Ed; i += nthr) {
        int n = i >> 9, k = i & 511;
        split3B(W_ih[(size_t)n * (2 * Ed) + Ed + k], g_Wcext + (size_t)n * KX3, k);
    }
    for (int i = idx; i < G4 * Ed; i += nthr) {
        int n = i >> 9, k = i & 511;
        split3B(W_ih[(size_t)n * (2 * Ed) + k], g_Wembext + (size_t)n * KX3, k);
    }
    if (idx < G4) g_bcat[idx] = b_ih[idx] + b_hh[idx];
    if (idx < Bsz * Hd) g_c[idx] = 0.f;
    for (int i = idx; i < Bsz * KX3; i += nthr) g_hext[i] = __float2half(0.f);
}

// ---------------- encoder_out -> 3-term ext fp16 ---------------------------
__global__ __launch_bounds__(256)
void k_convert_enc(const float* __restrict__ enc) {
    int idx = blockIdx.x * blockDim.x + threadIdx.x;
    int nthr = gridDim.x * blockDim.x;
    for (size_t i = idx; i < (size_t)Bsz * Pd * Ed; i += nthr) {
        size_t r = i >> 9; int k = (int)(i & 511);
        split3A(enc[i], g_encext + r * KX3, k);
    }
}

// ---------------- emb gather -> 3-term ext fp16 ----------------------------
__global__ __launch_bounds__(256)
void k_prefill(const int* __restrict__ captions, const float* __restrict__ emb) {
    int idx = blockIdx.x * blockDim.x + threadIdx.x;
    if (idx >= MROWS * Ed) return;
    int r = idx >> 9, j = idx & 511;
    int t = r >> 7, b = r & 127;
    int tok = captions[b * Td + t];
    split3A(emb[(size_t)tok * Ed + j], g_xembext + (size_t)r * KX3, j);
}

// ---------------- W_fc -> B2 plain fp16 ------------------------------------
__global__ __launch_bounds__(256)
void k_convert_wfc(const float* __restrict__ W_fc) {
    int idx = blockIdx.x * blockDim.x + threadIdx.x;
    int nthr = gridDim.x * blockDim.x;
    for (size_t i = idx; i < (size_t)NPAD * Ed; i += nthr) {
        int n = (int)(i >> 9), k = (int)(i & 511);
        float v = (n < Vd) ? W_fc[(size_t)n * Ed + k] : 0.f;
        g_B2[(size_t)n * KE2 + k] = __float2half(v);
    }
}

// ---------------- generic HMMA GEMM: C = A(fp16ext) x B^T + bias -----------
__global__ __launch_bounds__(256, 2)
void hgemm128(const __half* __restrict__ A, const __half* __restrict__ Bm,
              float* __restrict__ C, int N, int Kext, int ksize,
              const float* __restrict__ bias, size_t partStride) {
    extern __shared__ char smem[];
    const int tid = threadIdx.x, lane = tid & 31, wid = tid >> 5;
    const int m0 = blockIdx.x * 128;
    const int n0 = blockIdx.y * 128;
    const int nslab = ksize >> 6;
    const int wm = wid >> 1, wn = wid & 1;
    const uint32_t sb = smem_u32(smem);

    const __half* Ab = A + (size_t)m0 * Kext + (size_t)blockIdx.z * ksize;
    const __half* Bb = Bm + (size_t)n0 * Kext + (size_t)blockIdx.z * ksize;
    float* Cp = C + blockIdx.z * partStride;

    const int a_r  = lane & 15;
    const int a_cb = (lane >> 4) * 16;
    const uint32_t a_row = (uint32_t)(wm * 32 + a_r) * 128;
    const uint32_t a_msk = (uint32_t)(a_r & 7) << 4;
    const int b_r  = (lane & 7) + ((lane >> 4) << 3);
    const int b_cb = ((lane >> 3) & 1) * 16;
    const uint32_t b_row = (uint32_t)(wn * 64 + b_r) * 128;
    const uint32_t b_msk = (uint32_t)(b_r & 7) << 4;

    int c_row[4], c_off[4];
    #pragma unroll
    for (int u = 0; u < 4; u++) {
        int e = tid + 256 * u;
        c_row[u] = e >> 3;
        int ch   = e & 7;
        c_off[u] = c_row[u] * 128 + ((ch * 16) ^ ((c_row[u] & 7) << 4));
    }

    float d[2][8][4] = {};
    uint4 ra[4], rb[4];
    #pragma unroll
    for (int u = 0; u < 4; u++) {
        int e = tid + 256 * u;
        int row = e >> 3, ch = e & 7;
        ra[u] = *(const uint4*)(Ab + (size_t)row * Kext + ch * 8);
        rb[u] = *(const uint4*)(Bb + (size_t)row * Kext + ch * 8);
    }

    for (int s = 0; s < nslab; s++) {
        const int p = s & 1;
        #pragma unroll
        for (int u = 0; u < 4; u++) {
            *(uint4*)(smem + p * 16384 + c_off[u])         = ra[u];
            *(uint4*)(smem + 32768 + p * 16384 + c_off[u]) = rb[u];
        }
        if (s + 1 < nslab) {
            #pragma unroll
            for (int u = 0; u < 4; u++) {
                int e = tid + 256 * u;
                int row = e >> 3, ch = e & 7;
                ra[u] = *(const uint4*)(Ab + (size_t)row * Kext + (s + 1) * 64 + ch * 8);
                rb[u] = *(const uint4*)(Bb + (size_t)row * Kext + (s + 1) * 64 + ch * 8);
            }
        }
        __syncthreads();

        const uint32_t abase = sb + p * 16384;
        const uint32_t bbase = sb + 32768 + p * 16384;
        #pragma unroll
        for (int ks = 0; ks < 4; ks++) {
            uint32_t afr[2][4];
            {
                uint32_t byte = (uint32_t)((ks * 32 + a_cb)) ^ a_msk;
                uint32_t ad0 = abase + a_row + byte;
                LDSM_X4(afr[0][0], afr[0][1], afr[0][2], afr[0][3], ad0);
                LDSM_X4(afr[1][0], afr[1][1], afr[1][2], afr[1][3], ad0 + 2048);
            }
            #pragma unroll
            for (int g = 0; g < 4; g++) {
                uint32_t bfr[4];
                uint32_t byte = (uint32_t)((ks * 32 + b_cb)) ^ b_msk;
                uint32_t bd = bbase + b_row + g * 2048 + byte;
                LDSM_X4(bfr[0], bfr[1], bfr[2], bfr[3], bd);
                MMA16816(d[0][2 * g],     afr[0], bfr[0], bfr[1]);
                MMA16816(d[0][2 * g + 1], afr[0], bfr[2], bfr[3]);
                MMA16816(d[1][2 * g],     afr[1], bfr[0], bfr[1]);
                MMA16816(d[1][2 * g + 1], afr[1], bfr[2], bfr[3]);
            }
        }
        __syncthreads();
    }

    #pragma unroll
    for (int j = 0; j < 8; j++) {
        int col = n0 + wn * 64 + j * 8 + (lane & 3) * 2;
        float bb0 = bias ? bias[col] : 0.f;
        float bb1 = bias ? bias[col + 1] : 0.f;
        #pragma unroll
        for (int i = 0; i < 2; i++) {
            size_t r0 = (size_t)(m0 + wm * 32 + i * 16 + (lane >> 2));
            *(float2*)&Cp[r0 * N + col] =
                make_float2(d[i][j][0] + bb0, d[i][j][1] + bb1);
            *(float2*)&Cp[(r0 + 8) * N + col] =
                make_float2(d[i][j][2] + bb0, d[i][j][3] + bb1);
        }
    }
}

// ---------------- k_att: dec-reduce + e + softmax + context (fused) --------
__global__ __launch_bounds__(256)
void k_att(const float* __restrict__ enc_out, const float* __restrict__ b_dec,
           const float* __restrict__ w_full, const float* __restrict__ b_full) {
    const int b = blockIdx.x;
    const int tid = threadIdx.x, lane = tid & 31, wid = tid >> 5;
    __shared__ float s_dec[Ad];
    __shared__ float s_wf[Ad];
    __shared__ float s_e[Pd];
    __shared__ float s_red[16];

    if (tid < Ad) {
        float dv = b_dec[tid];
        #pragma unroll
        for (int s = 0; s < 4; s++)
            dv += g_hgp[s * PSH + b * NH + G4 + tid];
        s_dec[tid] = dv;
        s_wf[tid]  = w_full[tid];
    }
    __syncthreads();

    // e-phase: warp per p
    const float bf = b_full[0];
    const float* ep_b = g_enc_proj + (size_t)b * Pd * Ad;
    for (int p = wid; p < Pd; p += 8) {
        const float* ep = ep_b + p * Ad;
        float s = 0.f;
        #pragma unroll
        for (int i = 0; i < 8; i++) {
            int a = lane + 32 * i;
            float v = ep[a] + s_dec[a];
            s = fmaf(fmaxf(v, 0.f), s_wf[a], s);
        }
        #pragma unroll
        for (int o = 16; o > 0; o >>= 1) s += __shfl_xor_sync(0xffffffffu, s, o);
        if (lane == 0) s_e[p] = s + bf;
    }
    __syncthreads();

    // softmax: thread tid handles p = tid (Pd = 196 < 256)
    float v = (tid < Pd) ? s_e[tid] : -1e30f;
    float m = v;
    #pragma unroll
    for (int o = 16; o > 0; o >>= 1) m = fmaxf(m, __shfl_xor_sync(0xffffffffu, m, o));
    if (lane == 0) s_red[wid] = m;
    __syncthreads();
    float mm = s_red[0];
    #pragma unroll
    for (int i = 1; i < 8; i++) mm = fmaxf(mm, s_red[i]);

    float ev = (tid < Pd) ? __expf(v - mm) : 0.f;
    float ss = ev;
    #pragma unroll
    for (int o = 16; o > 0; o >>= 1) ss += __shfl_xor_sync(0xffffffffu, ss, o);
    if (lane == 0) s_red[8 + wid] = ss;
    if (tid < Pd) s_e[tid] = ev;
    __syncthreads();
    float tot = 0.f;
    #pragma unroll
    for (int i = 0; i < 8; i++) tot += s_red[8 + i];
    const float inv = 1.f / tot;

    // ctx-phase: thread handles dims tid and tid+256 (Pd = 196 even)
    const float* eo = enc_out + (size_t)b * Pd * Ed;
    float c0a = 0.f, c0b = 0.f, c1a = 0.f, c1b = 0.f;
    #pragma unroll 2
    for (int p = 0; p < Pd - 1; p += 2) {
        float a0 = s_e[p], a1 = s_e[p + 1];
        const float* r0 = eo + (size_t)p * Ed;
        c0a = fmaf(a0, r0[tid], c0a);
        c1a = fmaf(a0, r0[tid + 256], c1a);
        c0b = fmaf(a1, r0[Ed + tid], c0b);
        c1b = fmaf(a1, r0[Ed + tid + 256], c1b);
    }
    __half* cx = g_cext + (size_t)b * KX3;
    split3A((c0a + c0b) * inv, cx, tid);
    split3A((c1a + c1b) * inv, cx, tid + 256);
}

// ---------------- LSTM: reduce partials + pointwise + emit split h ---------
__device__ __forceinline__ float sigf(float x) { return 1.f / (1.f + expf(-x)); }

__global__ __launch_bounds__(256)
void k_lstm(int t) {
    int idx = blockIdx.x * blockDim.x + threadIdx.x;   // 65536
    int b = idx >> 9, j = idx & (Hd - 1);
    const float* eg = g_embgates + ((size_t)t * Bsz + b) * G4;
    float gi = g_bcat[j]          + eg[j];
    float gf = g_bcat[Hd + j]     + eg[Hd + j];
    float gg = g_bcat[2 * Hd + j] + eg[2 * Hd + j];
    float go = g_bcat[3 * Hd + j] + eg[3 * Hd + j];
    #pragma unroll
    for (int s = 0; s < 4; s++) {
        const float* hg = g_hgp + s * PSH + b * NH;
        const float* cg = g_cgp + s * PSC + b * G4;
        gi += hg[j]          + cg[j];
        gf += hg[Hd + j]     + cg[Hd + j];
        gg += hg[2 * Hd + j] + cg[2 * Hd + j];
        go += hg[3 * Hd + j] + cg[3 * Hd + j];
    }
    float i_ = sigf(gi);
    float f_ = sigf(gf);
    float g_ = tanhf(gg);
    float o_ = sigf(go);
    float c  = f_ * g_c[idx] + i_ * g_;
    float h  = o_ * tanhf(c);
    g_c[idx] = c;
    split3A(h, g_hext + (size_t)b * KX3, j);
    g_A2[((size_t)b * NSTEPS + t) * KE2 + j] = __float2half(h);
}

// ---------------- FC GEMM (plain fp16, K=512) ------------------------------
__global__ __launch_bounds__(256, 2)
void k_fc(const float* __restrict__ b_fc, float* __restrict__ C) {
    extern __shared__ char smem[];
    const int tid = threadIdx.x, lane = tid & 31, wid = tid >> 5;
    const int m0 = blockIdx.x * 128;
    const int n0 = blockIdx.y * 128;
    const int wm = wid >> 1;
    const int wn = wid & 1;
    const uint32_t sb = smem_u32(smem);

    const __half* Ab = g_A2 + (size_t)m0 * KE2;
    const __half* Bb = g_B2 + (size_t)n0 * KE2;

    const int a_r  = lane & 15;
    const int a_cb = (lane >> 4) * 16;
    const uint32_t a_row = (uint32_t)(wm * 32 + a_r) * 128;
    const uint32_t a_msk = (uint32_t)(a_r & 7) << 4;
    const int b_r  = (lane & 7) + ((lane >> 4) << 3);
    const int b_cb = ((lane >> 3) & 1) * 16;
    const uint32_t b_row = (uint32_t)(wn * 64 + b_r) * 128;
    const uint32_t b_msk = (uint32_t)(b_r & 7) << 4;

    int c_row[4], c_off[4];
    #pragma unroll
    for (int u = 0; u < 4; u++) {
        int e = tid + 256 * u;
        c_row[u] = e >> 3;
        int ch   = e & 7;
        c_off[u] = c_row[u] * 128 + ((ch * 16) ^ ((c_row[u] & 7) << 4));
    }

    float d[2][8][4] = {};
    uint4 ra[4], rb[4];
    #pragma unroll
    for (int u = 0; u < 4; u++) {
        int e = tid + 256 * u;
        int row = e >> 3, ch = e & 7;
        ra[u] = *(const uint4*)(Ab + (size_t)row * KE2 + ch * 8);
        rb[u] = *(const uint4*)(Bb + (size_t)row * KE2 + ch * 8);
    }

    for (int s = 0; s < NSLAB; s++) {
        const int p = s & 1;
        #pragma unroll
        for (int u = 0; u < 4; u++) {
            *(uint4*)(smem + p * 16384 + c_off[u])         = ra[u];
            *(uint4*)(smem + 32768 + p * 16384 + c_off[u]) = rb[u];
        }
        if (s + 1 < NSLAB) {
            #pragma unroll
            for (int u = 0; u < 4; u++) {
                int e = tid + 256 * u;
                int row = e >> 3, ch = e & 7;
                ra[u] = *(const uint4*)(Ab + (size_t)row * KE2 + (s + 1) * 64 + ch * 8);
                rb[u] = *(const uint4*)(Bb + (size_t)row * KE2 + (s + 1) * 64 + ch * 8);
            }
        }
        __syncthreads();

        const uint32_t abase = sb + p * 16384;
        const uint32_t bbase = sb + 32768 + p * 16384;
        #pragma unroll
        for (int ks = 0; ks < 4; ks++) {
            uint32_t afr[2][4];
            {
                uint32_t byte = (uint32_t)((ks * 32 + a_cb)) ^ a_msk;
                uint32_t ad0 = abase + a_row + byte;
                LDSM_X4(afr[0][0], afr[0][1], afr[0][2], afr[0][3], ad0);
                LDSM_X4(afr[1][0], afr[1][1], afr[1][2], afr[1][3], ad0 + 2048);
            }
            #pragma unroll
            for (int g = 0; g < 4; g++) {
                uint32_t bfr[4];
                uint32_t byte = (uint32_t)((ks * 32 + b_cb)) ^ b_msk;
                uint32_t bd = bbase + b_row + g * 2048 + byte;
                LDSM_X4(bfr[0], bfr[1], bfr[2], bfr[3], bd);
                MMA16816(d[0][2 * g],     afr[0], bfr[0], bfr[1]);
                MMA16816(d[0][2 * g + 1], afr[0], bfr[2], bfr[3]);
                MMA16816(d[1][2 * g],     afr[1], bfr[0], bfr[1]);
                MMA16816(d[1][2 * g + 1], afr[1], bfr[2], bfr[3]);
            }
        }
        __syncthreads();
    }

    #pragma unroll
    for (int j = 0; j < 8; j++) {
        int col = n0 + wn * 64 + j * 8 + (lane & 3) * 2;
        if (col < Vd) {
            float bb0 = b_fc[col], bb1 = b_fc[col + 1];
            #pragma unroll
            for (int i = 0; i < 2; i++) {
                size_t r0 = (size_t)(m0 + wm * 32 + i * 16 + (lane >> 2));
                *(float2*)&C[r0 * Vd + col] =
                    make_float2(d[i][j][0] + bb0, d[i][j][1] + bb1);
                *(float2*)&C[(r0 + 8) * Vd + col] =
                    make_float2(d[i][j][2] + bb0, d[i][j][3] + bb1);
            }
        }
    }
}

// ---------------- launcher -------------------------------------------------
extern "C" void kernel_launch(void* const* d_in, const int* in_sizes, int n_in,
                              void* d_out, int out_size) {
    const float* enc     = (const float*)d_in[0];
    const int*   caps    = (const int*)  d_in[1];
    const float* emb     = (const float*)d_in[2];
    const float* W_enc   = (const float*)d_in[3];
    const float* b_enc   = (const float*)d_in[4];
    const float* W_dec   = (const float*)d_in[5];
    const float* b_dec   = (const float*)d_in[6];
    const float* w_full  = (const float*)d_in[7];
    const float* b_full  = (const float*)d_in[8];
    const float* W_ih    = (const float*)d_in[9];
    const float* b_ih    = (const float*)d_in[10];
    const float* W_hh    = (const float*)d_in[11];
    const float* b_hh    = (const float*)d_in[12];
    const float* W_fc    = (const float*)d_in[13];
    const float* b_fc    = (const float*)d_in[14];
    float* out = (float*)d_out;

    cudaFuncSetAttribute(k_fc, cudaFuncAttributeMaxDynamicSharedMemorySize, 65536);
    cudaFuncSetAttribute(hgemm128, cudaFuncAttributeMaxDynamicSharedMemorySize, 65536);

    __half *p_encext, *p_Wencext, *p_Whext, *p_Wcext, *p_Wembext, *p_xembext,
           *p_hext, *p_cext;
    float *p_encproj, *p_embgates, *p_hgp, *p_cgp;
    cudaGetSymbolAddress((void**)&p_encext,   g_encext);
    cudaGetSymbolAddress((void**)&p_Wencext,  g_Wencext);
    cudaGetSymbolAddress((void**)&p_Whext,    g_Whext);
    cudaGetSymbolAddress((void**)&p_Wcext,    g_Wcext);
    cudaGetSymbolAddress((void**)&p_Wembext,  g_Wembext);
    cudaGetSymbolAddress((void**)&p_xembext,  g_xembext);
    cudaGetSymbolAddress((void**)&p_hext,     g_hext);
    cudaGetSymbolAddress((void**)&p_cext,     g_cext);
    cudaGetSymbolAddress((void**)&p_encproj,  g_enc_proj);
    cudaGetSymbolAddress((void**)&p_embgates, g_embgates);
    cudaGetSymbolAddress((void**)&p_hgp,      g_hgp);
    cudaGetSymbolAddress((void**)&p_cgp,      g_cgp);

    k_prep<<<4096, 256>>>(W_enc, W_dec, W_ih, W_hh, b_ih, b_hh);
    k_convert_enc<<<4096, 256>>>(enc);
    k_convert_wfc<<<4096, 256>>>(W_fc);
    k_prefill<<<(MROWS * Ed + 255) / 256, 256>>>(caps, emb);

    // enc_proj = enc @ W_enc + b_enc  (25088 x 256, Kext 1536)
    hgemm128<<<dim3(196, 2, 1), 256, 65536>>>(
        p_encext, p_Wencext, p_encproj, Ad, KX3, KX3, b_enc, 0);

    // emb-part of gates for all steps (2560 x 2048, Kext 1536)
    hgemm128<<<dim3(MROWS / 128, G4 / 128, 1), 256, 65536>>>(
        p_xembext, p_Wembext, p_embgates, G4, KX3, KX3, nullptr, 0);

    for (int t = 0; t < NSTEPS; t++) {
        // h @ [W_hh | W_dec]: (128 x 2304), split-K 4
        hgemm128<<<dim3(1, NH / 128, 4), 256, 65536>>>(
            p_hext, p_Whext, p_hgp, NH, KX3, KX3 / 4, nullptr, PSH);
        k_att<<<Bsz, 256>>>(enc, b_dec, w_full, b_full);
        // ctx @ W_ih_ctx: (128 x 2048), split-K 4
        hgemm128<<<dim3(1, G4 / 128, 4), 256, 65536>>>(
            p_cext, p_Wcext, p_cgp, G4, KX3, KX3 / 4, nullptr, PSC);
        k_lstm<<<(Bsz * Hd) / 256, 256>>>(t);
    }

    k_fc<<<dim3(MROWS / 128, NPAD / 128), 256, 65536>>>(b_fc, out);
}

// round 10
// speedup vs baseline: 3.2511x; 1.0341x over previous
#include <cuda_runtime.h>
#include <cuda_fp16.h>
#include <math.h>
#include <stdint.h>

#define Bsz 128
#define Pd  196
#define Ed  512
#define Hd  512
#define Ad  256
#define Vd  30000
#define Td  21
#define NSTEPS 20
#define G4   2048

#define KX3  1536               // 3-term ext K (recurrence / enc)
#define MROWS  (Bsz * NSTEPS)   // 2560
#define KE2    512              // FC: plain fp16
#define NPAD   30208            // 236 * 128
#define NSLAB  (KE2 / 64)       // 8

#define NH    2304              // 2048 gates + 256 dec
#define PSH   (Bsz * NH)
#define PSC   (Bsz * G4)
#define KSP   6                 // split-K for loop GEMMs (ksize 256)
#define NB    128               // persistent grid size (<= SM count)

// ---------------- device scratch ------------------------------------------
__device__ float g_enc_proj[Bsz * Pd * Ad];
__device__ float g_bcat[G4];
__device__ float g_c[Bsz * Hd];
__device__ float g_embgates[(size_t)MROWS * G4];
__device__ float g_hgp[KSP * PSH];
__device__ float g_cgp[KSP * PSC];
__device__ __align__(256) __half g_encext[(size_t)Bsz * Pd * KX3];
__device__ __align__(256) __half g_Wencext[Ad * KX3];
__device__ __align__(256) __half g_Whext[NH * KX3];
__device__ __align__(256) __half g_Wcext[G4 * KX3];
__device__ __align__(256) __half g_Wembext[G4 * KX3];
__device__ __align__(256) __half g_xembext[(size_t)MROWS * KX3];
__device__ __align__(256) __half g_hext[Bsz * KX3];
__device__ __align__(256) __half g_cext[Bsz * KX3];
__device__ __align__(256) __half g_A2[(size_t)MROWS * KE2];
__device__ __align__(256) __half g_B2[(size_t)NPAD * KE2];

__device__ int g_barcnt;
__device__ volatile int g_barsense;

// ---------------- asm helpers ----------------------------------------------
__device__ __forceinline__ uint32_t smem_u32(const void* p) {
    uint32_t a;
    asm("{ .reg .u64 t; cvta.to.shared.u64 t, %1; cvt.u32.u64 %0, t; }" : "=r"(a) : "l"(p));
    return a;
}
#define LDSM_X4(r0, r1, r2, r3, addr) \
    asm volatile("ldmatrix.sync.aligned.m8n8.x4.shared.b16 {%0,%1,%2,%3}, [%4];" \
                 : "=r"(r0), "=r"(r1), "=r"(r2), "=r"(r3) : "r"(addr))
#define MMA16816(d, a, b0v, b1v) \
    asm volatile("mma.sync.aligned.m16n8k16.row.col.f32.f16.f16.f32 " \
                 "{%0,%1,%2,%3}, {%4,%5,%6,%7}, {%8,%9}, {%0,%1,%2,%3};" \
                 : "+f"((d)[0]), "+f"((d)[1]), "+f"((d)[2]), "+f"((d)[3]) \
                 : "r"((a)[0]), "r"((a)[1]), "r"((a)[2]), "r"((a)[3]), \
                   "r"(b0v), "r"(b1v))

__device__ __forceinline__ void split3A(float v, __half* p, int j) {
    __half hi = __float2half(v);
    __half lo = __float2half(v - __half2float(hi));
    p[j] = hi; p[512 + j] = lo; p[1024 + j] = hi;
}
__device__ __forceinline__ void split3B(float v, __half* p, int j) {
    __half hi = __float2half(v);
    __half lo = __float2half(v - __half2float(hi));
    p[j] = hi; p[512 + j] = hi; p[1024 + j] = lo;
}

// ---------------- grid barrier (persistent kernel) -------------------------
__device__ __forceinline__ void grid_barrier(int sense) {
    __syncthreads();
    if (threadIdx.x == 0) {
        __threadfence();
        int old = atomicAdd(&g_barcnt, 1);
        if (old == NB - 1) {
            g_barcnt = 0;
            __threadfence();
            g_barsense = sense;
        } else {
            while (g_barsense != sense) { __nanosleep(64); }
            __threadfence();
        }
    }
    __syncthreads();
}

// ---------------- prep ------------------------------------------------------
__global__ void k_prep(const float* __restrict__ W_enc, const float* __restrict__ W_dec,
                       const float* __restrict__ W_ih, const float* __restrict__ W_hh,
                       const float* __restrict__ b_ih, const float* __restrict__ b_hh) {
    int idx = blockIdx.x * blockDim.x + threadIdx.x;
    int nthr = gridDim.x * blockDim.x;
    if (idx == 0) { g_barcnt = 0; g_barsense = 0; }
    for (int i = idx; i < Ad * Ed; i += nthr) {
        int a = i >> 9, k = i & 511;
        split3B(W_enc[k * Ad + a], g_Wencext + (size_t)a * KX3, k);
    }
    for (int i = idx; i < NH * Ed; i += nthr) {
        int n = i >> 9, k = i & 511;
        float w = (n < G4) ? W_hh[(size_t)n * Hd + k] : W_dec[k * Ad + (n - G4)];
        split3B(w, g_Whext + (size_t)n * KX3, k);
    }
    for (int i = idx; i < G4 * Ed; i += nthr) {
        int n = i >> 9, k = i & 511;
        split3B(W_ih[(size_t)n * (2 * Ed) + Ed + k], g_Wcext + (size_t)n * KX3, k);
    }
    for (int i = idx; i < G4 * Ed; i += nthr) {
        int n = i >> 9, k = i & 511;
        split3B(W_ih[(size_t)n * (2 * Ed) + k], g_Wembext + (size_t)n * KX3, k);
    }
    if (idx < G4) g_bcat[idx] = b_ih[idx] + b_hh[idx];
    if (idx < Bsz * Hd) g_c[idx] = 0.f;
    for (int i = idx; i < Bsz * KX3; i += nthr) g_hext[i] = __float2half(0.f);
}

__global__ __launch_bounds__(256)
void k_convert_enc(const float* __restrict__ enc) {
    int idx = blockIdx.x * blockDim.x + threadIdx.x;
    int nthr = gridDim.x * blockDim.x;
    for (size_t i = idx; i < (size_t)Bsz * Pd * Ed; i += nthr) {
        size_t r = i >> 9; int k = (int)(i & 511);
        split3A(enc[i], g_encext + r * KX3, k);
    }
}

__global__ __launch_bounds__(256)
void k_prefill(const int* __restrict__ captions, const float* __restrict__ emb) {
    int idx = blockIdx.x * blockDim.x + threadIdx.x;
    if (idx >= MROWS * Ed) return;
    int r = idx >> 9, j = idx & 511;
    int t = r >> 7, b = r & 127;
    int tok = captions[b * Td + t];
    split3A(emb[(size_t)tok * Ed + j], g_xembext + (size_t)r * KX3, j);
}

__global__ __launch_bounds__(256)
void k_convert_wfc(const float* __restrict__ W_fc) {
    int idx = blockIdx.x * blockDim.x + threadIdx.x;
    int nthr = gridDim.x * blockDim.x;
    for (size_t i = idx; i < (size_t)NPAD * Ed; i += nthr) {
        int n = (int)(i >> 9), k = (int)(i & 511);
        float v = (n < Vd) ? W_fc[(size_t)n * Ed + k] : 0.f;
        g_B2[(size_t)n * KE2 + k] = __float2half(v);
    }
}

// ---------------- generic HMMA GEMM kernel (pre-loop GEMMs) ----------------
__global__ __launch_bounds__(256, 2)
void hgemm128(const __half* __restrict__ A, const __half* __restrict__ Bm,
              float* __restrict__ C, int N, int Kext, int ksize,
              const float* __restrict__ bias, size_t partStride) {
    extern __shared__ char smem[];
    const int tid = threadIdx.x, lane = tid & 31, wid = tid >> 5;
    const int m0 = blockIdx.x * 128;
    const int n0 = blockIdx.y * 128;
    const int nslab = ksize >> 6;
    const int wm = wid >> 1, wn = wid & 1;
    const uint32_t sb = smem_u32(smem);

    const __half* Ab = A + (size_t)m0 * Kext + (size_t)blockIdx.z * ksize;
    const __half* Bb = Bm + (size_t)n0 * Kext + (size_t)blockIdx.z * ksize;
    float* Cp = C + blockIdx.z * partStride;

    const int a_r  = lane & 15;
    const int a_cb = (lane >> 4) * 16;
    const uint32_t a_row = (uint32_t)(wm * 32 + a_r) * 128;
    const uint32_t a_msk = (uint32_t)(a_r & 7) << 4;
    const int b_r  = (lane & 7) + ((lane >> 4) << 3);
    const int b_cb = ((lane >> 3) & 1) * 16;
    const uint32_t b_row = (uint32_t)(wn * 64 + b_r) * 128;
    const uint32_t b_msk = (uint32_t)(b_r & 7) << 4;

    int c_off[4];
    #pragma unroll
    for (int u = 0; u < 4; u++) {
        int e = tid + 256 * u;
        int row = e >> 3, ch = e & 7;
        c_off[u] = row * 128 + ((ch * 16) ^ ((row & 7) << 4));
    }

    float d[2][8][4] = {};
    uint4 ra[4], rb[4];
    #pragma unroll
    for (int u = 0; u < 4; u++) {
        int e = tid + 256 * u;
        int row = e >> 3, ch = e & 7;
        ra[u] = *(const uint4*)(Ab + (size_t)row * Kext + ch * 8);
        rb[u] = *(const uint4*)(Bb + (size_t)row * Kext + ch * 8);
    }

    for (int s = 0; s < nslab; s++) {
        const int p = s & 1;
        #pragma unroll
        for (int u = 0; u < 4; u++) {
            *(uint4*)(smem + p * 16384 + c_off[u])         = ra[u];
            *(uint4*)(smem + 32768 + p * 16384 + c_off[u]) = rb[u];
        }
        if (s + 1 < nslab) {
            #pragma unroll
            for (int u = 0; u < 4; u++) {
                int e = tid + 256 * u;
                int row = e >> 3, ch = e & 7;
                ra[u] = *(const uint4*)(Ab + (size_t)row * Kext + (s + 1) * 64 + ch * 8);
                rb[u] = *(const uint4*)(Bb + (size_t)row * Kext + (s + 1) * 64 + ch * 8);
            }
        }
        __syncthreads();

        const uint32_t abase = sb + p * 16384;
        const uint32_t bbase = sb + 32768 + p * 16384;
        #pragma unroll
        for (int ks = 0; ks < 4; ks++) {
            uint32_t afr[2][4];
            {
                uint32_t byte = (uint32_t)((ks * 32 + a_cb)) ^ a_msk;
                uint32_t ad0 = abase + a_row + byte;
                LDSM_X4(afr[0][0], afr[0][1], afr[0][2], afr[0][3], ad0);
                LDSM_X4(afr[1][0], afr[1][1], afr[1][2], afr[1][3], ad0 + 2048);
            }
            #pragma unroll
            for (int g = 0; g < 4; g++) {
                uint32_t bfr[4];
                uint32_t byte = (uint32_t)((ks * 32 + b_cb)) ^ b_msk;
                uint32_t bd = bbase + b_row + g * 2048 + byte;
                LDSM_X4(bfr[0], bfr[1], bfr[2], bfr[3], bd);
                MMA16816(d[0][2 * g],     afr[0], bfr[0], bfr[1]);
                MMA16816(d[0][2 * g + 1], afr[0], bfr[2], bfr[3]);
                MMA16816(d[1][2 * g],     afr[1], bfr[0], bfr[1]);
                MMA16816(d[1][2 * g + 1], afr[1], bfr[2], bfr[3]);
            }
        }
        __syncthreads();
    }

    #pragma unroll
    for (int j = 0; j < 8; j++) {
        int col = n0 + wn * 64 + j * 8 + (lane & 3) * 2;
        float bb0 = bias ? bias[col] : 0.f;
        float bb1 = bias ? bias[col + 1] : 0.f;
        #pragma unroll
        for (int i = 0; i < 2; i++) {
            size_t r0 = (size_t)(m0 + wm * 32 + i * 16 + (lane >> 2));
            *(float2*)&Cp[r0 * N + col] =
                make_float2(d[i][j][0] + bb0, d[i][j][1] + bb1);
            *(float2*)&Cp[(r0 + 8) * N + col] =
                make_float2(d[i][j][2] + bb0, d[i][j][3] + bb1);
        }
    }
}

// ---------------- device GEMM tile for the persistent loop ------------------
// 128x128 tile, Kext = KX3, ksize = 256 (4 slabs), m0 = 0, no bias.
__device__ void dev_gtile(const __half* __restrict__ Ab, const __half* __restrict__ Bb,
                          float* __restrict__ Cp, int N, int n0,
                          char* smem, uint32_t sb) {
    const int tid = threadIdx.x, lane = tid & 31, wid = tid >> 5;
    const int wm = wid >> 1, wn = wid & 1;

    const int a_r  = lane & 15;
    const int a_cb = (lane >> 4) * 16;
    const uint32_t a_row = (uint32_t)(wm * 32 + a_r) * 128;
    const uint32_t a_msk = (uint32_t)(a_r & 7) << 4;
    const int b_r  = (lane & 7) + ((lane >> 4) << 3);
    const int b_cb = ((lane >> 3) & 1) * 16;
    const uint32_t b_row = (uint32_t)(wn * 64 + b_r) * 128;
    const uint32_t b_msk = (uint32_t)(b_r & 7) << 4;

    int c_off[4];
    #pragma unroll
    for (int u = 0; u < 4; u++) {
        int e = tid + 256 * u;
        int row = e >> 3, ch = e & 7;
        c_off[u] = row * 128 + ((ch * 16) ^ ((row & 7) << 4));
    }

    float d[2][8][4] = {};
    uint4 ra[4], rb[4];
    #pragma unroll
    for (int u = 0; u < 4; u++) {
        int e = tid + 256 * u;
        int row = e >> 3, ch = e & 7;
        ra[u] = *(const uint4*)(Ab + (size_t)row * KX3 + ch * 8);
        rb[u] = *(const uint4*)(Bb + (size_t)row * KX3 + ch * 8);
    }

    for (int s = 0; s < 4; s++) {
        const int p = s & 1;
        #pragma unroll
        for (int u = 0; u < 4; u++) {
            *(uint4*)(smem + p * 16384 + c_off[u])         = ra[u];
            *(uint4*)(smem + 32768 + p * 16384 + c_off[u]) = rb[u];
        }
        if (s + 1 < 4) {
            #pragma unroll
            for (int u = 0; u < 4; u++) {
                int e = tid + 256 * u;
                int row = e >> 3, ch = e & 7;
                ra[u] = *(const uint4*)(Ab + (size_t)row * KX3 + (s + 1) * 64 + ch * 8);
                rb[u] = *(const uint4*)(Bb + (size_t)row * KX3 + (s + 1) * 64 + ch * 8);
            }
        }
        __syncthreads();

        const uint32_t abase = sb + p * 16384;
        const uint32_t bbase = sb + 32768 + p * 16384;
        #pragma unroll
        for (int ks = 0; ks < 4; ks++) {
            uint32_t afr[2][4];
            {
                uint32_t byte = (uint32_t)((ks * 32 + a_cb)) ^ a_msk;
                uint32_t ad0 = abase + a_row + byte;
                LDSM_X4(afr[0][0], afr[0][1], afr[0][2], afr[0][3], ad0);
                LDSM_X4(afr[1][0], afr[1][1], afr[1][2], afr[1][3], ad0 + 2048);
            }
            #pragma unroll
            for (int g = 0; g < 4; g++) {
                uint32_t bfr[4];
                uint32_t byte = (uint32_t)((ks * 32 + b_cb)) ^ b_msk;
                uint32_t bd = bbase + b_row + g * 2048 + byte;
                LDSM_X4(bfr[0], bfr[1], bfr[2], bfr[3], bd);
                MMA16816(d[0][2 * g],     afr[0], bfr[0], bfr[1]);
                MMA16816(d[0][2 * g + 1], afr[0], bfr[2], bfr[3]);
                MMA16816(d[1][2 * g],     afr[1], bfr[0], bfr[1]);
                MMA16816(d[1][2 * g + 1], afr[1], bfr[2], bfr[3]);
            }
        }
        __syncthreads();
    }

    #pragma unroll
    for (int j = 0; j < 8; j++) {
        int col = n0 + wn * 64 + j * 8 + (lane & 3) * 2;
        #pragma unroll
        for (int i = 0; i < 2; i++) {
            size_t r0 = (size_t)(wm * 32 + i * 16 + (lane >> 2));
            *(float2*)&Cp[r0 * N + col] = make_float2(d[i][j][0], d[i][j][1]);
            *(float2*)&Cp[(r0 + 8) * N + col] = make_float2(d[i][j][2], d[i][j][3]);
        }
    }
}

// ---------------- attention device body ------------------------------------
__device__ void att_body(int b, const float* __restrict__ enc_out,
                         const float* __restrict__ b_dec,
                         const float* __restrict__ w_full,
                         const float* __restrict__ b_full, char* smem) {
    float* s_dec = (float*)smem;
    float* s_wf  = s_dec + 256;
    float* s_e   = s_wf + 256;
    float* s_red = s_e + 256;
    const int tid = threadIdx.x, lane = tid & 31, wid = tid >> 5;

    {
        float dv = b_dec[tid];
        #pragma unroll
        for (int s = 0; s < KSP; s++)
            dv += g_hgp[s * PSH + b * NH + G4 + tid];
        s_dec[tid] = dv;
        s_wf[tid]  = w_full[tid];
    }
    __syncthreads();

    const float bf = b_full[0];
    const float* ep_b = g_enc_proj + (size_t)b * Pd * Ad;
    for (int p = wid; p < Pd; p += 8) {
        const float* ep = ep_b + p * Ad;
        float s = 0.f;
        #pragma unroll
        for (int i = 0; i < 8; i++) {
            int a = lane + 32 * i;
            float v = ep[a] + s_dec[a];
            s = fmaf(fmaxf(v, 0.f), s_wf[a], s);
        }
        #pragma unroll
        for (int o = 16; o > 0; o >>= 1) s += __shfl_xor_sync(0xffffffffu, s, o);
        if (lane == 0) s_e[p] = s + bf;
    }
    __syncthreads();

    float v = (tid < Pd) ? s_e[tid] : -1e30f;
    float m = v;
    #pragma unroll
    for (int o = 16; o > 0; o >>= 1) m = fmaxf(m, __shfl_xor_sync(0xffffffffu, m, o));
    if (lane == 0) s_red[wid] = m;
    __syncthreads();
    float mm = s_red[0];
    #pragma unroll
    for (int i = 1; i < 8; i++) mm = fmaxf(mm, s_red[i]);

    float ev = (tid < Pd) ? __expf(v - mm) : 0.f;
    float ss = ev;
    #pragma unroll
    for (int o = 16; o > 0; o >>= 1) ss += __shfl_xor_sync(0xffffffffu, ss, o);
    if (lane == 0) s_red[8 + wid] = ss;
    if (tid < Pd) s_e[tid] = ev;
    __syncthreads();
    float tot = 0.f;
    #pragma unroll
    for (int i = 0; i < 8; i++) tot += s_red[8 + i];
    const float inv = 1.f / tot;

    const float* eo = enc_out + (size_t)b * Pd * Ed;
    float c0a = 0.f, c0b = 0.f, c1a = 0.f, c1b = 0.f;
    #pragma unroll 2
    for (int p = 0; p < Pd - 1; p += 2) {
        float a0 = s_e[p], a1 = s_e[p + 1];
        const float* r0 = eo + (size_t)p * Ed;
        c0a = fmaf(a0, r0[tid], c0a);
        c1a = fmaf(a0, r0[tid + 256], c1a);
        c0b = fmaf(a1, r0[Ed + tid], c0b);
        c1b = fmaf(a1, r0[Ed + tid + 256], c1b);
    }
    __half* cx = g_cext + (size_t)b * KX3;
    split3A((c0a + c0b) * inv, cx, tid);
    split3A((c1a + c1b) * inv, cx, tid + 256);
    __syncthreads();
}

// ---------------- lstm device body -----------------------------------------
__device__ __forceinline__ float sigf(float x) { return 1.f / (1.f + expf(-x)); }

__device__ void lstm_body(int idx, int t) {
    int b = idx >> 9, j = idx & (Hd - 1);
    const float* eg = g_embgates + ((size_t)t * Bsz + b) * G4;
    float gi = g_bcat[j]          + eg[j];
    float gf = g_bcat[Hd + j]     + eg[Hd + j];
    float gg = g_bcat[2 * Hd + j] + eg[2 * Hd + j];
    float go = g_bcat[3 * Hd + j] + eg[3 * Hd + j];
    #pragma unroll
    for (int s = 0; s < KSP; s++) {
        const float* hg = g_hgp + s * PSH + b * NH;
        const float* cg = g_cgp + s * PSC + b * G4;
        gi += hg[j]          + cg[j];
        gf += hg[Hd + j]     + cg[Hd + j];
        gg += hg[2 * Hd + j] + cg[2 * Hd + j];
        go += hg[3 * Hd + j] + cg[3 * Hd + j];
    }
    float i_ = sigf(gi);
    float f_ = sigf(gf);
    float g_ = tanhf(gg);
    float o_ = sigf(go);
    float c  = f_ * g_c[idx] + i_ * g_;
    float h  = o_ * tanhf(c);
    g_c[idx] = c;
    split3A(h, g_hext + (size_t)b * KX3, j);
    g_A2[((size_t)b * NSTEPS + t) * KE2 + j] = __float2half(h);
}

// ---------------- persistent loop kernel -----------------------------------
__global__ __launch_bounds__(256)
void k_loop(const float* __restrict__ enc, const float* __restrict__ b_dec,
            const float* __restrict__ w_full, const float* __restrict__ b_full) {
    extern __shared__ char smem[];
    const uint32_t sb = smem_u32(smem);
    int sense = 0;

    for (int t = 0; t < NSTEPS; t++) {
        // phase 1: h @ [W_hh | W_dec]  (18 N-tiles x split-K 6 = 108 jobs)
        for (int job = blockIdx.x; job < 18 * KSP; job += NB) {
            int nt = job / KSP, z = job % KSP;
            dev_gtile(g_hext + z * 256,
                      g_Whext + (size_t)nt * 128 * KX3 + z * 256,
                      g_hgp + (size_t)z * PSH, NH, nt * 128, smem, sb);
        }
        sense ^= 1; grid_barrier(sense);

        // phase 2: attention (1 batch per block)
        for (int b = blockIdx.x; b < Bsz; b += NB)
            att_body(b, enc, b_dec, w_full, b_full, smem);
        sense ^= 1; grid_barrier(sense);

        // phase 3: ctx @ W_ih_ctx  (16 N-tiles x split-K 6 = 96 jobs)
        for (int job = blockIdx.x; job < 16 * KSP; job += NB) {
            int nt = job / KSP, z = job % KSP;
            dev_gtile(g_cext + z * 256,
                      g_Wcext + (size_t)nt * 128 * KX3 + z * 256,
                      g_cgp + (size_t)z * PSC, G4, nt * 128, smem, sb);
        }
        sense ^= 1; grid_barrier(sense);

        // phase 4: LSTM pointwise
        for (int i = blockIdx.x * 256 + threadIdx.x; i < Bsz * Hd; i += NB * 256)
            lstm_body(i, t);
        sense ^= 1; grid_barrier(sense);
    }
}

// ---------------- FC GEMM (plain fp16, K=512) ------------------------------
__global__ __launch_bounds__(256, 2)
void k_fc(const float* __restrict__ b_fc, float* __restrict__ C) {
    extern __shared__ char smem[];
    const int tid = threadIdx.x, lane = tid & 31, wid = tid >> 5;
    const int m0 = blockIdx.x * 128;
    const int n0 = blockIdx.y * 128;
    const int wm = wid >> 1;
    const int wn = wid & 1;
    const uint32_t sb = smem_u32(smem);

    const __half* Ab = g_A2 + (size_t)m0 * KE2;
    const __half* Bb = g_B2 + (size_t)n0 * KE2;

    const int a_r  = lane & 15;
    const int a_cb = (lane >> 4) * 16;
    const uint32_t a_row = (uint32_t)(wm * 32 + a_r) * 128;
    const uint32_t a_msk = (uint32_t)(a_r & 7) << 4;
    const int b_r  = (lane & 7) + ((lane >> 4) << 3);
    const int b_cb = ((lane >> 3) & 1) * 16;
    const uint32_t b_row = (uint32_t)(wn * 64 + b_r) * 128;
    const uint32_t b_msk = (uint32_t)(b_r & 7) << 4;

    int c_off[4];
    #pragma unroll
    for (int u = 0; u < 4; u++) {
        int e = tid + 256 * u;
        int row = e >> 3, ch = e & 7;
        c_off[u] = row * 128 + ((ch * 16) ^ ((row & 7) << 4));
    }

    float d[2][8][4] = {};
    uint4 ra[4], rb[4];
    #pragma unroll
    for (int u = 0; u < 4; u++) {
        int e = tid + 256 * u;
        int row = e >> 3, ch = e & 7;
        ra[u] = *(const uint4*)(Ab + (size_t)row * KE2 + ch * 8);
        rb[u] = *(const uint4*)(Bb + (size_t)row * KE2 + ch * 8);
    }

    for (int s = 0; s < NSLAB; s++) {
        const int p = s & 1;
        #pragma unroll
        for (int u = 0; u < 4; u++) {
            *(uint4*)(smem + p * 16384 + c_off[u])         = ra[u];
            *(uint4*)(smem + 32768 + p * 16384 + c_off[u]) = rb[u];
        }
        if (s + 1 < NSLAB) {
            #pragma unroll
            for (int u = 0; u < 4; u++) {
                int e = tid + 256 * u;
                int row = e >> 3, ch = e & 7;
                ra[u] = *(const uint4*)(Ab + (size_t)row * KE2 + (s + 1) * 64 + ch * 8);
                rb[u] = *(const uint4*)(Bb + (size_t)row * KE2 + (s + 1) * 64 + ch * 8);
            }
        }
        __syncthreads();

        const uint32_t abase = sb + p * 16384;
        const uint32_t bbase = sb + 32768 + p * 16384;
        #pragma unroll
        for (int ks = 0; ks < 4; ks++) {
            uint32_t afr[2][4];
            {
                uint32_t byte = (uint32_t)((ks * 32 + a_cb)) ^ a_msk;
                uint32_t ad0 = abase + a_row + byte;
                LDSM_X4(afr[0][0], afr[0][1], afr[0][2], afr[0][3], ad0);
                LDSM_X4(afr[1][0], afr[1][1], afr[1][2], afr[1][3], ad0 + 2048);
            }
            #pragma unroll
            for (int g = 0; g < 4; g++) {
                uint32_t bfr[4];
                uint32_t byte = (uint32_t)((ks * 32 + b_cb)) ^ b_msk;
                uint32_t bd = bbase + b_row + g * 2048 + byte;
                LDSM_X4(bfr[0], bfr[1], bfr[2], bfr[3], bd);
                MMA16816(d[0][2 * g],     afr[0], bfr[0], bfr[1]);
                MMA16816(d[0][2 * g + 1], afr[0], bfr[2], bfr[3]);
                MMA16816(d[1][2 * g],     afr[1], bfr[0], bfr[1]);
                MMA16816(d[1][2 * g + 1], afr[1], bfr[2], bfr[3]);
            }
        }
        __syncthreads();
    }

    #pragma unroll
    for (int j = 0; j < 8; j++) {
        int col = n0 + wn * 64 + j * 8 + (lane & 3) * 2;
        if (col < Vd) {
            float bb0 = b_fc[col], bb1 = b_fc[col + 1];
            #pragma unroll
            for (int i = 0; i < 2; i++) {
                size_t r0 = (size_t)(m0 + wm * 32 + i * 16 + (lane >> 2));
                *(float2*)&C[r0 * Vd + col] =
                    make_float2(d[i][j][0] + bb0, d[i][j][1] + bb1);
                *(float2*)&C[(r0 + 8) * Vd + col] =
                    make_float2(d[i][j][2] + bb0, d[i][j][3] + bb1);
            }
        }
    }
}

// ---------------- launcher -------------------------------------------------
extern "C" void kernel_launch(void* const* d_in, const int* in_sizes, int n_in,
                              void* d_out, int out_size) {
    const float* enc     = (const float*)d_in[0];
    const int*   caps    = (const int*)  d_in[1];
    const float* emb     = (const float*)d_in[2];
    const float* W_enc   = (const float*)d_in[3];
    const float* b_enc   = (const float*)d_in[4];
    const float* W_dec   = (const float*)d_in[5];
    const float* b_dec   = (const float*)d_in[6];
    const float* w_full  = (const float*)d_in[7];
    const float* b_full  = (const float*)d_in[8];
    const float* W_ih    = (const float*)d_in[9];
    const float* b_ih    = (const float*)d_in[10];
    const float* W_hh    = (const float*)d_in[11];
    const float* b_hh    = (const float*)d_in[12];
    const float* W_fc    = (const float*)d_in[13];
    const float* b_fc    = (const float*)d_in[14];
    float* out = (float*)d_out;

    cudaFuncSetAttribute(k_fc, cudaFuncAttributeMaxDynamicSharedMemorySize, 65536);
    cudaFuncSetAttribute(hgemm128, cudaFuncAttributeMaxDynamicSharedMemorySize, 65536);
    cudaFuncSetAttribute(k_loop, cudaFuncAttributeMaxDynamicSharedMemorySize, 65536);

    __half *p_encext, *p_Wencext, *p_Wembext, *p_xembext;
    float *p_encproj, *p_embgates;
    cudaGetSymbolAddress((void**)&p_encext,   g_encext);
    cudaGetSymbolAddress((void**)&p_Wencext,  g_Wencext);
    cudaGetSymbolAddress((void**)&p_Wembext,  g_Wembext);
    cudaGetSymbolAddress((void**)&p_xembext,  g_xembext);
    cudaGetSymbolAddress((void**)&p_encproj,  g_enc_proj);
    cudaGetSymbolAddress((void**)&p_embgates, g_embgates);

    k_prep<<<4096, 256>>>(W_enc, W_dec, W_ih, W_hh, b_ih, b_hh);
    k_convert_enc<<<4096, 256>>>(enc);
    k_convert_wfc<<<4096, 256>>>(W_fc);
    k_prefill<<<(MROWS * Ed + 255) / 256, 256>>>(caps, emb);

    // enc_proj = enc @ W_enc + b_enc  (25088 x 256, Kext 1536)
    hgemm128<<<dim3(196, 2, 1), 256, 65536>>>(
        p_encext, p_Wencext, p_encproj, Ad, KX3, KX3, b_enc, 0);

    // emb-part of gates for all steps (2560 x 2048, Kext 1536)
    hgemm128<<<dim3(MROWS / 128, G4 / 128, 1), 256, 65536>>>(
        p_xembext, p_Wembext, p_embgates, G4, KX3, KX3, nullptr, 0);

    // whole 20-step recurrence in one persistent kernel
    k_loop<<<NB, 256, 65536>>>(enc, b_dec, w_full, b_full);

    k_fc<<<dim3(MROWS / 128, NPAD / 128), 256, 65536>>>(b_fc, out);
}

// round 11
// speedup vs baseline: 4.2180x; 1.2974x over previous
#include <cuda_runtime.h>
#include <cuda_fp16.h>
#include <math.h>
#include <stdint.h>

#define Bsz 128
#define Pd  196
#define Ed  512
#define Hd  512
#define Ad  256
#define Vd  30000
#define Td  21
#define NSTEPS 20
#define G4   2048

#define KX3  1536               // 3-term ext K (recurrence / enc)
#define MROWS  (Bsz * NSTEPS)   // 2560
#define KE2    512              // FC: plain fp16
#define NPAD   30208            // 236 * 128
#define NSLAB  (KE2 / 64)       // 8

#define NH    2304              // 2048 gates + 256 dec
#define PSH   (Bsz * NH)
#define PSC   (Bsz * G4)
#define KSP   6                 // split-K for loop GEMMs (ksize 256)
#define NB    128               // persistent grid size (<= SM count)

// ---------------- device scratch ------------------------------------------
__device__ __align__(256) __half g_enc_projh[Bsz * Pd * Ad];  // 12.8 MB fp16
__device__ float g_bcat[G4];
__device__ float g_c[Bsz * Hd];
__device__ float g_embgates[(size_t)MROWS * G4];
__device__ float g_hgp[KSP * PSH];
__device__ float g_cgp[KSP * PSC];
__device__ __align__(256) __half g_encext[(size_t)Bsz * Pd * KX3];
__device__ __align__(256) __half g_Wencext[Ad * KX3];
__device__ __align__(256) __half g_Whext[NH * KX3];
__device__ __align__(256) __half g_Wcext[G4 * KX3];
__device__ __align__(256) __half g_Wembext[G4 * KX3];
__device__ __align__(256) __half g_xembext[(size_t)MROWS * KX3];
__device__ __align__(256) __half g_hext[Bsz * KX3];
__device__ __align__(256) __half g_cext[Bsz * KX3];
__device__ __align__(256) __half g_A2[(size_t)MROWS * KE2];
__device__ __align__(256) __half g_B2[(size_t)NPAD * KE2];

__device__ int g_barcnt;
__device__ volatile int g_barsense;

// ---------------- asm helpers ----------------------------------------------
__device__ __forceinline__ uint32_t smem_u32(const void* p) {
    uint32_t a;
    asm("{ .reg .u64 t; cvta.to.shared.u64 t, %1; cvt.u32.u64 %0, t; }" : "=r"(a) : "l"(p));
    return a;
}
#define LDSM_X4(r0, r1, r2, r3, addr) \
    asm volatile("ldmatrix.sync.aligned.m8n8.x4.shared.b16 {%0,%1,%2,%3}, [%4];" \
                 : "=r"(r0), "=r"(r1), "=r"(r2), "=r"(r3) : "r"(addr))
#define MMA16816(d, a, b0v, b1v) \
    asm volatile("mma.sync.aligned.m16n8k16.row.col.f32.f16.f16.f32 " \
                 "{%0,%1,%2,%3}, {%4,%5,%6,%7}, {%8,%9}, {%0,%1,%2,%3};" \
                 : "+f"((d)[0]), "+f"((d)[1]), "+f"((d)[2]), "+f"((d)[3]) \
                 : "r"((a)[0]), "r"((a)[1]), "r"((a)[2]), "r"((a)[3]), \
                   "r"(b0v), "r"(b1v))

__device__ __forceinline__ void split3A(float v, __half* p, int j) {
    __half hi = __float2half(v);
    __half lo = __float2half(v - __half2float(hi));
    p[j] = hi; p[512 + j] = lo; p[1024 + j] = hi;
}
__device__ __forceinline__ void split3B(float v, __half* p, int j) {
    __half hi = __float2half(v);
    __half lo = __float2half(v - __half2float(hi));
    p[j] = hi; p[512 + j] = hi; p[1024 + j] = lo;
}

// ---------------- grid barrier (persistent kernel) -------------------------
__device__ __forceinline__ void grid_barrier(int sense) {
    __syncthreads();
    if (threadIdx.x == 0) {
        __threadfence();
        int old = atomicAdd(&g_barcnt, 1);
        if (old == NB - 1) {
            g_barcnt = 0;
            __threadfence();
            g_barsense = sense;
        } else {
            while (g_barsense != sense) { __nanosleep(64); }
            __threadfence();
        }
    }
    __syncthreads();
}

// ---------------- prep ------------------------------------------------------
__global__ void k_prep(const float* __restrict__ W_enc, const float* __restrict__ W_dec,
                       const float* __restrict__ W_ih, const float* __restrict__ W_hh,
                       const float* __restrict__ b_ih, const float* __restrict__ b_hh) {
    int idx = blockIdx.x * blockDim.x + threadIdx.x;
    int nthr = gridDim.x * blockDim.x;
    if (idx == 0) { g_barcnt = 0; g_barsense = 0; }
    for (int i = idx; i < Ad * Ed; i += nthr) {
        int a = i >> 9, k = i & 511;
        split3B(W_enc[k * Ad + a], g_Wencext + (size_t)a * KX3, k);
    }
    for (int i = idx; i < NH * Ed; i += nthr) {
        int n = i >> 9, k = i & 511;
        float w = (n < G4) ? W_hh[(size_t)n * Hd + k] : W_dec[k * Ad + (n - G4)];
        split3B(w, g_Whext + (size_t)n * KX3, k);
    }
    for (int i = idx; i < G4 * Ed; i += nthr) {
        int n = i >> 9, k = i & 511;
        split3B(W_ih[(size_t)n * (2 * Ed) + Ed + k], g_Wcext + (size_t)n * KX3, k);
    }
    for (int i = idx; i < G4 * Ed; i += nthr) {
        int n = i >> 9, k = i & 511;
        split3B(W_ih[(size_t)n * (2 * Ed) + k], g_Wembext + (size_t)n * KX3, k);
    }
    if (idx < G4) g_bcat[idx] = b_ih[idx] + b_hh[idx];
    if (idx < Bsz * Hd) g_c[idx] = 0.f;
    for (int i = idx; i < Bsz * KX3; i += nthr) g_hext[i] = __float2half(0.f);
}

__global__ __launch_bounds__(256)
void k_convert_enc(const float* __restrict__ enc) {
    int idx = blockIdx.x * blockDim.x + threadIdx.x;
    int nthr = gridDim.x * blockDim.x;
    for (size_t i = idx; i < (size_t)Bsz * Pd * Ed; i += nthr) {
        size_t r = i >> 9; int k = (int)(i & 511);
        split3A(enc[i], g_encext + r * KX3, k);
    }
}

__global__ __launch_bounds__(256)
void k_prefill(const int* __restrict__ captions, const float* __restrict__ emb) {
    int idx = blockIdx.x * blockDim.x + threadIdx.x;
    if (idx >= MROWS * Ed) return;
    int r = idx >> 9, j = idx & 511;
    int t = r >> 7, b = r & 127;
    int tok = captions[b * Td + t];
    split3A(emb[(size_t)tok * Ed + j], g_xembext + (size_t)r * KX3, j);
}

__global__ __launch_bounds__(256)
void k_convert_wfc(const float* __restrict__ W_fc) {
    int idx = blockIdx.x * blockDim.x + threadIdx.x;
    int nthr = gridDim.x * blockDim.x;
    for (size_t i = idx; i < (size_t)NPAD * Ed; i += nthr) {
        int n = (int)(i >> 9), k = (int)(i & 511);
        float v = (n < Vd) ? W_fc[(size_t)n * Ed + k] : 0.f;
        g_B2[(size_t)n * KE2 + k] = __float2half(v);
    }
}

// ---------------- generic HMMA GEMM kernel (pre-loop GEMMs) ----------------
// If C16 != nullptr, output fp16 (with bias) to C16 instead of fp32 to C.
__global__ __launch_bounds__(256, 2)
void hgemm128(const __half* __restrict__ A, const __half* __restrict__ Bm,
              float* __restrict__ C, __half* __restrict__ C16,
              int N, int Kext, int ksize,
              const float* __restrict__ bias, size_t partStride) {
    extern __shared__ char smem[];
    const int tid = threadIdx.x, lane = tid & 31, wid = tid >> 5;
    const int m0 = blockIdx.x * 128;
    const int n0 = blockIdx.y * 128;
    const int nslab = ksize >> 6;
    const int wm = wid >> 1, wn = wid & 1;
    const uint32_t sb = smem_u32(smem);

    const __half* Ab = A + (size_t)m0 * Kext + (size_t)blockIdx.z * ksize;
    const __half* Bb = Bm + (size_t)n0 * Kext + (size_t)blockIdx.z * ksize;
    float* Cp = C + blockIdx.z * partStride;

    const int a_r  = lane & 15;
    const int a_cb = (lane >> 4) * 16;
    const uint32_t a_row = (uint32_t)(wm * 32 + a_r) * 128;
    const uint32_t a_msk = (uint32_t)(a_r & 7) << 4;
    const int b_r  = (lane & 7) + ((lane >> 4) << 3);
    const int b_cb = ((lane >> 3) & 1) * 16;
    const uint32_t b_row = (uint32_t)(wn * 64 + b_r) * 128;
    const uint32_t b_msk = (uint32_t)(b_r & 7) << 4;

    int c_off[4];
    #pragma unroll
    for (int u = 0; u < 4; u++) {
        int e = tid + 256 * u;
        int row = e >> 3, ch = e & 7;
        c_off[u] = row * 128 + ((ch * 16) ^ ((row & 7) << 4));
    }

    float d[2][8][4] = {};
    uint4 ra[4], rb[4];
    #pragma unroll
    for (int u = 0; u < 4; u++) {
        int e = tid + 256 * u;
        int row = e >> 3, ch = e & 7;
        ra[u] = *(const uint4*)(Ab + (size_t)row * Kext + ch * 8);
        rb[u] = *(const uint4*)(Bb + (size_t)row * Kext + ch * 8);
    }

    for (int s = 0; s < nslab; s++) {
        const int p = s & 1;
        #pragma unroll
        for (int u = 0; u < 4; u++) {
            *(uint4*)(smem + p * 16384 + c_off[u])         = ra[u];
            *(uint4*)(smem + 32768 + p * 16384 + c_off[u]) = rb[u];
        }
        if (s + 1 < nslab) {
            #pragma unroll
            for (int u = 0; u < 4; u++) {
                int e = tid + 256 * u;
                int row = e >> 3, ch = e & 7;
                ra[u] = *(const uint4*)(Ab + (size_t)row * Kext + (s + 1) * 64 + ch * 8);
                rb[u] = *(const uint4*)(Bb + (size_t)row * Kext + (s + 1) * 64 + ch * 8);
            }
        }
        __syncthreads();

        const uint32_t abase = sb + p * 16384;
        const uint32_t bbase = sb + 32768 + p * 16384;
        #pragma unroll
        for (int ks = 0; ks < 4; ks++) {
            uint32_t afr[2][4];
            {
                uint32_t byte = (uint32_t)((ks * 32 + a_cb)) ^ a_msk;
                uint32_t ad0 = abase + a_row + byte;
                LDSM_X4(afr[0][0], afr[0][1], afr[0][2], afr[0][3], ad0);
                LDSM_X4(afr[1][0], afr[1][1], afr[1][2], afr[1][3], ad0 + 2048);
            }
            #pragma unroll
            for (int g = 0; g < 4; g++) {
                uint32_t bfr[4];
                uint32_t byte = (uint32_t)((ks * 32 + b_cb)) ^ b_msk;
                uint32_t bd = bbase + b_row + g * 2048 + byte;
                LDSM_X4(bfr[0], bfr[1], bfr[2], bfr[3], bd);
                MMA16816(d[0][2 * g],     afr[0], bfr[0], bfr[1]);
                MMA16816(d[0][2 * g + 1], afr[0], bfr[2], bfr[3]);
                MMA16816(d[1][2 * g],     afr[1], bfr[0], bfr[1]);
                MMA16816(d[1][2 * g + 1], afr[1], bfr[2], bfr[3]);
            }
        }
        __syncthreads();
    }

    if (C16) {
        #pragma unroll
        for (int j = 0; j < 8; j++) {
            int col = n0 + wn * 64 + j * 8 + (lane & 3) * 2;
            float bb0 = bias ? bias[col] : 0.f;
            float bb1 = bias ? bias[col + 1] : 0.f;
            #pragma unroll
            for (int i = 0; i < 2; i++) {
                size_t r0 = (size_t)(m0 + wm * 32 + i * 16 + (lane >> 2));
                *(__half2*)&C16[r0 * N + col] =
                    __floats2half2_rn(d[i][j][0] + bb0, d[i][j][1] + bb1);
                *(__half2*)&C16[(r0 + 8) * N + col] =
                    __floats2half2_rn(d[i][j][2] + bb0, d[i][j][3] + bb1);
            }
        }
    } else {
        #pragma unroll
        for (int j = 0; j < 8; j++) {
            int col = n0 + wn * 64 + j * 8 + (lane & 3) * 2;
            float bb0 = bias ? bias[col] : 0.f;
            float bb1 = bias ? bias[col + 1] : 0.f;
            #pragma unroll
            for (int i = 0; i < 2; i++) {
                size_t r0 = (size_t)(m0 + wm * 32 + i * 16 + (lane >> 2));
                *(float2*)&Cp[r0 * N + col] =
                    make_float2(d[i][j][0] + bb0, d[i][j][1] + bb1);
                *(float2*)&Cp[(r0 + 8) * N + col] =
                    make_float2(d[i][j][2] + bb0, d[i][j][3] + bb1);
            }
        }
    }
}

// ---------------- device GEMM tile for the persistent loop ------------------
__device__ void dev_gtile(const __half* __restrict__ Ab, const __half* __restrict__ Bb,
                          float* __restrict__ Cp, int N, int n0,
                          char* smem, uint32_t sb) {
    const int tid = threadIdx.x, lane = tid & 31, wid = tid >> 5;
    const int wm = wid >> 1, wn = wid & 1;

    const int a_r  = lane & 15;
    const int a_cb = (lane >> 4) * 16;
    const uint32_t a_row = (uint32_t)(wm * 32 + a_r) * 128;
    const uint32_t a_msk = (uint32_t)(a_r & 7) << 4;
    const int b_r  = (lane & 7) + ((lane >> 4) << 3);
    const int b_cb = ((lane >> 3) & 1) * 16;
    const uint32_t b_row = (uint32_t)(wn * 64 + b_r) * 128;
    const uint32_t b_msk = (uint32_t)(b_r & 7) << 4;

    int c_off[4];
    #pragma unroll
    for (int u = 0; u < 4; u++) {
        int e = tid + 256 * u;
        int row = e >> 3, ch = e & 7;
        c_off[u] = row * 128 + ((ch * 16) ^ ((row & 7) << 4));
    }

    float d[2][8][4] = {};
    uint4 ra[4], rb[4];
    #pragma unroll
    for (int u = 0; u < 4; u++) {
        int e = tid + 256 * u;
        int row = e >> 3, ch = e & 7;
        ra[u] = *(const uint4*)(Ab + (size_t)row * KX3 + ch * 8);
        rb[u] = *(const uint4*)(Bb + (size_t)row * KX3 + ch * 8);
    }

    for (int s = 0; s < 4; s++) {
        const int p = s & 1;
        #pragma unroll
        for (int u = 0; u < 4; u++) {
            *(uint4*)(smem + p * 16384 + c_off[u])         = ra[u];
            *(uint4*)(smem + 32768 + p * 16384 + c_off[u]) = rb[u];
        }
        if (s + 1 < 4) {
            #pragma unroll
            for (int u = 0; u < 4; u++) {
                int e = tid + 256 * u;
                int row = e >> 3, ch = e & 7;
                ra[u] = *(const uint4*)(Ab + (size_t)row * KX3 + (s + 1) * 64 + ch * 8);
                rb[u] = *(const uint4*)(Bb + (size_t)row * KX3 + (s + 1) * 64 + ch * 8);
            }
        }
        __syncthreads();

        const uint32_t abase = sb + p * 16384;
        const uint32_t bbase = sb + 32768 + p * 16384;
        #pragma unroll
        for (int ks = 0; ks < 4; ks++) {
            uint32_t afr[2][4];
            {
                uint32_t byte = (uint32_t)((ks * 32 + a_cb)) ^ a_msk;
                uint32_t ad0 = abase + a_row + byte;
                LDSM_X4(afr[0][0], afr[0][1], afr[0][2], afr[0][3], ad0);
                LDSM_X4(afr[1][0], afr[1][1], afr[1][2], afr[1][3], ad0 + 2048);
            }
            #pragma unroll
            for (int g = 0; g < 4; g++) {
                uint32_t bfr[4];
                uint32_t byte = (uint32_t)((ks * 32 + b_cb)) ^ b_msk;
                uint32_t bd = bbase + b_row + g * 2048 + byte;
                LDSM_X4(bfr[0], bfr[1], bfr[2], bfr[3], bd);
                MMA16816(d[0][2 * g],     afr[0], bfr[0], bfr[1]);
                MMA16816(d[0][2 * g + 1], afr[0], bfr[2], bfr[3]);
                MMA16816(d[1][2 * g],     afr[1], bfr[0], bfr[1]);
                MMA16816(d[1][2 * g + 1], afr[1], bfr[2], bfr[3]);
            }
        }
        __syncthreads();
    }

    #pragma unroll
    for (int j = 0; j < 8; j++) {
        int col = n0 + wn * 64 + j * 8 + (lane & 3) * 2;
        #pragma unroll
        for (int i = 0; i < 2; i++) {
            size_t r0 = (size_t)(wm * 32 + i * 16 + (lane >> 2));
            *(float2*)&Cp[r0 * N + col] = make_float2(d[i][j][0], d[i][j][1]);
            *(float2*)&Cp[(r0 + 8) * N + col] = make_float2(d[i][j][2], d[i][j][3]);
        }
    }
}

// ---------------- attention device body (fp16 traffic) ---------------------
__device__ void att_body(int b, const float* __restrict__ b_dec,
                         const float* __restrict__ w_full,
                         const float* __restrict__ b_full, char* smem) {
    float* s_dec = (float*)smem;
    float* s_wf  = s_dec + 256;
    float* s_e   = s_wf + 256;
    float* s_red = s_e + 256;
    const int tid = threadIdx.x, lane = tid & 31, wid = tid >> 5;

    {
        float dv = b_dec[tid];
        #pragma unroll
        for (int s = 0; s < KSP; s++)
            dv += g_hgp[s * PSH + b * NH + G4 + tid];
        s_dec[tid] = dv;
        s_wf[tid]  = w_full[tid];
    }
    __syncthreads();

    // e-phase: warp per p, __half2 loads of fp16 enc_proj
    const float bf = b_full[0];
    const __half* ep_b = g_enc_projh + (size_t)b * Pd * Ad;
    for (int p = wid; p < Pd; p += 8) {
        const __half* ep = ep_b + p * Ad;
        float s = 0.f;
        #pragma unroll
        for (int i = 0; i < 4; i++) {
            int a2 = 2 * lane + 64 * i;
            float2 f = __half22float2(*(const __half2*)(ep + a2));
            float v0 = f.x + s_dec[a2];
            float v1 = f.y + s_dec[a2 + 1];
            s = fmaf(fmaxf(v0, 0.f), s_wf[a2], s);
            s = fmaf(fmaxf(v1, 0.f), s_wf[a2 + 1], s);
        }
        #pragma unroll
        for (int o = 16; o > 0; o >>= 1) s += __shfl_xor_sync(0xffffffffu, s, o);
        if (lane == 0) s_e[p] = s + bf;
    }
    __syncthreads();

    // softmax
    float v = (tid < Pd) ? s_e[tid] : -1e30f;
    float m = v;
    #pragma unroll
    for (int o = 16; o > 0; o >>= 1) m = fmaxf(m, __shfl_xor_sync(0xffffffffu, m, o));
    if (lane == 0) s_red[wid] = m;
    __syncthreads();
    float mm = s_red[0];
    #pragma unroll
    for (int i = 1; i < 8; i++) mm = fmaxf(mm, s_red[i]);

    float ev = (tid < Pd) ? __expf(v - mm) : 0.f;
    float ss = ev;
    #pragma unroll
    for (int o = 16; o > 0; o >>= 1) ss += __shfl_xor_sync(0xffffffffu, ss, o);
    if (lane == 0) s_red[8 + wid] = ss;
    if (tid < Pd) s_e[tid] = ev;
    __syncthreads();
    float tot = 0.f;
    #pragma unroll
    for (int i = 0; i < 8; i++) tot += s_red[8 + i];
    const float inv = 1.f / tot;

    // ctx-phase: fp16 hi-section of g_encext, __half2 per row,
    // thread handles adjacent dims 2*tid, 2*tid+1
    const __half* eo = g_encext + (size_t)b * Pd * KX3 + 2 * tid;
    float acc0 = 0.f, acc1 = 0.f;
    #pragma unroll 4
    for (int p = 0; p < Pd; p++) {
        float al = s_e[p];
        float2 f = __half22float2(*(const __half2*)(eo + (size_t)p * KX3));
        acc0 = fmaf(al, f.x, acc0);
        acc1 = fmaf(al, f.y, acc1);
    }
    __half* cx = g_cext + (size_t)b * KX3;
    split3A(acc0 * inv, cx, 2 * tid);
    split3A(acc1 * inv, cx, 2 * tid + 1);
    __syncthreads();
}

// ---------------- lstm device body -----------------------------------------
__device__ __forceinline__ float sigf(float x) { return 1.f / (1.f + expf(-x)); }

__device__ void lstm_body(int idx, int t) {
    int b = idx >> 9, j = idx & (Hd - 1);
    const float* eg = g_embgates + ((size_t)t * Bsz + b) * G4;
    float gi = g_bcat[j]          + eg[j];
    float gf = g_bcat[Hd + j]     + eg[Hd + j];
    float gg = g_bcat[2 * Hd + j] + eg[2 * Hd + j];
    float go = g_bcat[3 * Hd + j] + eg[3 * Hd + j];
    #pragma unroll
    for (int s = 0; s < KSP; s++) {
        const float* hg = g_hgp + s * PSH + b * NH;
        const float* cg = g_cgp + s * PSC + b * G4;
        gi += hg[j]          + cg[j];
        gf += hg[Hd + j]     + cg[Hd + j];
        gg += hg[2 * Hd + j] + cg[2 * Hd + j];
        go += hg[3 * Hd + j] + cg[3 * Hd + j];
    }
    float i_ = sigf(gi);
    float f_ = sigf(gf);
    float g_ = tanhf(gg);
    float o_ = sigf(go);
    float c  = f_ * g_c[idx] + i_ * g_;
    float h  = o_ * tanhf(c);
    g_c[idx] = c;
    split3A(h, g_hext + (size_t)b * KX3, j);
    g_A2[((size_t)b * NSTEPS + t) * KE2 + j] = __float2half(h);
}

// ---------------- persistent loop kernel -----------------------------------
__global__ __launch_bounds__(256)
void k_loop(const float* __restrict__ b_dec,
            const float* __restrict__ w_full, const float* __restrict__ b_full) {
    extern __shared__ char smem[];
    const uint32_t sb = smem_u32(smem);
    int sense = 0;

    for (int t = 0; t < NSTEPS; t++) {
        // phase 1: h @ [W_hh | W_dec]  (18 N-tiles x split-K 6 = 108 jobs)
        for (int job = blockIdx.x; job < 18 * KSP; job += NB) {
            int nt = job / KSP, z = job % KSP;
            dev_gtile(g_hext + z * 256,
                      g_Whext + (size_t)nt * 128 * KX3 + z * 256,
                      g_hgp + (size_t)z * PSH, NH, nt * 128, smem, sb);
        }
        sense ^= 1; grid_barrier(sense);

        // phase 2: attention (1 batch per block)
        for (int b = blockIdx.x; b < Bsz; b += NB)
            att_body(b, b_dec, w_full, b_full, smem);
        sense ^= 1; grid_barrier(sense);

        // phase 3: ctx @ W_ih_ctx  (16 N-tiles x split-K 6 = 96 jobs)
        for (int job = blockIdx.x; job < 16 * KSP; job += NB) {
            int nt = job / KSP, z = job % KSP;
            dev_gtile(g_cext + z * 256,
                      g_Wcext + (size_t)nt * 128 * KX3 + z * 256,
                      g_cgp + (size_t)z * PSC, G4, nt * 128, smem, sb);
        }
        sense ^= 1; grid_barrier(sense);

        // phase 4: LSTM pointwise
        for (int i = blockIdx.x * 256 + threadIdx.x; i < Bsz * Hd; i += NB * 256)
            lstm_body(i, t);
        sense ^= 1; grid_barrier(sense);
    }
}

// ---------------- FC GEMM (plain fp16, K=512) ------------------------------
__global__ __launch_bounds__(256, 2)
void k_fc(const float* __restrict__ b_fc, float* __restrict__ C) {
    extern __shared__ char smem[];
    const int tid = threadIdx.x, lane = tid & 31, wid = tid >> 5;
    const int m0 = blockIdx.x * 128;
    const int n0 = blockIdx.y * 128;
    const int wm = wid >> 1;
    const int wn = wid & 1;
    const uint32_t sb = smem_u32(smem);

    const __half* Ab = g_A2 + (size_t)m0 * KE2;
    const __half* Bb = g_B2 + (size_t)n0 * KE2;

    const int a_r  = lane & 15;
    const int a_cb = (lane >> 4) * 16;
    const uint32_t a_row = (uint32_t)(wm * 32 + a_r) * 128;
    const uint32_t a_msk = (uint32_t)(a_r & 7) << 4;
    const int b_r  = (lane & 7) + ((lane >> 4) << 3);
    const int b_cb = ((lane >> 3) & 1) * 16;
    const uint32_t b_row = (uint32_t)(wn * 64 + b_r) * 128;
    const uint32_t b_msk = (uint32_t)(b_r & 7) << 4;

    int c_off[4];
    #pragma unroll
    for (int u = 0; u < 4; u++) {
        int e = tid + 256 * u;
        int row = e >> 3, ch = e & 7;
        c_off[u] = row * 128 + ((ch * 16) ^ ((row & 7) << 4));
    }

    float d[2][8][4] = {};
    uint4 ra[4], rb[4];
    #pragma unroll
    for (int u = 0; u < 4; u++) {
        int e = tid + 256 * u;
        int row = e >> 3, ch = e & 7;
        ra[u] = *(const uint4*)(Ab + (size_t)row * KE2 + ch * 8);
        rb[u] = *(const uint4*)(Bb + (size_t)row * KE2 + ch * 8);
    }

    for (int s = 0; s < NSLAB; s++) {
        const int p = s & 1;
        #pragma unroll
        for (int u = 0; u < 4; u++) {
            *(uint4*)(smem + p * 16384 + c_off[u])         = ra[u];
            *(uint4*)(smem + 32768 + p * 16384 + c_off[u]) = rb[u];
        }
        if (s + 1 < NSLAB) {
            #pragma unroll
            for (int u = 0; u < 4; u++) {
                int e = tid + 256 * u;
                int row = e >> 3, ch = e & 7;
                ra[u] = *(const uint4*)(Ab + (size_t)row * KE2 + (s + 1) * 64 + ch * 8);
                rb[u] = *(const uint4*)(Bb + (size_t)row * KE2 + (s + 1) * 64 + ch * 8);
            }
        }
        __syncthreads();

        const uint32_t abase = sb + p * 16384;
        const uint32_t bbase = sb + 32768 + p * 16384;
        #pragma unroll
        for (int ks = 0; ks < 4; ks++) {
            uint32_t afr[2][4];
            {
                uint32_t byte = (uint32_t)((ks * 32 + a_cb)) ^ a_msk;
                uint32_t ad0 = abase + a_row + byte;
                LDSM_X4(afr[0][0], afr[0][1], afr[0][2], afr[0][3], ad0);
                LDSM_X4(afr[1][0], afr[1][1], afr[1][2], afr[1][3], ad0 + 2048);
            }
            #pragma unroll
            for (int g = 0; g < 4; g++) {
                uint32_t bfr[4];
                uint32_t byte = (uint32_t)((ks * 32 + b_cb)) ^ b_msk;
                uint32_t bd = bbase + b_row + g * 2048 + byte;
                LDSM_X4(bfr[0], bfr[1], bfr[2], bfr[3], bd);
                MMA16816(d[0][2 * g],     afr[0], bfr[0], bfr[1]);
                MMA16816(d[0][2 * g + 1], afr[0], bfr[2], bfr[3]);
                MMA16816(d[1][2 * g],     afr[1], bfr[0], bfr[1]);
                MMA16816(d[1][2 * g + 1], afr[1], bfr[2], bfr[3]);
            }
        }
        __syncthreads();
    }

    #pragma unroll
    for (int j = 0; j < 8; j++) {
        int col = n0 + wn * 64 + j * 8 + (lane & 3) * 2;
        if (col < Vd) {
            float bb0 = b_fc[col], bb1 = b_fc[col + 1];
            #pragma unroll
            for (int i = 0; i < 2; i++) {
                size_t r0 = (size_t)(m0 + wm * 32 + i * 16 + (lane >> 2));
                *(float2*)&C[r0 * Vd + col] =
                    make_float2(d[i][j][0] + bb0, d[i][j][1] + bb1);
                *(float2*)&C[(r0 + 8) * Vd + col] =
                    make_float2(d[i][j][2] + bb0, d[i][j][3] + bb1);
            }
        }
    }
}

// ---------------- launcher -------------------------------------------------
extern "C" void kernel_launch(void* const* d_in, const int* in_sizes, int n_in,
                              void* d_out, int out_size) {
    const float* enc     = (const float*)d_in[0];
    const int*   caps    = (const int*)  d_in[1];
    const float* emb     = (const float*)d_in[2];
    const float* W_enc   = (const float*)d_in[3];
    const float* b_enc   = (const float*)d_in[4];
    const float* W_dec   = (const float*)d_in[5];
    const float* b_dec   = (const float*)d_in[6];
    const float* w_full  = (const float*)d_in[7];
    const float* b_full  = (const float*)d_in[8];
    const float* W_ih    = (const float*)d_in[9];
    const float* b_ih    = (const float*)d_in[10];
    const float* W_hh    = (const float*)d_in[11];
    const float* b_hh    = (const float*)d_in[12];
    const float* W_fc    = (const float*)d_in[13];
    const float* b_fc    = (const float*)d_in[14];
    float* out = (float*)d_out;

    cudaFuncSetAttribute(k_fc, cudaFuncAttributeMaxDynamicSharedMemorySize, 65536);
    cudaFuncSetAttribute(hgemm128, cudaFuncAttributeMaxDynamicSharedMemorySize, 65536);
    cudaFuncSetAttribute(k_loop, cudaFuncAttributeMaxDynamicSharedMemorySize, 65536);

    __half *p_encext, *p_Wencext, *p_Wembext, *p_xembext, *p_encprojh;
    float *p_embgates;
    cudaGetSymbolAddress((void**)&p_encext,   g_encext);
    cudaGetSymbolAddress((void**)&p_Wencext,  g_Wencext);
    cudaGetSymbolAddress((void**)&p_Wembext,  g_Wembext);
    cudaGetSymbolAddress((void**)&p_xembext,  g_xembext);
    cudaGetSymbolAddress((void**)&p_encprojh, g_enc_projh);
    cudaGetSymbolAddress((void**)&p_embgates, g_embgates);

    k_prep<<<4096, 256>>>(W_enc, W_dec, W_ih, W_hh, b_ih, b_hh);
    k_convert_enc<<<4096, 256>>>(enc);
    k_convert_wfc<<<4096, 256>>>(W_fc);
    k_prefill<<<(MROWS * Ed + 255) / 256, 256>>>(caps, emb);

    // enc_proj = enc @ W_enc + b_enc  (25088 x 256, Kext 1536) -> fp16
    hgemm128<<<dim3(196, 2, 1), 256, 65536>>>(
        p_encext, p_Wencext, nullptr, p_encprojh, Ad, KX3, KX3, b_enc, 0);

    // emb-part of gates for all steps (2560 x 2048, Kext 1536) -> fp32
    hgemm128<<<dim3(MROWS / 128, G4 / 128, 1), 256, 65536>>>(
        p_xembext, p_Wembext, p_embgates, nullptr, G4, KX3, KX3, nullptr, 0);

    // whole 20-step recurrence in one persistent kernel
    k_loop<<<NB, 256, 65536>>>(b_dec, w_full, b_full);

    k_fc<<<dim3(MROWS / 128, NPAD / 128), 256, 65536>>>(b_fc, out);
}

// round 12
// speedup vs baseline: 5.0076x; 1.1872x over previous
#include <cuda_runtime.h>
#include <cuda_fp16.h>
#include <math.h>
#include <stdint.h>

#define Bsz 128
#define Pd  196
#define Ed  512
#define Hd  512
#define Ad  256
#define Vd  30000
#define Td  21
#define NSTEPS 20
#define G4   2048

#define KX3  1536               // 3-term ext K (recurrence / enc)
#define MROWS  (Bsz * NSTEPS)   // 2560
#define KE2    512              // FC: plain fp16
#define NPAD   30208            // 236 * 128
#define NSLAB  (KE2 / 64)       // 8

#define NH    2304              // 2048 gates + 256 dec
#define PSH   (Bsz * NH)
#define PSC   (Bsz * G4)
#define KSP   6                 // split-K for loop GEMMs (ksize 256)
#define NB    128               // persistent grid size (<= SM count)
#define LT    512               // k_loop threads per block

// ---------------- device scratch ------------------------------------------
__device__ __align__(256) __half g_enc_projh[Bsz * Pd * Ad];  // 12.8 MB fp16
__device__ float g_bcat[G4];
__device__ float g_c[Bsz * Hd];
__device__ float g_embgates[(size_t)MROWS * G4];
__device__ float g_hgp[KSP * PSH];
__device__ float g_cgp[KSP * PSC];
__device__ __align__(256) __half g_encext[(size_t)Bsz * Pd * KX3];
__device__ __align__(256) __half g_Wencext[Ad * KX3];
__device__ __align__(256) __half g_Whext[NH * KX3];
__device__ __align__(256) __half g_Wcext[G4 * KX3];
__device__ __align__(256) __half g_Wembext[G4 * KX3];
__device__ __align__(256) __half g_xembext[(size_t)MROWS * KX3];
__device__ __align__(256) __half g_hext[Bsz * KX3];
__device__ __align__(256) __half g_cext[Bsz * KX3];
__device__ __align__(256) __half g_A2[(size_t)MROWS * KE2];
__device__ __align__(256) __half g_B2[(size_t)NPAD * KE2];

__device__ int g_barcnt;
__device__ volatile int g_barsense;

// ---------------- asm helpers ----------------------------------------------
__device__ __forceinline__ uint32_t smem_u32(const void* p) {
    uint32_t a;
    asm("{ .reg .u64 t; cvta.to.shared.u64 t, %1; cvt.u32.u64 %0, t; }" : "=r"(a) : "l"(p));
    return a;
}
#define LDSM_X4(r0, r1, r2, r3, addr) \
    asm volatile("ldmatrix.sync.aligned.m8n8.x4.shared.b16 {%0,%1,%2,%3}, [%4];" \
                 : "=r"(r0), "=r"(r1), "=r"(r2), "=r"(r3) : "r"(addr))
#define MMA16816(d, a, b0v, b1v) \
    asm volatile("mma.sync.aligned.m16n8k16.row.col.f32.f16.f16.f32 " \
                 "{%0,%1,%2,%3}, {%4,%5,%6,%7}, {%8,%9}, {%0,%1,%2,%3};" \
                 : "+f"((d)[0]), "+f"((d)[1]), "+f"((d)[2]), "+f"((d)[3]) \
                 : "r"((a)[0]), "r"((a)[1]), "r"((a)[2]), "r"((a)[3]), \
                   "r"(b0v), "r"(b1v))

__device__ __forceinline__ void split3A(float v, __half* p, int j) {
    __half hi = __float2half(v);
    __half lo = __float2half(v - __half2float(hi));
    p[j] = hi; p[512 + j] = lo; p[1024 + j] = hi;
}
__device__ __forceinline__ void split3B(float v, __half* p, int j) {
    __half hi = __float2half(v);
    __half lo = __float2half(v - __half2float(hi));
    p[j] = hi; p[512 + j] = hi; p[1024 + j] = lo;
}

// ---------------- grid barrier (persistent kernel) -------------------------
__device__ __forceinline__ void grid_barrier(int sense) {
    __syncthreads();
    if (threadIdx.x == 0) {
        __threadfence();
        int old = atomicAdd(&g_barcnt, 1);
        if (old == NB - 1) {
            g_barcnt = 0;
            __threadfence();
            g_barsense = sense;
        } else {
            while (g_barsense != sense) { __nanosleep(64); }
            __threadfence();
        }
    }
    __syncthreads();
}

// ---------------- merged prep: all converts in one kernel ------------------
__global__ __launch_bounds__(256)
void k_prep_all(const float* __restrict__ enc,
                const int* __restrict__ captions, const float* __restrict__ emb,
                const float* __restrict__ W_enc, const float* __restrict__ W_dec,
                const float* __restrict__ W_ih, const float* __restrict__ W_hh,
                const float* __restrict__ b_ih, const float* __restrict__ b_hh,
                const float* __restrict__ W_fc) {
    int idx = blockIdx.x * blockDim.x + threadIdx.x;
    int nthr = gridDim.x * blockDim.x;
    if (idx == 0) { g_barcnt = 0; g_barsense = 0; }
    for (int i = idx; i < Ad * Ed; i += nthr) {
        int a = i >> 9, k = i & 511;
        split3B(W_enc[k * Ad + a], g_Wencext + (size_t)a * KX3, k);
    }
    for (int i = idx; i < NH * Ed; i += nthr) {
        int n = i >> 9, k = i & 511;
        float w = (n < G4) ? W_hh[(size_t)n * Hd + k] : W_dec[k * Ad + (n - G4)];
        split3B(w, g_Whext + (size_t)n * KX3, k);
    }
    for (int i = idx; i < G4 * Ed; i += nthr) {
        int n = i >> 9, k = i & 511;
        split3B(W_ih[(size_t)n * (2 * Ed) + Ed + k], g_Wcext + (size_t)n * KX3, k);
        split3B(W_ih[(size_t)n * (2 * Ed) + k],      g_Wembext + (size_t)n * KX3, k);
    }
    if (idx < G4) g_bcat[idx] = b_ih[idx] + b_hh[idx];
    if (idx < Bsz * Hd) g_c[idx] = 0.f;
    for (int i = idx; i < Bsz * KX3; i += nthr) g_hext[i] = __float2half(0.f);
    // encoder_out -> 3-term ext
    for (size_t i = idx; i < (size_t)Bsz * Pd * Ed; i += nthr) {
        size_t r = i >> 9; int k = (int)(i & 511);
        split3A(enc[i], g_encext + r * KX3, k);
    }
    // emb gather -> 3-term ext
    for (int i = idx; i < MROWS * Ed; i += nthr) {
        int r = i >> 9, j = i & 511;
        int t = r >> 7, b = r & 127;
        int tok = captions[b * Td + t];
        split3A(emb[(size_t)tok * Ed + j], g_xembext + (size_t)r * KX3, j);
    }
    // W_fc -> plain fp16
    for (size_t i = idx; i < (size_t)NPAD * Ed; i += nthr) {
        int n = (int)(i >> 9), k = (int)(i & 511);
        float v = (n < Vd) ? W_fc[(size_t)n * Ed + k] : 0.f;
        g_B2[(size_t)n * KE2 + k] = __float2half(v);
    }
}

// ---------------- generic HMMA GEMM kernel (pre-loop GEMMs, 256 thr) -------
__global__ __launch_bounds__(256, 2)
void hgemm128(const __half* __restrict__ A, const __half* __restrict__ Bm,
              float* __restrict__ C, __half* __restrict__ C16,
              int N, int Kext, int ksize,
              const float* __restrict__ bias, size_t partStride) {
    extern __shared__ char smem[];
    const int tid = threadIdx.x, lane = tid & 31, wid = tid >> 5;
    const int m0 = blockIdx.x * 128;
    const int n0 = blockIdx.y * 128;
    const int nslab = ksize >> 6;
    const int wm = wid >> 1, wn = wid & 1;
    const uint32_t sb = smem_u32(smem);

    const __half* Ab = A + (size_t)m0 * Kext + (size_t)blockIdx.z * ksize;
    const __half* Bb = Bm + (size_t)n0 * Kext + (size_t)blockIdx.z * ksize;
    float* Cp = C + blockIdx.z * partStride;

    const int a_r  = lane & 15;
    const int a_cb = (lane >> 4) * 16;
    const uint32_t a_row = (uint32_t)(wm * 32 + a_r) * 128;
    const uint32_t a_msk = (uint32_t)(a_r & 7) << 4;
    const int b_r  = (lane & 7) + ((lane >> 4) << 3);
    const int b_cb = ((lane >> 3) & 1) * 16;
    const uint32_t b_row = (uint32_t)(wn * 64 + b_r) * 128;
    const uint32_t b_msk = (uint32_t)(b_r & 7) << 4;

    int c_off[4];
    #pragma unroll
    for (int u = 0; u < 4; u++) {
        int e = tid + 256 * u;
        int row = e >> 3, ch = e & 7;
        c_off[u] = row * 128 + ((ch * 16) ^ ((row & 7) << 4));
    }

    float d[2][8][4] = {};
    uint4 ra[4], rb[4];
    #pragma unroll
    for (int u = 0; u < 4; u++) {
        int e = tid + 256 * u;
        int row = e >> 3, ch = e & 7;
        ra[u] = *(const uint4*)(Ab + (size_t)row * Kext + ch * 8);
        rb[u] = *(const uint4*)(Bb + (size_t)row * Kext + ch * 8);
    }

    for (int s = 0; s < nslab; s++) {
        const int p = s & 1;
        #pragma unroll
        for (int u = 0; u < 4; u++) {
            *(uint4*)(smem + p * 16384 + c_off[u])         = ra[u];
            *(uint4*)(smem + 32768 + p * 16384 + c_off[u]) = rb[u];
        }
        if (s + 1 < nslab) {
            #pragma unroll
            for (int u = 0; u < 4; u++) {
                int e = tid + 256 * u;
                int row = e >> 3, ch = e & 7;
                ra[u] = *(const uint4*)(Ab + (size_t)row * Kext + (s + 1) * 64 + ch * 8);
                rb[u] = *(const uint4*)(Bb + (size_t)row * Kext + (s + 1) * 64 + ch * 8);
            }
        }
        __syncthreads();

        const uint32_t abase = sb + p * 16384;
        const uint32_t bbase = sb + 32768 + p * 16384;
        #pragma unroll
        for (int ks = 0; ks < 4; ks++) {
            uint32_t afr[2][4];
            {
                uint32_t byte = (uint32_t)((ks * 32 + a_cb)) ^ a_msk;
                uint32_t ad0 = abase + a_row + byte;
                LDSM_X4(afr[0][0], afr[0][1], afr[0][2], afr[0][3], ad0);
                LDSM_X4(afr[1][0], afr[1][1], afr[1][2], afr[1][3], ad0 + 2048);
            }
            #pragma unroll
            for (int g = 0; g < 4; g++) {
                uint32_t bfr[4];
                uint32_t byte = (uint32_t)((ks * 32 + b_cb)) ^ b_msk;
                uint32_t bd = bbase + b_row + g * 2048 + byte;
                LDSM_X4(bfr[0], bfr[1], bfr[2], bfr[3], bd);
                MMA16816(d[0][2 * g],     afr[0], bfr[0], bfr[1]);
                MMA16816(d[0][2 * g + 1], afr[0], bfr[2], bfr[3]);
                MMA16816(d[1][2 * g],     afr[1], bfr[0], bfr[1]);
                MMA16816(d[1][2 * g + 1], afr[1], bfr[2], bfr[3]);
            }
        }
        __syncthreads();
    }

    if (C16) {
        #pragma unroll
        for (int j = 0; j < 8; j++) {
            int col = n0 + wn * 64 + j * 8 + (lane & 3) * 2;
            float bb0 = bias ? bias[col] : 0.f;
            float bb1 = bias ? bias[col + 1] : 0.f;
            #pragma unroll
            for (int i = 0; i < 2; i++) {
                size_t r0 = (size_t)(m0 + wm * 32 + i * 16 + (lane >> 2));
                *(__half2*)&C16[r0 * N + col] =
                    __floats2half2_rn(d[i][j][0] + bb0, d[i][j][1] + bb1);
                *(__half2*)&C16[(r0 + 8) * N + col] =
                    __floats2half2_rn(d[i][j][2] + bb0, d[i][j][3] + bb1);
            }
        }
    } else {
        #pragma unroll
        for (int j = 0; j < 8; j++) {
            int col = n0 + wn * 64 + j * 8 + (lane & 3) * 2;
            float bb0 = bias ? bias[col] : 0.f;
            float bb1 = bias ? bias[col + 1] : 0.f;
            #pragma unroll
            for (int i = 0; i < 2; i++) {
                size_t r0 = (size_t)(m0 + wm * 32 + i * 16 + (lane >> 2));
                *(float2*)&Cp[r0 * N + col] =
                    make_float2(d[i][j][0] + bb0, d[i][j][1] + bb1);
                *(float2*)&Cp[(r0 + 8) * N + col] =
                    make_float2(d[i][j][2] + bb0, d[i][j][3] + bb1);
            }
        }
    }
}

// ---------------- device GEMM tile for the persistent loop (512 thr) -------
// 128x128 tile, 16 warps (4M x 4N, warp tile 32x32), Kext=KX3, ksize=256.
__device__ void dev_gtile(const __half* __restrict__ Ab, const __half* __restrict__ Bb,
                          float* __restrict__ Cp, int N, int n0,
                          char* smem, uint32_t sb) {
    const int tid = threadIdx.x, lane = tid & 31, wid = tid >> 5;
    const int wm = wid >> 2, wn = wid & 3;

    const int a_r  = lane & 15;
    const int a_cb = (lane >> 4) * 16;
    const uint32_t a_row = (uint32_t)(wm * 32 + a_r) * 128;
    const uint32_t a_msk = (uint32_t)(a_r & 7) << 4;
    const int b_r  = (lane & 7) + ((lane >> 4) << 3);
    const int b_cb = ((lane >> 3) & 1) * 16;
    const uint32_t b_row = (uint32_t)(wn * 32 + b_r) * 128;
    const uint32_t b_msk = (uint32_t)(b_r & 7) << 4;

    int c_off[2];
    #pragma unroll
    for (int u = 0; u < 2; u++) {
        int e = tid + 512 * u;
        int row = e >> 3, ch = e & 7;
        c_off[u] = row * 128 + ((ch * 16) ^ ((row & 7) << 4));
    }

    float d[2][4][4] = {};
    uint4 ra[2], rb[2];
    #pragma unroll
    for (int u = 0; u < 2; u++) {
        int e = tid + 512 * u;
        int row = e >> 3, ch = e & 7;
        ra[u] = *(const uint4*)(Ab + (size_t)row * KX3 + ch * 8);
        rb[u] = *(const uint4*)(Bb + (size_t)row * KX3 + ch * 8);
    }

    for (int s = 0; s < 4; s++) {
        const int p = s & 1;
        #pragma unroll
        for (int u = 0; u < 2; u++) {
            *(uint4*)(smem + p * 16384 + c_off[u])         = ra[u];
            *(uint4*)(smem + 32768 + p * 16384 + c_off[u]) = rb[u];
        }
        if (s + 1 < 4) {
            #pragma unroll
            for (int u = 0; u < 2; u++) {
                int e = tid + 512 * u;
                int row = e >> 3, ch = e & 7;
                ra[u] = *(const uint4*)(Ab + (size_t)row * KX3 + (s + 1) * 64 + ch * 8);
                rb[u] = *(const uint4*)(Bb + (size_t)row * KX3 + (s + 1) * 64 + ch * 8);
            }
        }
        __syncthreads();

        const uint32_t abase = sb + p * 16384;
        const uint32_t bbase = sb + 32768 + p * 16384;
        #pragma unroll
        for (int ks = 0; ks < 4; ks++) {
            uint32_t afr[2][4];
            {
                uint32_t byte = (uint32_t)((ks * 32 + a_cb)) ^ a_msk;
                uint32_t ad0 = abase + a_row + byte;
                LDSM_X4(afr[0][0], afr[0][1], afr[0][2], afr[0][3], ad0);
                LDSM_X4(afr[1][0], afr[1][1], afr[1][2], afr[1][3], ad0 + 2048);
            }
            #pragma unroll
            for (int g = 0; g < 2; g++) {
                uint32_t bfr[4];
                uint32_t byte = (uint32_t)((ks * 32 + b_cb)) ^ b_msk;
                uint32_t bd = bbase + b_row + g * 2048 + byte;
                LDSM_X4(bfr[0], bfr[1], bfr[2], bfr[3], bd);
                MMA16816(d[0][2 * g],     afr[0], bfr[0], bfr[1]);
                MMA16816(d[0][2 * g + 1], afr[0], bfr[2], bfr[3]);
                MMA16816(d[1][2 * g],     afr[1], bfr[0], bfr[1]);
                MMA16816(d[1][2 * g + 1], afr[1], bfr[2], bfr[3]);
            }
        }
        __syncthreads();
    }

    #pragma unroll
    for (int j = 0; j < 4; j++) {
        int col = n0 + wn * 32 + j * 8 + (lane & 3) * 2;
        #pragma unroll
        for (int i = 0; i < 2; i++) {
            size_t r0 = (size_t)(wm * 32 + i * 16 + (lane >> 2));
            *(float2*)&Cp[r0 * N + col] = make_float2(d[i][j][0], d[i][j][1]);
            *(float2*)&Cp[(r0 + 8) * N + col] = make_float2(d[i][j][2], d[i][j][3]);
        }
    }
}

// ---------------- attention device body (512 threads) ----------------------
__device__ void att_body(int b, const float* __restrict__ b_dec,
                         const float* __restrict__ w_full,
                         const float* __restrict__ b_full, char* smem) {
    float* s_dec = (float*)smem;          // 256
    float* s_wf  = s_dec + 256;           // 256
    float* s_e   = s_wf + 256;            // 256
    float* s_red = s_e + 256;             // 32
    float* s_ctx = s_red + 32;            // 2 * 512
    const int tid = threadIdx.x, lane = tid & 31, wid = tid >> 5;

    if (tid < 256) {
        float dv = b_dec[tid];
        #pragma unroll
        for (int s = 0; s < KSP; s++)
            dv += g_hgp[s * PSH + b * NH + G4 + tid];
        s_dec[tid] = dv;
        s_wf[tid]  = w_full[tid];
    }
    __syncthreads();

    // e-phase: 16 warps, warp per p
    const float bf = b_full[0];
    const __half* ep_b = g_enc_projh + (size_t)b * Pd * Ad;
    for (int p = wid; p < Pd; p += 16) {
        const __half* ep = ep_b + p * Ad;
        float s = 0.f;
        #pragma unroll
        for (int i = 0; i < 4; i++) {
            int a2 = 2 * lane + 64 * i;
            float2 f = __half22float2(*(const __half2*)(ep + a2));
            float v0 = f.x + s_dec[a2];
            float v1 = f.y + s_dec[a2 + 1];
            s = fmaf(fmaxf(v0, 0.f), s_wf[a2], s);
            s = fmaf(fmaxf(v1, 0.f), s_wf[a2 + 1], s);
        }
        #pragma unroll
        for (int o = 16; o > 0; o >>= 1) s += __shfl_xor_sync(0xffffffffu, s, o);
        if (lane == 0) s_e[p] = s + bf;
    }
    __syncthreads();

    // softmax over 16 warps
    float v = (tid < Pd) ? s_e[tid] : -1e30f;
    float m = v;
    #pragma unroll
    for (int o = 16; o > 0; o >>= 1) m = fmaxf(m, __shfl_xor_sync(0xffffffffu, m, o));
    if (lane == 0) s_red[wid] = m;
    __syncthreads();
    float mm = s_red[0];
    #pragma unroll
    for (int i = 1; i < 16; i++) mm = fmaxf(mm, s_red[i]);

    float ev = (tid < Pd) ? __expf(v - mm) : 0.f;
    float ss = ev;
    #pragma unroll
    for (int o = 16; o > 0; o >>= 1) ss += __shfl_xor_sync(0xffffffffu, ss, o);
    if (lane == 0) s_red[16 + wid] = ss;
    if (tid < Pd) s_e[tid] = ev;
    __syncthreads();
    float tot = 0.f;
    #pragma unroll
    for (int i = 0; i < 16; i++) tot += s_red[16 + i];
    const float inv = 1.f / tot;

    // ctx-phase: two 256-thread halves split the p-range, combine in smem
    const int half = tid >> 8;            // 0 or 1
    const int tl   = tid & 255;
    const int p0 = half * (Pd / 2), p1 = p0 + (Pd / 2);
    const __half* eo = g_encext + (size_t)b * Pd * KX3 + 2 * tl;
    float acc0 = 0.f, acc1 = 0.f;
    #pragma unroll 4
    for (int p = p0; p < p1; p++) {
        float al = s_e[p];
        float2 f = __half22float2(*(const __half2*)(eo + (size_t)p * KX3));
        acc0 = fmaf(al, f.x, acc0);
        acc1 = fmaf(al, f.y, acc1);
    }
    s_ctx[half * 512 + 2 * tl]     = acc0;
    s_ctx[half * 512 + 2 * tl + 1] = acc1;
    __syncthreads();
    if (tid < 256) {
        float f0 = (s_ctx[2 * tid]     + s_ctx[512 + 2 * tid])     * inv;
        float f1 = (s_ctx[2 * tid + 1] + s_ctx[512 + 2 * tid + 1]) * inv;
        __half* cx = g_cext + (size_t)b * KX3;
        split3A(f0, cx, 2 * tid);
        split3A(f1, cx, 2 * tid + 1);
    }
    __syncthreads();
}

// ---------------- lstm device body -----------------------------------------
__device__ __forceinline__ float sigf(float x) { return 1.f / (1.f + expf(-x)); }

__device__ void lstm_body(int idx, int t) {
    int b = idx >> 9, j = idx & (Hd - 1);
    const float* eg = g_embgates + ((size_t)t * Bsz + b) * G4;
    float gi = g_bcat[j]          + eg[j];
    float gf = g_bcat[Hd + j]     + eg[Hd + j];
    float gg = g_bcat[2 * Hd + j] + eg[2 * Hd + j];
    float go = g_bcat[3 * Hd + j] + eg[3 * Hd + j];
    #pragma unroll
    for (int s = 0; s < KSP; s++) {
        const float* hg = g_hgp + s * PSH + b * NH;
        const float* cg = g_cgp + s * PSC + b * G4;
        gi += hg[j]          + cg[j];
        gf += hg[Hd + j]     + cg[Hd + j];
        gg += hg[2 * Hd + j] + cg[2 * Hd + j];
        go += hg[3 * Hd + j] + cg[3 * Hd + j];
    }
    float i_ = sigf(gi);
    float f_ = sigf(gf);
    float g_ = tanhf(gg);
    float o_ = sigf(go);
    float c  = f_ * g_c[idx] + i_ * g_;
    float h  = o_ * tanhf(c);
    g_c[idx] = c;
    split3A(h, g_hext + (size_t)b * KX3, j);
    g_A2[((size_t)b * NSTEPS + t) * KE2 + j] = __float2half(h);
}

// ---------------- persistent loop kernel (512 threads) ----------------------
__global__ __launch_bounds__(LT)
void k_loop(const float* __restrict__ b_dec,
            const float* __restrict__ w_full, const float* __restrict__ b_full) {
    extern __shared__ char smem[];
    const uint32_t sb = smem_u32(smem);
    int sense = 0;

    for (int t = 0; t < NSTEPS; t++) {
        // phase 1: h @ [W_hh | W_dec]  (18 N-tiles x split-K 6 = 108 jobs)
        for (int job = blockIdx.x; job < 18 * KSP; job += NB) {
            int nt = job / KSP, z = job % KSP;
            dev_gtile(g_hext + z * 256,
                      g_Whext + (size_t)nt * 128 * KX3 + z * 256,
                      g_hgp + (size_t)z * PSH, NH, nt * 128, smem, sb);
        }
        sense ^= 1; grid_barrier(sense);

        // phase 2: attention (1 batch per block)
        for (int b = blockIdx.x; b < Bsz; b += NB)
            att_body(b, b_dec, w_full, b_full, smem);
        sense ^= 1; grid_barrier(sense);

        // phase 3: ctx @ W_ih_ctx  (16 N-tiles x split-K 6 = 96 jobs)
        for (int job = blockIdx.x; job < 16 * KSP; job += NB) {
            int nt = job / KSP, z = job % KSP;
            dev_gtile(g_cext + z * 256,
                      g_Wcext + (size_t)nt * 128 * KX3 + z * 256,
                      g_cgp + (size_t)z * PSC, G4, nt * 128, smem, sb);
        }
        sense ^= 1; grid_barrier(sense);

        // phase 4: LSTM pointwise
        for (int i = blockIdx.x * LT + threadIdx.x; i < Bsz * Hd; i += NB * LT)
            lstm_body(i, t);
        sense ^= 1; grid_barrier(sense);
    }
}

// ---------------- FC GEMM (plain fp16, K=512) ------------------------------
__global__ __launch_bounds__(256, 2)
void k_fc(const float* __restrict__ b_fc, float* __restrict__ C) {
    extern __shared__ char smem[];
    const int tid = threadIdx.x, lane = tid & 31, wid = tid >> 5;
    const int m0 = blockIdx.x * 128;
    const int n0 = blockIdx.y * 128;
    const int wm = wid >> 1;
    const int wn = wid & 1;
    const uint32_t sb = smem_u32(smem);

    const __half* Ab = g_A2 + (size_t)m0 * KE2;
    const __half* Bb = g_B2 + (size_t)n0 * KE2;

    const int a_r  = lane & 15;
    const int a_cb = (lane >> 4) * 16;
    const uint32_t a_row = (uint32_t)(wm * 32 + a_r) * 128;
    const uint32_t a_msk = (uint32_t)(a_r & 7) << 4;
    const int b_r  = (lane & 7) + ((lane >> 4) << 3);
    const int b_cb = ((lane >> 3) & 1) * 16;
    const uint32_t b_row = (uint32_t)(wn * 64 + b_r) * 128;
    const uint32_t b_msk = (uint32_t)(b_r & 7) << 4;

    int c_off[4];
    #pragma unroll
    for (int u = 0; u < 4; u++) {
        int e = tid + 256 * u;
        int row = e >> 3, ch = e & 7;
        c_off[u] = row * 128 + ((ch * 16) ^ ((row & 7) << 4));
    }

    float d[2][8][4] = {};
    uint4 ra[4], rb[4];
    #pragma unroll
    for (int u = 0; u < 4; u++) {
        int e = tid + 256 * u;
        int row = e >> 3, ch = e & 7;
        ra[u] = *(const uint4*)(Ab + (size_t)row * KE2 + ch * 8);
        rb[u] = *(const uint4*)(Bb + (size_t)row * KE2 + ch * 8);
    }

    for (int s = 0; s < NSLAB; s++) {
        const int p = s & 1;
        #pragma unroll
        for (int u = 0; u < 4; u++) {
            *(uint4*)(smem + p * 16384 + c_off[u])         = ra[u];
            *(uint4*)(smem + 32768 + p * 16384 + c_off[u]) = rb[u];
        }
        if (s + 1 < NSLAB) {
            #pragma unroll
            for (int u = 0; u < 4; u++) {
                int e = tid + 256 * u;
                int row = e >> 3, ch = e & 7;
                ra[u] = *(const uint4*)(Ab + (size_t)row * KE2 + (s + 1) * 64 + ch * 8);
                rb[u] = *(const uint4*)(Bb + (size_t)row * KE2 + (s + 1) * 64 + ch * 8);
            }
        }
        __syncthreads();

        const uint32_t abase = sb + p * 16384;
        const uint32_t bbase = sb + 32768 + p * 16384;
        #pragma unroll
        for (int ks = 0; ks < 4; ks++) {
            uint32_t afr[2][4];
            {
                uint32_t byte = (uint32_t)((ks * 32 + a_cb)) ^ a_msk;
                uint32_t ad0 = abase + a_row + byte;
                LDSM_X4(afr[0][0], afr[0][1], afr[0][2], afr[0][3], ad0);
                LDSM_X4(afr[1][0], afr[1][1], afr[1][2], afr[1][3], ad0 + 2048);
            }
            #pragma unroll
            for (int g = 0; g < 4; g++) {
                uint32_t bfr[4];
                uint32_t byte = (uint32_t)((ks * 32 + b_cb)) ^ b_msk;
                uint32_t bd = bbase + b_row + g * 2048 + byte;
                LDSM_X4(bfr[0], bfr[1], bfr[2], bfr[3], bd);
                MMA16816(d[0][2 * g],     afr[0], bfr[0], bfr[1]);
                MMA16816(d[0][2 * g + 1], afr[0], bfr[2], bfr[3]);
                MMA16816(d[1][2 * g],     afr[1], bfr[0], bfr[1]);
                MMA16816(d[1][2 * g + 1], afr[1], bfr[2], bfr[3]);
            }
        }
        __syncthreads();
    }

    #pragma unroll
    for (int j = 0; j < 8; j++) {
        int col = n0 + wn * 64 + j * 8 + (lane & 3) * 2;
        if (col < Vd) {
            float bb0 = b_fc[col], bb1 = b_fc[col + 1];
            #pragma unroll
            for (int i = 0; i < 2; i++) {
                size_t r0 = (size_t)(m0 + wm * 32 + i * 16 + (lane >> 2));
                *(float2*)&C[r0 * Vd + col] =
                    make_float2(d[i][j][0] + bb0, d[i][j][1] + bb1);
                *(float2*)&C[(r0 + 8) * Vd + col] =
                    make_float2(d[i][j][2] + bb0, d[i][j][3] + bb1);
            }
        }
    }
}

// ---------------- launcher -------------------------------------------------
extern "C" void kernel_launch(void* const* d_in, const int* in_sizes, int n_in,
                              void* d_out, int out_size) {
    const float* enc     = (const float*)d_in[0];
    const int*   caps    = (const int*)  d_in[1];
    const float* emb     = (const float*)d_in[2];
    const float* W_enc   = (const float*)d_in[3];
    const float* b_enc   = (const float*)d_in[4];
    const float* W_dec   = (const float*)d_in[5];
    const float* b_dec   = (const float*)d_in[6];
    const float* w_full  = (const float*)d_in[7];
    const float* b_full  = (const float*)d_in[8];
    const float* W_ih    = (const float*)d_in[9];
    const float* b_ih    = (const float*)d_in[10];
    const float* W_hh    = (const float*)d_in[11];
    const float* b_hh    = (const float*)d_in[12];
    const float* W_fc    = (const float*)d_in[13];
    const float* b_fc    = (const float*)d_in[14];
    float* out = (float*)d_out;

    cudaFuncSetAttribute(k_fc, cudaFuncAttributeMaxDynamicSharedMemorySize, 65536);
    cudaFuncSetAttribute(hgemm128, cudaFuncAttributeMaxDynamicSharedMemorySize, 65536);
    cudaFuncSetAttribute(k_loop, cudaFuncAttributeMaxDynamicSharedMemorySize, 65536);

    __half *p_encext, *p_Wencext, *p_Wembext, *p_xembext, *p_encprojh;
    float *p_embgates;
    cudaGetSymbolAddress((void**)&p_encext,   g_encext);
    cudaGetSymbolAddress((void**)&p_Wencext,  g_Wencext);
    cudaGetSymbolAddress((void**)&p_Wembext,  g_Wembext);
    cudaGetSymbolAddress((void**)&p_xembext,  g_xembext);
    cudaGetSymbolAddress((void**)&p_encprojh, g_enc_projh);
    cudaGetSymbolAddress((void**)&p_embgates, g_embgates);

    k_prep_all<<<8192, 256>>>(enc, caps, emb, W_enc, W_dec, W_ih, W_hh,
                              b_ih, b_hh, W_fc);

    // enc_proj = enc @ W_enc + b_enc  (25088 x 256, Kext 1536) -> fp16
    hgemm128<<<dim3(196, 2, 1), 256, 65536>>>(
        p_encext, p_Wencext, nullptr, p_encprojh, Ad, KX3, KX3, b_enc, 0);

    // emb-part of gates for all steps (2560 x 2048, Kext 1536) -> fp32
    hgemm128<<<dim3(MROWS / 128, G4 / 128, 1), 256, 65536>>>(
        p_xembext, p_Wembext, p_embgates, nullptr, G4, KX3, KX3, nullptr, 0);

    // whole 20-step recurrence in one persistent kernel (512 threads/block)
    k_loop<<<NB, LT, 65536>>>(b_dec, w_full, b_full);

    k_fc<<<dim3(MROWS / 128, NPAD / 128), 256, 65536>>>(b_fc, out);
}

// round 17
// speedup vs baseline: 6.0932x; 1.2168x over previous
#include <cuda_runtime.h>
#include <cuda_fp16.h>
#include <math.h>
#include <stdint.h>

#define Bsz 128
#define Pd  196
#define Ed  512
#define Hd  512
#define Ad  256
#define Vd  30000
#define Td  21
#define NSTEPS 20
#define G4   2048

#define KX2  1024               // 2-term ext K: [Ahi|Alo] x [Bhi|Bhi]
#define MROWS  (Bsz * NSTEPS)   // 2560
#define KE2    512              // FC: plain fp16
#define NPAD   30208            // 236 * 128
#define NSLAB  (KE2 / 64)       // 8

#define PS    (Bsz * G4)
#define KSPL  4                 // loop split-K (ksize 256)
#define NB    128               // persistent grid size
#define LT    512               // k_loop threads per block

// ---------------- device scratch ------------------------------------------
__device__ __align__(256) __half g_enc_projh[Bsz * Pd * Ad];  // 12.8 MB fp16
__device__ float g_bcat[G4];
__device__ float g_c[Bsz * Hd];
__device__ float g_h[Bsz * Hd];
__device__ float g_embgates[(size_t)MROWS * G4];
__device__ float g_hgp[KSPL * PS];
__device__ float g_cgp[KSPL * PS];
__device__ __align__(256) __half g_encext[(size_t)Bsz * Pd * KX2];  // 51 MB
__device__ __align__(256) __half g_Wencext[Ad * KX2];
__device__ __align__(256) __half g_Whext[G4 * KX2];
__device__ __align__(256) __half g_Wcext[G4 * KX2];
__device__ __align__(256) __half g_Wembext[G4 * KX2];
__device__ __align__(256) __half g_WdecT[Ad * Ed];            // fp16 [a][k]
__device__ __align__(256) __half g_xembext[(size_t)MROWS * KX2];
__device__ __align__(256) __half g_hext[Bsz * KX2];
__device__ __align__(256) __half g_cext[Bsz * KX2];
__device__ __align__(256) __half g_A2[(size_t)MROWS * KE2];
__device__ __align__(256) __half g_B2[(size_t)NPAD * KE2];

__device__ int g_barcnt;
__device__ volatile int g_barsense;

// ---------------- asm helpers ----------------------------------------------
__device__ __forceinline__ uint32_t smem_u32(const void* p) {
    uint32_t a;
    asm("{ .reg .u64 t; cvta.to.shared.u64 t, %1; cvt.u32.u64 %0, t; }" : "=r"(a) : "l"(p));
    return a;
}
#define LDSM_X4(r0, r1, r2, r3, addr) \
    asm volatile("ldmatrix.sync.aligned.m8n8.x4.shared.b16 {%0,%1,%2,%3}, [%4];" \
                 : "=r"(r0), "=r"(r1), "=r"(r2), "=r"(r3) : "r"(addr))
#define MMA16816(d, a, b0v, b1v) \
    asm volatile("mma.sync.aligned.m16n8k16.row.col.f32.f16.f16.f32 " \
                 "{%0,%1,%2,%3}, {%4,%5,%6,%7}, {%8,%9}, {%0,%1,%2,%3};" \
                 : "+f"((d)[0]), "+f"((d)[1]), "+f"((d)[2]), "+f"((d)[3]) \
                 : "r"((a)[0]), "r"((a)[1]), "r"((a)[2]), "r"((a)[3]), \
                   "r"(b0v), "r"(b1v))

__device__ __forceinline__ void split2A(float v, __half* p, int j) {
    __half hi = __float2half(v);
    __half lo = __float2half(v - __half2float(hi));
    p[j] = hi; p[512 + j] = lo;                 // [Ahi | Alo]
}
__device__ __forceinline__ void split2B(float v, __half* p, int j) {
    __half hi = __float2half(v);
    p[j] = hi; p[512 + j] = hi;                 // [Bhi | Bhi]
}

// ---------------- grid barrier ---------------------------------------------
__device__ __forceinline__ void grid_barrier(int sense) {
    __syncthreads();
    if (threadIdx.x == 0) {
        __threadfence();
        int old = atomicAdd(&g_barcnt, 1);
        if (old == NB - 1) {
            g_barcnt = 0;
            __threadfence();
            g_barsense = sense;
        } else {
            while (g_barsense != sense) { __nanosleep(32); }
            __threadfence();
        }
    }
    __syncthreads();
}

// ---------------- merged prep ----------------------------------------------
__global__ __launch_bounds__(256)
void k_prep_all(const float* __restrict__ enc,
                const int* __restrict__ captions, const float* __restrict__ emb,
                const float* __restrict__ W_enc, const float* __restrict__ W_dec,
                const float* __restrict__ W_ih, const float* __restrict__ W_hh,
                const float* __restrict__ b_ih, const float* __restrict__ b_hh,
                const float* __restrict__ W_fc) {
    int idx = blockIdx.x * blockDim.x + threadIdx.x;
    int nthr = gridDim.x * blockDim.x;
    if (idx == 0) { g_barcnt = 0; g_barsense = 0; }
    for (int i = idx; i < Ad * Ed; i += nthr) {
        int a = i >> 9, k = i & 511;
        split2B(W_enc[k * Ad + a], g_Wencext + (size_t)a * KX2, k);
        g_WdecT[i] = __float2half(W_dec[k * Ad + a]);
    }
    for (int i = idx; i < G4 * Ed; i += nthr) {
        int n = i >> 9, k = i & 511;
        split2B(W_hh[(size_t)n * Hd + k],            g_Whext   + (size_t)n * KX2, k);
        split2B(W_ih[(size_t)n * (2 * Ed) + Ed + k], g_Wcext   + (size_t)n * KX2, k);
        split2B(W_ih[(size_t)n * (2 * Ed) + k],      g_Wembext + (size_t)n * KX2, k);
    }
    if (idx < G4) g_bcat[idx] = b_ih[idx] + b_hh[idx];
    if (idx < Bsz * Hd) { g_c[idx] = 0.f; g_h[idx] = 0.f; }
    for (int i = idx; i < Bsz * KX2; i += nthr) g_hext[i] = __float2half(0.f);
    for (size_t i = idx; i < (size_t)Bsz * Pd * Ed; i += nthr) {
        size_t r = i >> 9; int k = (int)(i & 511);
        split2A(enc[i], g_encext + r * KX2, k);
    }
    for (int i = idx; i < MROWS * Ed; i += nthr) {
        int r = i >> 9, j = i & 511;
        int t = r >> 7, b = r & 127;
        int tok = captions[b * Td + t];
        split2A(emb[(size_t)tok * Ed + j], g_xembext + (size_t)r * KX2, j);
    }
    for (size_t i = idx; i < (size_t)NPAD * Ed; i += nthr) {
        int n = (int)(i >> 9), k = (int)(i & 511);
        float v = (n < Vd) ? W_fc[(size_t)n * Ed + k] : 0.f;
        g_B2[(size_t)n * KE2 + k] = __float2half(v);
    }
}

// ---------------- generic HMMA GEMM kernel (pre-loop GEMMs) ----------------
__global__ __launch_bounds__(256, 2)
void hgemm128(const __half* __restrict__ A, const __half* __restrict__ Bm,
              float* __restrict__ C, __half* __restrict__ C16,
              int N, int Kext, int ksize, const float* __restrict__ bias) {
    extern __shared__ char smem[];
    const int tid = threadIdx.x, lane = tid & 31, wid = tid >> 5;
    const int m0 = blockIdx.x * 128;
    const int n0 = blockIdx.y * 128;
    const int nslab = ksize >> 6;
    const int wm = wid >> 1, wn = wid & 1;
    const uint32_t sb = smem_u32(smem);

    const __half* Ab = A + (size_t)m0 * Kext;
    const __half* Bb = Bm + (size_t)n0 * Kext;

    const int a_r  = lane & 15;
    const int a_cb = (lane >> 4) * 16;
    const uint32_t a_row = (uint32_t)(wm * 32 + a_r) * 128;
    const uint32_t a_msk = (uint32_t)(a_r & 7) << 4;
    const int b_r  = (lane & 7) + ((lane >> 4) << 3);
    const int b_cb = ((lane >> 3) & 1) * 16;
    const uint32_t b_row = (uint32_t)(wn * 64 + b_r) * 128;
    const uint32_t b_msk = (uint32_t)(b_r & 7) << 4;

    int c_off[4];
    #pragma unroll
    for (int u = 0; u < 4; u++) {
        int e = tid + 256 * u;
        int row = e >> 3, ch = e & 7;
        c_off[u] = row * 128 + ((ch * 16) ^ ((row & 7) << 4));
    }

    float d[2][8][4] = {};
    uint4 ra[4], rb[4];
    #pragma unroll
    for (int u = 0; u < 4; u++) {
        int e = tid + 256 * u;
        int row = e >> 3, ch = e & 7;
        ra[u] = *(const uint4*)(Ab + (size_t)row * Kext + ch * 8);
        rb[u] = *(const uint4*)(Bb + (size_t)row * Kext + ch * 8);
    }

    for (int s = 0; s < nslab; s++) {
        const int p = s & 1;
        #pragma unroll
        for (int u = 0; u < 4; u++) {
            *(uint4*)(smem + p * 16384 + c_off[u])         = ra[u];
            *(uint4*)(smem + 32768 + p * 16384 + c_off[u]) = rb[u];
        }
        if (s + 1 < nslab) {
            #pragma unroll
            for (int u = 0; u < 4; u++) {
                int e = tid + 256 * u;
                int row = e >> 3, ch = e & 7;
                ra[u] = *(const uint4*)(Ab + (size_t)row * Kext + (s + 1) * 64 + ch * 8);
                rb[u] = *(const uint4*)(Bb + (size_t)row * Kext + (s + 1) * 64 + ch * 8);
            }
        }
        __syncthreads();

        const uint32_t abase = sb + p * 16384;
        const uint32_t bbase = sb + 32768 + p * 16384;
        #pragma unroll
        for (int ks = 0; ks < 4; ks++) {
            uint32_t afr[2][4];
            {
                uint32_t byte = (uint32_t)((ks * 32 + a_cb)) ^ a_msk;
                uint32_t ad0 = abase + a_row + byte;
                LDSM_X4(afr[0][0], afr[0][1], afr[0][2], afr[0][3], ad0);
                LDSM_X4(afr[1][0], afr[1][1], afr[1][2], afr[1][3], ad0 + 2048);
            }
            #pragma unroll
            for (int g = 0; g < 4; g++) {
                uint32_t bfr[4];
                uint32_t byte = (uint32_t)((ks * 32 + b_cb)) ^ b_msk;
                uint32_t bd = bbase + b_row + g * 2048 + byte;
                LDSM_X4(bfr[0], bfr[1], bfr[2], bfr[3], bd);
                MMA16816(d[0][2 * g],     afr[0], bfr[0], bfr[1]);
                MMA16816(d[0][2 * g + 1], afr[0], bfr[2], bfr[3]);
                MMA16816(d[1][2 * g],     afr[1], bfr[0], bfr[1]);
                MMA16816(d[1][2 * g + 1], afr[1], bfr[2], bfr[3]);
            }
        }
        __syncthreads();
    }

    if (C16) {
        #pragma unroll
        for (int j = 0; j < 8; j++) {
            int col = n0 + wn * 64 + j * 8 + (lane & 3) * 2;
            float bb0 = bias ? bias[col] : 0.f;
            float bb1 = bias ? bias[col + 1] : 0.f;
            #pragma unroll
            for (int i = 0; i < 2; i++) {
                size_t r0 = (size_t)(m0 + wm * 32 + i * 16 + (lane >> 2));
                *(__half2*)&C16[r0 * N + col] =
                    __floats2half2_rn(d[i][j][0] + bb0, d[i][j][1] + bb1);
                *(__half2*)&C16[(r0 + 8) * N + col] =
                    __floats2half2_rn(d[i][j][2] + bb0, d[i][j][3] + bb1);
            }
        }
    } else {
        #pragma unroll
        for (int j = 0; j < 8; j++) {
            int col = n0 + wn * 64 + j * 8 + (lane & 3) * 2;
            float bb0 = bias ? bias[col] : 0.f;
            float bb1 = bias ? bias[col + 1] : 0.f;
            #pragma unroll
            for (int i = 0; i < 2; i++) {
                size_t r0 = (size_t)(m0 + wm * 32 + i * 16 + (lane >> 2));
                *(float2*)&C[r0 * N + col] =
                    make_float2(d[i][j][0] + bb0, d[i][j][1] + bb1);
                *(float2*)&C[(r0 + 8) * N + col] =
                    make_float2(d[i][j][2] + bb0, d[i][j][3] + bb1);
            }
        }
    }
}

// ---------------- device GEMM tile (loop, 512 thr, ksize=256) --------------
__device__ void dev_gtile(const __half* __restrict__ Ab, const __half* __restrict__ Bb,
                          float* __restrict__ Cp, int N, int n0,
                          char* smem, uint32_t sb) {
    const int tid = threadIdx.x, lane = tid & 31, wid = tid >> 5;
    const int wm = wid >> 2, wn = wid & 3;

    const int a_r  = lane & 15;
    const int a_cb = (lane >> 4) * 16;
    const uint32_t a_row = (uint32_t)(wm * 32 + a_r) * 128;
    const uint32_t a_msk = (uint32_t)(a_r & 7) << 4;
    const int b_r  = (lane & 7) + ((lane >> 4) << 3);
    const int b_cb = ((lane >> 3) & 1) * 16;
    const uint32_t b_row = (uint32_t)(wn * 32 + b_r) * 128;
    const uint32_t b_msk = (uint32_t)(b_r & 7) << 4;

    int c_off[2];
    #pragma unroll
    for (int u = 0; u < 2; u++) {
        int e = tid + 512 * u;
        int row = e >> 3, ch = e & 7;
        c_off[u] = row * 128 + ((ch * 16) ^ ((row & 7) << 4));
    }

    float d[2][4][4] = {};
    uint4 ra[2], rb[2];
    #pragma unroll
    for (int u = 0; u < 2; u++) {
        int e = tid + 512 * u;
        int row = e >> 3, ch = e & 7;
        ra[u] = *(const uint4*)(Ab + (size_t)row * KX2 + ch * 8);
        rb[u] = *(const uint4*)(Bb + (size_t)row * KX2 + ch * 8);
    }

    for (int s = 0; s < 4; s++) {
        const int p = s & 1;
        #pragma unroll
        for (int u = 0; u < 2; u++) {
            *(uint4*)(smem + p * 16384 + c_off[u])         = ra[u];
            *(uint4*)(smem + 32768 + p * 16384 + c_off[u]) = rb[u];
        }
        if (s + 1 < 4) {
            #pragma unroll
            for (int u = 0; u < 2; u++) {
                int e = tid + 512 * u;
                int row = e >> 3, ch = e & 7;
                ra[u] = *(const uint4*)(Ab + (size_t)row * KX2 + (s + 1) * 64 + ch * 8);
                rb[u] = *(const uint4*)(Bb + (size_t)row * KX2 + (s + 1) * 64 + ch * 8);
            }
        }
        __syncthreads();

        const uint32_t abase = sb + p * 16384;
        const uint32_t bbase = sb + 32768 + p * 16384;
        #pragma unroll
        for (int ks = 0; ks < 4; ks++) {
            uint32_t afr[2][4];
            {
                uint32_t byte = (uint32_t)((ks * 32 + a_cb)) ^ a_msk;
                uint32_t ad0 = abase + a_row + byte;
                LDSM_X4(afr[0][0], afr[0][1], afr[0][2], afr[0][3], ad0);
                LDSM_X4(afr[1][0], afr[1][1], afr[1][2], afr[1][3], ad0 + 2048);
            }
            #pragma unroll
            for (int g = 0; g < 2; g++) {
                uint32_t bfr[4];
                uint32_t byte = (uint32_t)((ks * 32 + b_cb)) ^ b_msk;
                uint32_t bd = bbase + b_row + g * 2048 + byte;
                LDSM_X4(bfr[0], bfr[1], bfr[2], bfr[3], bd);
                MMA16816(d[0][2 * g],     afr[0], bfr[0], bfr[1]);
                MMA16816(d[0][2 * g + 1], afr[0], bfr[2], bfr[3]);
                MMA16816(d[1][2 * g],     afr[1], bfr[0], bfr[1]);
                MMA16816(d[1][2 * g + 1], afr[1], bfr[2], bfr[3]);
            }
        }
        __syncthreads();
    }

    #pragma unroll
    for (int j = 0; j < 4; j++) {
        int col = n0 + wn * 32 + j * 8 + (lane & 3) * 2;
        #pragma unroll
        for (int i = 0; i < 2; i++) {
            size_t r0 = (size_t)(wm * 32 + i * 16 + (lane >> 2));
            *(float2*)&Cp[r0 * N + col] = make_float2(d[i][j][0], d[i][j][1]);
            *(float2*)&Cp[(r0 + 8) * N + col] = make_float2(d[i][j][2], d[i][j][3]);
        }
    }
}

// ---------------- attention body: local dec + e + softmax + ctx ------------
__device__ void att_body(int b, const float* __restrict__ b_dec,
                         const float* __restrict__ w_full,
                         const float* __restrict__ b_full, char* smem) {
    float* s_h    = (float*)smem;           // 512
    float* s_dec  = s_h + 512;              // 256
    float* s_wf   = s_dec + 256;            // 256
    float* s_e    = s_wf + 256;             // 256
    float* s_red  = s_e + 256;              // 32
    float* s_ctx  = s_red + 32;             // 1024
    float* s_dp   = s_ctx + 1024;           // 512
    const int tid = threadIdx.x, lane = tid & 31, wid = tid >> 5;

    // dec = h @ W_decT + b_dec (local SIMT)
    s_h[tid] = g_h[b * Hd + tid];
    __syncthreads();
    {
        int a = tid & 255, hf = tid >> 8;
        const __half* wcol = g_WdecT + (size_t)a * Ed + hf * 256;
        const float* hrow = s_h + hf * 256;
        float acc = 0.f;
        #pragma unroll 8
        for (int i = 0; i < 256; i += 2) {
            float2 w = __half22float2(*(const __half2*)(wcol + i));
            acc = fmaf(hrow[i], w.x, acc);
            acc = fmaf(hrow[i + 1], w.y, acc);
        }
        s_dp[tid] = acc;
    }
    __syncthreads();
    if (tid < 256) {
        s_dec[tid] = s_dp[tid] + s_dp[256 + tid] + b_dec[tid];
        s_wf[tid]  = w_full[tid];
    }
    __syncthreads();

    // e-phase: 16 warps, warp per p
    const float bf = b_full[0];
    const __half* ep_b = g_enc_projh + (size_t)b * Pd * Ad;
    for (int p = wid; p < Pd; p += 16) {
        const __half* ep = ep_b + p * Ad;
        float s = 0.f;
        #pragma unroll
        for (int i = 0; i < 4; i++) {
            int a2 = 2 * lane + 64 * i;
            float2 f = __half22float2(*(const __half2*)(ep + a2));
            float v0 = f.x + s_dec[a2];
            float v1 = f.y + s_dec[a2 + 1];
            s = fmaf(fmaxf(v0, 0.f), s_wf[a2], s);
            s = fmaf(fmaxf(v1, 0.f), s_wf[a2 + 1], s);
        }
        #pragma unroll
        for (int o = 16; o > 0; o >>= 1) s += __shfl_xor_sync(0xffffffffu, s, o);
        if (lane == 0) s_e[p] = s + bf;
    }
    __syncthreads();

    // softmax
    float v = (tid < Pd) ? s_e[tid] : -1e30f;
    float m = v;
    #pragma unroll
    for (int o = 16; o > 0; o >>= 1) m = fmaxf(m, __shfl_xor_sync(0xffffffffu, m, o));
    if (lane == 0) s_red[wid] = m;
    __syncthreads();
    float mm = s_red[0];
    #pragma unroll
    for (int i = 1; i < 16; i++) mm = fmaxf(mm, s_red[i]);

    float ev = (tid < Pd) ? __expf(v - mm) : 0.f;
    float ss = ev;
    #pragma unroll
    for (int o = 16; o > 0; o >>= 1) ss += __shfl_xor_sync(0xffffffffu, ss, o);
    if (lane == 0) s_red[16 + wid] = ss;
    if (tid < Pd) s_e[tid] = ev;
    __syncthreads();
    float tot = 0.f;
    #pragma unroll
    for (int i = 0; i < 16; i++) tot += s_red[16 + i];
    const float inv = 1.f / tot;

    // ctx-phase: two halves split p-range over hi-part of g_encext
    const int half = tid >> 8;
    const int tl   = tid & 255;
    const int p0 = half * (Pd / 2), p1 = p0 + (Pd / 2);
    const __half* eo = g_encext + (size_t)b * Pd * KX2 + 2 * tl;
    float acc0 = 0.f, acc1 = 0.f;
    #pragma unroll 4
    for (int p = p0; p < p1; p++) {
        float al = s_e[p];
        float2 f = __half22float2(*(const __half2*)(eo + (size_t)p * KX2));
        acc0 = fmaf(al, f.x, acc0);
        acc1 = fmaf(al, f.y, acc1);
    }
    s_ctx[half * 512 + 2 * tl]     = acc0;
    s_ctx[half * 512 + 2 * tl + 1] = acc1;
    __syncthreads();
    if (tid < 256) {
        float f0 = (s_ctx[2 * tid]     + s_ctx[512 + 2 * tid])     * inv;
        float f1 = (s_ctx[2 * tid + 1] + s_ctx[512 + 2 * tid + 1]) * inv;
        __half* cx = g_cext + (size_t)b * KX2;
        split2A(f0, cx, 2 * tid);
        split2A(f1, cx, 2 * tid + 1);
    }
    __syncthreads();
}

// ---------------- lstm body -------------------------------------------------
__device__ __forceinline__ float sigf(float x) { return 1.f / (1.f + expf(-x)); }

__device__ void lstm_body(int idx, int t) {
    int b = idx >> 9, j = idx & (Hd - 1);
    const float* eg = g_embgates + ((size_t)t * Bsz + b) * G4;
    float gi = g_bcat[j]          + eg[j];
    float gf = g_bcat[Hd + j]     + eg[Hd + j];
    float gg = g_bcat[2 * Hd + j] + eg[2 * Hd + j];
    float go = g_bcat[3 * Hd + j] + eg[3 * Hd + j];
    #pragma unroll
    for (int s = 0; s < KSPL; s++) {
        const float* hg = g_hgp + (size_t)s * PS + b * G4;
        const float* cg = g_cgp + (size_t)s * PS + b * G4;
        gi += hg[j]          + cg[j];
        gf += hg[Hd + j]     + cg[Hd + j];
        gg += hg[2 * Hd + j] + cg[2 * Hd + j];
        go += hg[3 * Hd + j] + cg[3 * Hd + j];
    }
    float i_ = sigf(gi);
    float f_ = sigf(gf);
    float g_ = tanhf(gg);
    float o_ = sigf(go);
    float c  = f_ * g_c[idx] + i_ * g_;
    float h  = o_ * tanhf(c);
    g_c[idx] = c;
    g_h[idx] = h;
    split2A(h, g_hext + (size_t)b * KX2, j);
    g_A2[((size_t)b * NSTEPS + t) * KE2 + j] = __float2half(h);
}

// ---------------- persistent loop kernel (3 phases/step) -------------------
__global__ __launch_bounds__(LT)
void k_loop(const float* __restrict__ b_dec,
            const float* __restrict__ w_full, const float* __restrict__ b_full) {
    extern __shared__ char smem[];
    const uint32_t sb = smem_u32(smem);
    int sense = 0;

    for (int t = 0; t < NSTEPS; t++) {
        // phase A: attention with local dec (1 batch per block)
        att_body(blockIdx.x, b_dec, w_full, b_full, smem);
        sense ^= 1; grid_barrier(sense);

        // phase B: gates GEMMs — h@W_hh (64 jobs) + ctx@W_c (64 jobs)
        {
            int job = blockIdx.x;
            int hv = job >> 6;                 // 0: h-gates, 1: ctx-gates
            int nt = (job & 63) >> 2;          // 0..15
            int z  = job & 3;                  // 0..3
            const __half* A = (hv == 0) ? (g_hext + z * 256) : (g_cext + z * 256);
            const __half* B = ((hv == 0) ? g_Whext : g_Wcext) + (size_t)nt * 128 * KX2 + z * 256;
            float* C = ((hv == 0) ? g_hgp : g_cgp) + (size_t)z * PS;
            dev_gtile(A, B, C, G4, nt * 128, smem, sb);
        }
        sense ^= 1; grid_barrier(sense);

        // phase C: LSTM pointwise
        for (int i = blockIdx.x * LT + threadIdx.x; i < Bsz * Hd; i += NB * LT)
            lstm_body(i, t);
        sense ^= 1; grid_barrier(sense);
    }
}

// ---------------- FC GEMM (plain fp16, K=512) ------------------------------
__global__ __launch_bounds__(256, 2)
void k_fc(const float* __restrict__ b_fc, float* __restrict__ C) {
    extern __shared__ char smem[];
    const int tid = threadIdx.x, lane = tid & 31, wid = tid >> 5;
    const int m0 = blockIdx.x * 128;
    const int n0 = blockIdx.y * 128;
    const int wm = wid >> 1;
    const int wn = wid & 1;
    const uint32_t sb = smem_u32(smem);

    const __half* Ab = g_A2 + (size_t)m0 * KE2;
    const __half* Bb = g_B2 + (size_t)n0 * KE2;

    const int a_r  = lane & 15;
    const int a_cb = (lane >> 4) * 16;
    const uint32_t a_row = (uint32_t)(wm * 32 + a_r) * 128;
    const uint32_t a_msk = (uint32_t)(a_r & 7) << 4;
    const int b_r  = (lane & 7) + ((lane >> 4) << 3);
    const int b_cb = ((lane >> 3) & 1) * 16;
    const uint32_t b_row = (uint32_t)(wn * 64 + b_r) * 128;
    const uint32_t b_msk = (uint32_t)(b_r & 7) << 4;

    int c_off[4];
    #pragma unroll
    for (int u = 0; u < 4; u++) {
        int e = tid + 256 * u;
        int row = e >> 3, ch = e & 7;
        c_off[u] = row * 128 + ((ch * 16) ^ ((row & 7) << 4));
    }

    float d[2][8][4] = {};
    uint4 ra[4], rb[4];
    #pragma unroll
    for (int u = 0; u < 4; u++) {
        int e = tid + 256 * u;
        int row = e >> 3, ch = e & 7;
        ra[u] = *(const uint4*)(Ab + (size_t)row * KE2 + ch * 8);
        rb[u] = *(const uint4*)(Bb + (size_t)row * KE2 + ch * 8);
    }

    for (int s = 0; s < NSLAB; s++) {
        const int p = s & 1;
        #pragma unroll
        for (int u = 0; u < 4; u++) {
            *(uint4*)(smem + p * 16384 + c_off[u])         = ra[u];
            *(uint4*)(smem + 32768 + p * 16384 + c_off[u]) = rb[u];
        }
        if (s + 1 < NSLAB) {
            #pragma unroll
            for (int u = 0; u < 4; u++) {
                int e = tid + 256 * u;
                int row = e >> 3, ch = e & 7;
                ra[u] = *(const uint4*)(Ab + (size_t)row * KE2 + (s + 1) * 64 + ch * 8);
                rb[u] = *(const uint4*)(Bb + (size_t)row * KE2 + (s + 1) * 64 + ch * 8);
            }
        }
        __syncthreads();

        const uint32_t abase = sb + p * 16384;
        const uint32_t bbase = sb + 32768 + p * 16384;
        #pragma unroll
        for (int ks = 0; ks < 4; ks++) {
            uint32_t afr[2][4];
            {
                uint32_t byte = (uint32_t)((ks * 32 + a_cb)) ^ a_msk;
                uint32_t ad0 = abase + a_row + byte;
                LDSM_X4(afr[0][0], afr[0][1], afr[0][2], afr[0][3], ad0);
                LDSM_X4(afr[1][0], afr[1][1], afr[1][2], afr[1][3], ad0 + 2048);
            }
            #pragma unroll
            for (int g = 0; g < 4; g++) {
                uint32_t bfr[4];
                uint32_t byte = (uint32_t)((ks * 32 + b_cb)) ^ b_msk;
                uint32_t bd = bbase + b_row + g * 2048 + byte;
                LDSM_X4(bfr[0], bfr[1], bfr[2], bfr[3], bd);
                MMA16816(d[0][2 * g],     afr[0], bfr[0], bfr[1]);
                MMA16816(d[0][2 * g + 1], afr[0], bfr[2], bfr[3]);
                MMA16816(d[1][2 * g],     afr[1], bfr[0], bfr[1]);
                MMA16816(d[1][2 * g + 1], afr[1], bfr[2], bfr[3]);
            }
        }
        __syncthreads();
    }

    #pragma unroll
    for (int j = 0; j < 8; j++) {
        int col = n0 + wn * 64 + j * 8 + (lane & 3) * 2;
        if (col < Vd) {
            float bb0 = b_fc[col], bb1 = b_fc[col + 1];
            #pragma unroll
            for (int i = 0; i < 2; i++) {
                size_t r0 = (size_t)(m0 + wm * 32 + i * 16 + (lane >> 2));
                *(float2*)&C[r0 * Vd + col] =
                    make_float2(d[i][j][0] + bb0, d[i][j][1] + bb1);
                *(float2*)&C[(r0 + 8) * Vd + col] =
                    make_float2(d[i][j][2] + bb0, d[i][j][3] + bb1);
            }
        }
    }
}

// ---------------- launcher -------------------------------------------------
extern "C" void kernel_launch(void* const* d_in, const int* in_sizes, int n_in,
                              void* d_out, int out_size) {
    const float* enc     = (const float*)d_in[0];
    const int*   caps    = (const int*)  d_in[1];
    const float* emb     = (const float*)d_in[2];
    const float* W_enc   = (const float*)d_in[3];
    const float* b_enc   = (const float*)d_in[4];
    const float* W_dec   = (const float*)d_in[5];
    const float* b_dec   = (const float*)d_in[6];
    const float* w_full  = (const float*)d_in[7];
    const float* b_full  = (const float*)d_in[8];
    const float* W_ih    = (const float*)d_in[9];
    const float* b_ih    = (const float*)d_in[10];
    const float* W_hh    = (const float*)d_in[11];
    const float* b_hh    = (const float*)d_in[12];
    const float* W_fc    = (const float*)d_in[13];
    const float* b_fc    = (const float*)d_in[14];
    float* out = (float*)d_out;

    cudaFuncSetAttribute(k_fc, cudaFuncAttributeMaxDynamicSharedMemorySize, 65536);
    cudaFuncSetAttribute(hgemm128, cudaFuncAttributeMaxDynamicSharedMemorySize, 65536);
    cudaFuncSetAttribute(k_loop, cudaFuncAttributeMaxDynamicSharedMemorySize, 65536);

    __half *p_encext, *p_Wencext, *p_Wembext, *p_xembext, *p_encprojh;
    float *p_embgates;
    cudaGetSymbolAddress((void**)&p_encext,   g_encext);
    cudaGetSymbolAddress((void**)&p_Wencext,  g_Wencext);
    cudaGetSymbolAddress((void**)&p_Wembext,  g_Wembext);
    cudaGetSymbolAddress((void**)&p_xembext,  g_xembext);
    cudaGetSymbolAddress((void**)&p_encprojh, g_enc_projh);
    cudaGetSymbolAddress((void**)&p_embgates, g_embgates);

    k_prep_all<<<8192, 256>>>(enc, caps, emb, W_enc, W_dec, W_ih, W_hh,
                              b_ih, b_hh, W_fc);

    // enc_proj = enc @ W_enc + b_enc  (25088 x 256, Kext 1024) -> fp16
    hgemm128<<<dim3(196, 2), 256, 65536>>>(
        p_encext, p_Wencext, nullptr, p_encprojh, Ad, KX2, KX2, b_enc);

    // emb-part of gates for all steps (2560 x 2048, Kext 1024) -> fp32
    hgemm128<<<dim3(MROWS / 128, G4 / 128), 256, 65536>>>(
        p_xembext, p_Wembext, p_embgates, nullptr, G4, KX2, KX2, nullptr);

    // 20-step recurrence, 3 phases/step
    k_loop<<<NB, LT, 65536>>>(b_dec, w_full, b_full);

    k_fc<<<dim3(MROWS / 128, NPAD / 128), 256, 65536>>>(b_fc, out);
}